// round 1
// baseline (speedup 1.0000x reference)
#include <cuda_runtime.h>
#include <cuda_bf16.h>
#include <math.h>

// Problem constants
#define Bb 8
#define Tt 1024
#define Dd 512
#define Hh 8
#define HD 64
#define D4 2048
#define ROWS (Bb*Tt)          // 8192

// ---------------- scratch (device globals; allocation-free) ----------------
__device__ float g_xn  [ROWS*Dd];
__device__ float g_qkv [ROWS*3*Dd];
__device__ float g_ctx [ROWS*Dd];
__device__ float g_std [ROWS*Dd];
__device__ float g_kw  [Bb*Tt*Tt];
__device__ float g_ksum[ROWS];
__device__ float g_ko  [ROWS*Dd];
__device__ float g_x1  [ROWS*Dd];
__device__ float g_xn2 [ROWS*Dd];
__device__ float g_h   [ROWS*D4];

// ---------------- LayerNorm: one warp per row of 512 ----------------
__global__ __launch_bounds__(256) void ln_kernel(
    const float* __restrict__ x, const float* __restrict__ w,
    const float* __restrict__ b, float* __restrict__ y)
{
    int warp = threadIdx.x >> 5, lane = threadIdx.x & 31;
    long row = (long)blockIdx.x * 8 + warp;
    const float* xr = x + row * Dd;
    float4 v[4];
    float s = 0.f, sq = 0.f;
#pragma unroll
    for (int i = 0; i < 4; i++) {
        v[i] = *(const float4*)&xr[lane*4 + i*128];
        s  += v[i].x + v[i].y + v[i].z + v[i].w;
        sq += v[i].x*v[i].x + v[i].y*v[i].y + v[i].z*v[i].z + v[i].w*v[i].w;
    }
#pragma unroll
    for (int o = 16; o; o >>= 1) {
        s  += __shfl_xor_sync(0xffffffffu, s,  o);
        sq += __shfl_xor_sync(0xffffffffu, sq, o);
    }
    float mean = s * (1.0f/512.0f);
    float var  = sq * (1.0f/512.0f) - mean*mean;
    float r    = rsqrtf(var + 1e-5f);
    float* yr = y + row * Dd;
#pragma unroll
    for (int i = 0; i < 4; i++) {
        int d = lane*4 + i*128;
        float4 wv = *(const float4*)&w[d];
        float4 bv = *(const float4*)&b[d];
        float4 o4;
        o4.x = (v[i].x - mean)*r*wv.x + bv.x;
        o4.y = (v[i].y - mean)*r*wv.y + bv.y;
        o4.z = (v[i].z - mean)*r*wv.z + bv.z;
        o4.w = (v[i].w - mean)*r*wv.w + bv.w;
        *(float4*)&yr[d] = o4;
    }
}

// ---------------- tiled SGEMM, 64x64 tile, 4x4/thread ----------------
// TB=true : C[M,N] = A[M,K] @ B[N,K]^T   (B row-major [N,K])
// TB=false: C[M,N] = A[M,K] @ B[K,N]     (B row-major [K,N])
// EPI: 0 none, 1 exact GELU, 2 add residual
__device__ __forceinline__ float gelu_exact(float v) {
    return 0.5f * v * (1.0f + erff(v * 0.7071067811865476f));
}

template<bool TB, int EPI>
__global__ __launch_bounds__(256) void gemm64(
    const float* __restrict__ A, const float* __restrict__ B,
    const float* __restrict__ bias, const float* __restrict__ res,
    float* __restrict__ C, int M, int N, int K,
    long sA, long sB, long sC)
{
    __shared__ float As[16][68];   // As[k][m]
    __shared__ float Bs[16][68];   // Bs[k][n]
    int z = blockIdx.z;
    A += (long)z * sA; B += (long)z * sB; C += (long)z * sC;
    const float* resp = res ? res + (long)z * sC : (const float*)0;

    int tid = threadIdx.x;
    int tx = tid & 15, ty = tid >> 4;
    int m0 = blockIdx.y << 6, n0 = blockIdx.x << 6;
    int lrow = tid >> 2, lkq = (tid & 3) << 2;
    float acc[4][4] = {};

    for (int kk = 0; kk < K; kk += 16) {
        float4 a4 = *(const float4*)&A[(long)(m0 + lrow)*K + kk + lkq];
        As[lkq+0][lrow] = a4.x; As[lkq+1][lrow] = a4.y;
        As[lkq+2][lrow] = a4.z; As[lkq+3][lrow] = a4.w;
        if (TB) {
            float4 b4 = *(const float4*)&B[(long)(n0 + lrow)*K + kk + lkq];
            Bs[lkq+0][lrow] = b4.x; Bs[lkq+1][lrow] = b4.y;
            Bs[lkq+2][lrow] = b4.z; Bs[lkq+3][lrow] = b4.w;
        } else {
            int kr = tid >> 4, nq = (tid & 15) << 2;
            float4 b4 = *(const float4*)&B[(long)(kk + kr)*N + n0 + nq];
            *(float4*)&Bs[kr][nq] = b4;
        }
        __syncthreads();
#pragma unroll
        for (int k = 0; k < 16; k++) {
            float4 b4 = *(const float4*)&Bs[k][tx*4];
            float a0 = As[k][ty*4+0], a1 = As[k][ty*4+1];
            float a2 = As[k][ty*4+2], a3 = As[k][ty*4+3];
            acc[0][0] += a0*b4.x; acc[0][1] += a0*b4.y; acc[0][2] += a0*b4.z; acc[0][3] += a0*b4.w;
            acc[1][0] += a1*b4.x; acc[1][1] += a1*b4.y; acc[1][2] += a1*b4.z; acc[1][3] += a1*b4.w;
            acc[2][0] += a2*b4.x; acc[2][1] += a2*b4.y; acc[2][2] += a2*b4.z; acc[2][3] += a2*b4.w;
            acc[3][0] += a3*b4.x; acc[3][1] += a3*b4.y; acc[3][2] += a3*b4.z; acc[3][3] += a3*b4.w;
        }
        __syncthreads();
    }

    float4 bi = make_float4(0.f,0.f,0.f,0.f);
    if (bias) bi = *(const float4*)&bias[n0 + tx*4];
#pragma unroll
    for (int i = 0; i < 4; i++) {
        long gm = m0 + ty*4 + i;
        float4 c;
        c.x = acc[i][0] + bi.x; c.y = acc[i][1] + bi.y;
        c.z = acc[i][2] + bi.z; c.w = acc[i][3] + bi.w;
        if (EPI == 1) {
            c.x = gelu_exact(c.x); c.y = gelu_exact(c.y);
            c.z = gelu_exact(c.z); c.w = gelu_exact(c.w);
        }
        if (EPI == 2) {
            float4 r = *(const float4*)&resp[gm*N + n0 + tx*4];
            c.x += r.x; c.y += r.y; c.z += r.z; c.w += r.w;
        }
        *(float4*)&C[gm*N + n0 + tx*4] = c;
    }
}

// ---------------- flash attention, fp32, 64q x 64k tiles ----------------
// one block per (b, h, q-tile). Q/K/V read directly from packed qkv buffer.
__global__ __launch_bounds__(256) void attn_kernel(
    const float* __restrict__ qkv, float* __restrict__ ctx)
{
    extern __shared__ float sm[];
    float* Qs = sm;             // [64][68]  q-major (pre-scaled by 1/8)
    float* Ks = sm + 4352;      // [64][68]  d-major (transposed)
    float* Vs = sm + 8704;      // [64][68]  k-major
    float* Ps = sm + 13056;     // [64][68]  q-major

    int b = blockIdx.z, h = blockIdx.y, qt = blockIdx.x;
    int tid = threadIdx.x, tx = tid & 15, ty = tid >> 4;
    const int LDR = 3*Dd;
    const float* base = qkv + (long)b * Tt * LDR;
    int row = tid >> 2, cq = (tid & 3) << 2;

    // load Q tile (scaled)
    {
        const float* qptr = base + (long)(qt*64) * LDR + h*HD;
#pragma unroll
        for (int w = 0; w < 4; w++) {
            int dd = cq + w*16;
            float4 v = *(const float4*)&qptr[(long)row*LDR + dd];
            v.x *= 0.125f; v.y *= 0.125f; v.z *= 0.125f; v.w *= 0.125f;
            *(float4*)&Qs[row*68 + dd] = v;
        }
    }

    float m[4], l[4], o[4][4];
#pragma unroll
    for (int i = 0; i < 4; i++) {
        m[i] = -1e30f; l[i] = 0.f;
#pragma unroll
        for (int j = 0; j < 4; j++) o[i][j] = 0.f;
    }

    for (int kt = 0; kt < Tt/64; kt++) {
        __syncthreads();
        const float* kptr = base + (long)(kt*64) * LDR + Dd  + h*HD;
        const float* vptr = base + (long)(kt*64) * LDR + 2*Dd + h*HD;
#pragma unroll
        for (int w = 0; w < 4; w++) {
            int dd = cq + w*16;
            float4 kv = *(const float4*)&kptr[(long)row*LDR + dd];
            Ks[(dd+0)*68 + row] = kv.x;
            Ks[(dd+1)*68 + row] = kv.y;
            Ks[(dd+2)*68 + row] = kv.z;
            Ks[(dd+3)*68 + row] = kv.w;
            float4 vv = *(const float4*)&vptr[(long)row*LDR + dd];
            *(float4*)&Vs[row*68 + dd] = vv;
        }
        __syncthreads();

        float s[4][4] = {};
#pragma unroll
        for (int d = 0; d < 64; d++) {
            float4 k4 = *(const float4*)&Ks[d*68 + tx*4];
            float a0 = Qs[(ty*4+0)*68 + d];
            float a1 = Qs[(ty*4+1)*68 + d];
            float a2 = Qs[(ty*4+2)*68 + d];
            float a3 = Qs[(ty*4+3)*68 + d];
            s[0][0] += a0*k4.x; s[0][1] += a0*k4.y; s[0][2] += a0*k4.z; s[0][3] += a0*k4.w;
            s[1][0] += a1*k4.x; s[1][1] += a1*k4.y; s[1][2] += a1*k4.z; s[1][3] += a1*k4.w;
            s[2][0] += a2*k4.x; s[2][1] += a2*k4.y; s[2][2] += a2*k4.z; s[2][3] += a2*k4.w;
            s[3][0] += a3*k4.x; s[3][1] += a3*k4.y; s[3][2] += a3*k4.z; s[3][3] += a3*k4.w;
        }

#pragma unroll
        for (int i = 0; i < 4; i++) {
            float mt = fmaxf(fmaxf(s[i][0], s[i][1]), fmaxf(s[i][2], s[i][3]));
#pragma unroll
            for (int off = 1; off < 16; off <<= 1)
                mt = fmaxf(mt, __shfl_xor_sync(0xffffffffu, mt, off));
            float mn = fmaxf(m[i], mt);
            float corr = __expf(m[i] - mn);
            m[i] = mn;
            l[i] *= corr;
#pragma unroll
            for (int j = 0; j < 4; j++) o[i][j] *= corr;
            float p0 = __expf(s[i][0] - mn);
            float p1 = __expf(s[i][1] - mn);
            float p2 = __expf(s[i][2] - mn);
            float p3 = __expf(s[i][3] - mn);
            l[i] += p0 + p1 + p2 + p3;
            float4 p4 = make_float4(p0, p1, p2, p3);
            *(float4*)&Ps[(ty*4+i)*68 + tx*4] = p4;
        }
        __syncthreads();

#pragma unroll
        for (int k = 0; k < 64; k++) {
            float4 v4 = *(const float4*)&Vs[k*68 + tx*4];
            float p0 = Ps[(ty*4+0)*68 + k];
            float p1 = Ps[(ty*4+1)*68 + k];
            float p2 = Ps[(ty*4+2)*68 + k];
            float p3 = Ps[(ty*4+3)*68 + k];
            o[0][0] += p0*v4.x; o[0][1] += p0*v4.y; o[0][2] += p0*v4.z; o[0][3] += p0*v4.w;
            o[1][0] += p1*v4.x; o[1][1] += p1*v4.y; o[1][2] += p1*v4.z; o[1][3] += p1*v4.w;
            o[2][0] += p2*v4.x; o[2][1] += p2*v4.y; o[2][2] += p2*v4.z; o[2][3] += p2*v4.w;
            o[3][0] += p3*v4.x; o[3][1] += p3*v4.y; o[3][2] += p3*v4.z; o[3][3] += p3*v4.w;
        }
    }

    float* optr = ctx + ((long)(b*Tt + qt*64)) * Dd + h*HD;
#pragma unroll
    for (int i = 0; i < 4; i++) {
        float li = l[i];
#pragma unroll
        for (int off = 1; off < 16; off <<= 1)
            li += __shfl_xor_sync(0xffffffffu, li, off);
        float inv = 1.0f / li;
        float4 r = make_float4(o[i][0]*inv, o[i][1]*inv, o[i][2]*inv, o[i][3]*inv);
        *(float4*)&optr[(long)(ty*4+i)*Dd + tx*4] = r;
    }
}

// ---------------- Gaussian kernel weights + row sums ----------------
__global__ __launch_bounds__(256) void kw_kernel(
    const int* __restrict__ posv, const int* __restrict__ posh,
    float* __restrict__ kw, float* __restrict__ ksum)
{
    long bq = blockIdx.x;                 // 0..8191
    int b = (int)(bq >> 10), q = (int)(bq & 1023);
    int tid = threadIdx.x;
    const int* pvb = posv + (long)b*Tt;
    const int* phb = posh + (long)b*Tt;
    int qv = pvb[q], qh = phb[q];
    int k0 = tid * 4;
    int4 kv4 = *(const int4*)&pvb[k0];
    int4 kh4 = *(const int4*)&phb[k0];
    const float c = -1.0f / 512.0f;       // -1/(2*sigma^2)
    int dvx = qv-kv4.x, dhx = qh-kh4.x;
    int dvy = qv-kv4.y, dhy = qh-kh4.y;
    int dvz = qv-kv4.z, dhz = qh-kh4.z;
    int dvw = qv-kv4.w, dhw = qh-kh4.w;
    float4 w4;
    w4.x = __expf((float)(dvx*dvx + dhx*dhx) * c);
    w4.y = __expf((float)(dvy*dvy + dhy*dhy) * c);
    w4.z = __expf((float)(dvz*dvz + dhz*dhz) * c);
    w4.w = __expf((float)(dvw*dvw + dhw*dhw) * c);
    *(float4*)&kw[bq*Tt + k0] = w4;
    float s = w4.x + w4.y + w4.z + w4.w;
#pragma unroll
    for (int o = 16; o; o >>= 1) s += __shfl_xor_sync(0xffffffffu, s, o);
    __shared__ float red[8];
    if ((tid & 31) == 0) red[tid >> 5] = s;
    __syncthreads();
    if (tid == 0) {
        float t = 0.f;
#pragma unroll
        for (int i = 0; i < 8; i++) t += red[i];
        ksum[bq] = t;
    }
}

// ---------------- combine (x1) + LayerNorm2 fused ----------------
__global__ __launch_bounds__(256) void combine_ln2_kernel(
    const float* __restrict__ x, const float* __restrict__ stdo,
    const float* __restrict__ ko, const float* __restrict__ ksum,
    const float* __restrict__ gate,
    const float* __restrict__ w, const float* __restrict__ bb,
    float* __restrict__ x1, float* __restrict__ xn2)
{
    int warp = threadIdx.x >> 5, lane = threadIdx.x & 31;
    long row = (long)blockIdx.x * 8 + warp;
    float g = 1.0f / (1.0f + __expf(-gate[0]));
    float gi = 1.0f - g;
    float inv_ks = 1.0f / ksum[row];
    long base = row * Dd;
    float4 v[4];
    float s = 0.f, sq = 0.f;
#pragma unroll
    for (int i = 0; i < 4; i++) {
        int d = lane*4 + i*128;
        float4 xv = *(const float4*)&x[base + d];
        float4 sv = *(const float4*)&stdo[base + d];
        float4 kv = *(const float4*)&ko[base + d];
        float4 o4;
        o4.x = xv.x + g*sv.x + gi*kv.x*inv_ks;
        o4.y = xv.y + g*sv.y + gi*kv.y*inv_ks;
        o4.z = xv.z + g*sv.z + gi*kv.z*inv_ks;
        o4.w = xv.w + g*sv.w + gi*kv.w*inv_ks;
        *(float4*)&x1[base + d] = o4;
        v[i] = o4;
        s  += o4.x + o4.y + o4.z + o4.w;
        sq += o4.x*o4.x + o4.y*o4.y + o4.z*o4.z + o4.w*o4.w;
    }
#pragma unroll
    for (int o = 16; o; o >>= 1) {
        s  += __shfl_xor_sync(0xffffffffu, s,  o);
        sq += __shfl_xor_sync(0xffffffffu, sq, o);
    }
    float mean = s * (1.0f/512.0f);
    float var  = sq * (1.0f/512.0f) - mean*mean;
    float r    = rsqrtf(var + 1e-5f);
#pragma unroll
    for (int i = 0; i < 4; i++) {
        int d = lane*4 + i*128;
        float4 wv = *(const float4*)&w[d];
        float4 bv = *(const float4*)&bb[d];
        float4 o4;
        o4.x = (v[i].x - mean)*r*wv.x + bv.x;
        o4.y = (v[i].y - mean)*r*wv.y + bv.y;
        o4.z = (v[i].z - mean)*r*wv.z + bv.z;
        o4.w = (v[i].w - mean)*r*wv.w + bv.w;
        *(float4*)&xn2[base + d] = o4;
    }
}

// ---------------- launch ----------------
extern "C" void kernel_launch(void* const* d_in, const int* in_sizes, int n_in,
                              void* d_out, int out_size)
{
    const float* x      = (const float*)d_in[0];
    const int*   posv   = (const int*)  d_in[1];
    const int*   posh   = (const int*)  d_in[2];
    const float* n1w    = (const float*)d_in[3];
    const float* n1b    = (const float*)d_in[4];
    const float* in_w   = (const float*)d_in[5];
    const float* in_b   = (const float*)d_in[6];
    const float* out_w  = (const float*)d_in[7];
    const float* out_b  = (const float*)d_in[8];
    const float* n2w    = (const float*)d_in[9];
    const float* n2b    = (const float*)d_in[10];
    const float* w1     = (const float*)d_in[11];
    const float* b1     = (const float*)d_in[12];
    const float* w2     = (const float*)d_in[13];
    const float* b2     = (const float*)d_in[14];
    const float* gate   = (const float*)d_in[15];
    float* out = (float*)d_out;

    float *xn, *qkv, *ctx, *stdo, *kw, *ksum, *ko, *x1, *xn2, *hbuf;
    cudaGetSymbolAddress((void**)&xn,   g_xn);
    cudaGetSymbolAddress((void**)&qkv,  g_qkv);
    cudaGetSymbolAddress((void**)&ctx,  g_ctx);
    cudaGetSymbolAddress((void**)&stdo, g_std);
    cudaGetSymbolAddress((void**)&kw,   g_kw);
    cudaGetSymbolAddress((void**)&ksum, g_ksum);
    cudaGetSymbolAddress((void**)&ko,   g_ko);
    cudaGetSymbolAddress((void**)&x1,   g_x1);
    cudaGetSymbolAddress((void**)&xn2,  g_xn2);
    cudaGetSymbolAddress((void**)&hbuf, g_h);

    // 1) LN1
    ln_kernel<<<ROWS/8, 256>>>(x, n1w, n1b, xn);

    // 2) QKV = xn @ in_w^T + in_b   [8192 x 1536]
    gemm64<true, 0><<<dim3(3*Dd/64, ROWS/64, 1), 256>>>(
        xn, in_w, in_b, nullptr, qkv, ROWS, 3*Dd, Dd, 0, 0, 0);

    // 3) flash attention -> ctx [8192 x 512]
    {
        static const int SMEM = 4 * 4352 * 4;  // 69632 B
        cudaFuncSetAttribute(attn_kernel, cudaFuncAttributeMaxDynamicSharedMemorySize, SMEM);
        attn_kernel<<<dim3(Tt/64, Hh, Bb), 256, SMEM>>>(qkv, ctx);
    }

    // 4) std_out = ctx @ out_w^T + out_b
    gemm64<true, 0><<<dim3(Dd/64, ROWS/64, 1), 256>>>(
        ctx, out_w, out_b, nullptr, stdo, ROWS, Dd, Dd, 0, 0, 0);

    // 5) Gaussian kernel weights (unnormalized) + row sums
    kw_kernel<<<ROWS, 256>>>(posv, posh, kw, ksum);

    // 6) ko = kw @ xn   (batched, B not transposed)
    gemm64<false, 0><<<dim3(Dd/64, Tt/64, Bb), 256>>>(
        kw, xn, nullptr, nullptr, ko, Tt, Dd, Tt,
        (long)Tt*Tt, (long)Tt*Dd, (long)Tt*Dd);

    // 7) x1 = x + g*std + (1-g)*ko/ksum ; xn2 = LN2(x1)
    combine_ln2_kernel<<<ROWS/8, 256>>>(x, stdo, ko, ksum, gate, n2w, n2b, x1, xn2);

    // 8) h = gelu(xn2 @ w1^T + b1)   [8192 x 2048]
    gemm64<true, 1><<<dim3(D4/64, ROWS/64, 1), 256>>>(
        xn2, w1, b1, nullptr, hbuf, ROWS, D4, Dd, 0, 0, 0);

    // 9) out = x1 + h @ w2^T + b2    [8192 x 512]
    gemm64<true, 2><<<dim3(Dd/64, ROWS/64, 1), 256>>>(
        hbuf, w2, b2, x1, out, ROWS, Dd, D4, 0, 0, 0);
}

// round 2
// speedup vs baseline: 1.1452x; 1.1452x over previous
#include <cuda_runtime.h>
#include <cuda_bf16.h>
#include <math.h>

// Problem constants
#define Bb 8
#define Tt 1024
#define Dd 512
#define Hh 8
#define HD 64
#define D4 2048
#define ROWS (Bb*Tt)          // 8192

// ---------------- scratch (device globals; allocation-free) ----------------
__device__ float g_xn  [ROWS*Dd];
__device__ float g_qkv [ROWS*3*Dd];
__device__ float g_ctx [ROWS*Dd];
__device__ float g_std [ROWS*Dd];
__device__ float g_kw  [Bb*Tt*Tt];
__device__ float g_ksum[ROWS];
__device__ float g_ko  [ROWS*Dd];
__device__ float g_x1  [ROWS*Dd];
__device__ float g_xn2 [ROWS*Dd];
__device__ float g_h   [ROWS*D4];

// ---------------- LayerNorm: one warp per row of 512 ----------------
__global__ __launch_bounds__(256) void ln_kernel(
    const float* __restrict__ x, const float* __restrict__ w,
    const float* __restrict__ b, float* __restrict__ y)
{
    int warp = threadIdx.x >> 5, lane = threadIdx.x & 31;
    long row = (long)blockIdx.x * 8 + warp;
    const float* xr = x + row * Dd;
    float4 v[4];
    float s = 0.f, sq = 0.f;
#pragma unroll
    for (int i = 0; i < 4; i++) {
        v[i] = *(const float4*)&xr[lane*4 + i*128];
        s  += v[i].x + v[i].y + v[i].z + v[i].w;
        sq += v[i].x*v[i].x + v[i].y*v[i].y + v[i].z*v[i].z + v[i].w*v[i].w;
    }
#pragma unroll
    for (int o = 16; o; o >>= 1) {
        s  += __shfl_xor_sync(0xffffffffu, s,  o);
        sq += __shfl_xor_sync(0xffffffffu, sq, o);
    }
    float mean = s * (1.0f/512.0f);
    float var  = sq * (1.0f/512.0f) - mean*mean;
    float r    = rsqrtf(var + 1e-5f);
    float* yr = y + row * Dd;
#pragma unroll
    for (int i = 0; i < 4; i++) {
        int d = lane*4 + i*128;
        float4 wv = *(const float4*)&w[d];
        float4 bv = *(const float4*)&b[d];
        float4 o4;
        o4.x = (v[i].x - mean)*r*wv.x + bv.x;
        o4.y = (v[i].y - mean)*r*wv.y + bv.y;
        o4.z = (v[i].z - mean)*r*wv.z + bv.z;
        o4.w = (v[i].w - mean)*r*wv.w + bv.w;
        *(float4*)&yr[d] = o4;
    }
}

// ---------------- SGEMM 128x128x16, 8x8/thread, double-buffered ----------------
// TB=true : C[M,N] = A[M,K] @ B[N,K]^T   (B row-major [N,K])
// TB=false: C[M,N] = A[M,K] @ B[K,N]     (B row-major [K,N])
// EPI: 0 none, 1 exact GELU, 2 add residual
__device__ __forceinline__ float gelu_exact(float v) {
    return 0.5f * v * (1.0f + erff(v * 0.7071067811865476f));
}

template<bool TB, int EPI>
__global__ __launch_bounds__(256) void gemm128(
    const float* __restrict__ A, const float* __restrict__ B,
    const float* __restrict__ bias, const float* __restrict__ res,
    float* __restrict__ C, int M, int N, int K,
    long sA, long sB, long sC)
{
    __shared__ float As[2][16][132];   // As[buf][k][m]
    __shared__ float Bs[2][16][132];   // Bs[buf][k][n]
    int z = blockIdx.z;
    A += (long)z * sA; B += (long)z * sB; C += (long)z * sC;
    const float* resp = res ? res + (long)z * sC : (const float*)0;

    int tid = threadIdx.x;
    int tx = tid & 15, ty = tid >> 4;
    int m0 = blockIdx.y << 7, n0 = blockIdx.x << 7;

    int ar  = tid >> 2;            // 0..63
    int akq = (tid & 3) << 2;      // 0,4,8,12
    int bkr = tid >> 5;            // 0..7
    int bnq = (tid & 31) << 2;     // 0..124

    const float* Aptr = A + (long)(m0 + ar) * K + akq;
    const float* Bptr = TB ? (B + (long)(n0 + ar) * K + akq)
                           : (B + (long)bkr * N + n0 + bnq);

    float acc[8][8] = {};
    int nk = K >> 4;

    float4 pa0, pa1, pb0, pb1;
    // prologue: tile 0 -> regs -> smem buf 0
    pa0 = *(const float4*)(Aptr);
    pa1 = *(const float4*)(Aptr + (long)64*K);
    if (TB) {
        pb0 = *(const float4*)(Bptr);
        pb1 = *(const float4*)(Bptr + (long)64*K);
    } else {
        pb0 = *(const float4*)(Bptr);
        pb1 = *(const float4*)(Bptr + (long)8*N);
    }
    As[0][akq+0][ar]    = pa0.x; As[0][akq+1][ar]    = pa0.y;
    As[0][akq+2][ar]    = pa0.z; As[0][akq+3][ar]    = pa0.w;
    As[0][akq+0][ar+64] = pa1.x; As[0][akq+1][ar+64] = pa1.y;
    As[0][akq+2][ar+64] = pa1.z; As[0][akq+3][ar+64] = pa1.w;
    if (TB) {
        Bs[0][akq+0][ar]    = pb0.x; Bs[0][akq+1][ar]    = pb0.y;
        Bs[0][akq+2][ar]    = pb0.z; Bs[0][akq+3][ar]    = pb0.w;
        Bs[0][akq+0][ar+64] = pb1.x; Bs[0][akq+1][ar+64] = pb1.y;
        Bs[0][akq+2][ar+64] = pb1.z; Bs[0][akq+3][ar+64] = pb1.w;
    } else {
        *(float4*)&Bs[0][bkr  ][bnq] = pb0;
        *(float4*)&Bs[0][bkr+8][bnq] = pb1;
    }
    __syncthreads();

    int cur = 0;
    for (int kk = 0; kk < nk; kk++) {
        if (kk + 1 < nk) {
            long ko = (long)(kk + 1) * 16;
            pa0 = *(const float4*)(Aptr + ko);
            pa1 = *(const float4*)(Aptr + (long)64*K + ko);
            if (TB) {
                pb0 = *(const float4*)(Bptr + ko);
                pb1 = *(const float4*)(Bptr + (long)64*K + ko);
            } else {
                pb0 = *(const float4*)(Bptr + ko * N);
                pb1 = *(const float4*)(Bptr + (ko + 8) * N);
            }
        }
#pragma unroll
        for (int k = 0; k < 16; k++) {
            float4 a0 = *(const float4*)&As[cur][k][ty*8];
            float4 a1 = *(const float4*)&As[cur][k][ty*8+4];
            float4 b0 = *(const float4*)&Bs[cur][k][tx*8];
            float4 b1 = *(const float4*)&Bs[cur][k][tx*8+4];
            float av[8] = {a0.x,a0.y,a0.z,a0.w,a1.x,a1.y,a1.z,a1.w};
            float bv[8] = {b0.x,b0.y,b0.z,b0.w,b1.x,b1.y,b1.z,b1.w};
#pragma unroll
            for (int i = 0; i < 8; i++)
#pragma unroll
                for (int j = 0; j < 8; j++)
                    acc[i][j] += av[i]*bv[j];
        }
        if (kk + 1 < nk) {
            int nb = cur ^ 1;
            As[nb][akq+0][ar]    = pa0.x; As[nb][akq+1][ar]    = pa0.y;
            As[nb][akq+2][ar]    = pa0.z; As[nb][akq+3][ar]    = pa0.w;
            As[nb][akq+0][ar+64] = pa1.x; As[nb][akq+1][ar+64] = pa1.y;
            As[nb][akq+2][ar+64] = pa1.z; As[nb][akq+3][ar+64] = pa1.w;
            if (TB) {
                Bs[nb][akq+0][ar]    = pb0.x; Bs[nb][akq+1][ar]    = pb0.y;
                Bs[nb][akq+2][ar]    = pb0.z; Bs[nb][akq+3][ar]    = pb0.w;
                Bs[nb][akq+0][ar+64] = pb1.x; Bs[nb][akq+1][ar+64] = pb1.y;
                Bs[nb][akq+2][ar+64] = pb1.z; Bs[nb][akq+3][ar+64] = pb1.w;
            } else {
                *(float4*)&Bs[nb][bkr  ][bnq] = pb0;
                *(float4*)&Bs[nb][bkr+8][bnq] = pb1;
            }
        }
        __syncthreads();
        cur ^= 1;
    }

    float4 bi0 = make_float4(0.f,0.f,0.f,0.f), bi1 = bi0;
    if (bias) {
        bi0 = *(const float4*)&bias[n0 + tx*8];
        bi1 = *(const float4*)&bias[n0 + tx*8 + 4];
    }
#pragma unroll
    for (int i = 0; i < 8; i++) {
        long gm = m0 + ty*8 + i;
        float4 c0, c1;
        c0.x = acc[i][0] + bi0.x; c0.y = acc[i][1] + bi0.y;
        c0.z = acc[i][2] + bi0.z; c0.w = acc[i][3] + bi0.w;
        c1.x = acc[i][4] + bi1.x; c1.y = acc[i][5] + bi1.y;
        c1.z = acc[i][6] + bi1.z; c1.w = acc[i][7] + bi1.w;
        if (EPI == 1) {
            c0.x = gelu_exact(c0.x); c0.y = gelu_exact(c0.y);
            c0.z = gelu_exact(c0.z); c0.w = gelu_exact(c0.w);
            c1.x = gelu_exact(c1.x); c1.y = gelu_exact(c1.y);
            c1.z = gelu_exact(c1.z); c1.w = gelu_exact(c1.w);
        }
        if (EPI == 2) {
            float4 r0 = *(const float4*)&resp[gm*N + n0 + tx*8];
            float4 r1 = *(const float4*)&resp[gm*N + n0 + tx*8 + 4];
            c0.x += r0.x; c0.y += r0.y; c0.z += r0.z; c0.w += r0.w;
            c1.x += r1.x; c1.y += r1.y; c1.z += r1.z; c1.w += r1.w;
        }
        *(float4*)&C[gm*N + n0 + tx*8]     = c0;
        *(float4*)&C[gm*N + n0 + tx*8 + 4] = c1;
    }
}

// ---------------- flash attention, fp32, 64q x 64k tiles ----------------
__global__ __launch_bounds__(256) void attn_kernel(
    const float* __restrict__ qkv, float* __restrict__ ctx)
{
    extern __shared__ float sm[];
    float* Qs = sm;             // [64][68]
    float* Ks = sm + 4352;      // [64][68] transposed (d-major)
    float* Vs = sm + 8704;      // [64][68]
    float* Ps = sm + 13056;     // [64][68]

    int b = blockIdx.z, h = blockIdx.y, qt = blockIdx.x;
    int tid = threadIdx.x, tx = tid & 15, ty = tid >> 4;
    const int LDR = 3*Dd;
    const float* base = qkv + (long)b * Tt * LDR;
    int row = tid >> 2, cq = (tid & 3) << 2;

    {
        const float* qptr = base + (long)(qt*64) * LDR + h*HD;
#pragma unroll
        for (int w = 0; w < 4; w++) {
            int dd = cq + w*16;
            float4 v = *(const float4*)&qptr[(long)row*LDR + dd];
            v.x *= 0.125f; v.y *= 0.125f; v.z *= 0.125f; v.w *= 0.125f;
            *(float4*)&Qs[row*68 + dd] = v;
        }
    }

    float m[4], l[4], o[4][4];
#pragma unroll
    for (int i = 0; i < 4; i++) {
        m[i] = -1e30f; l[i] = 0.f;
#pragma unroll
        for (int j = 0; j < 4; j++) o[i][j] = 0.f;
    }

    for (int kt = 0; kt < Tt/64; kt++) {
        __syncthreads();
        const float* kptr = base + (long)(kt*64) * LDR + Dd  + h*HD;
        const float* vptr = base + (long)(kt*64) * LDR + 2*Dd + h*HD;
#pragma unroll
        for (int w = 0; w < 4; w++) {
            int dd = cq + w*16;
            float4 kv = *(const float4*)&kptr[(long)row*LDR + dd];
            Ks[(dd+0)*68 + row] = kv.x;
            Ks[(dd+1)*68 + row] = kv.y;
            Ks[(dd+2)*68 + row] = kv.z;
            Ks[(dd+3)*68 + row] = kv.w;
            float4 vv = *(const float4*)&vptr[(long)row*LDR + dd];
            *(float4*)&Vs[row*68 + dd] = vv;
        }
        __syncthreads();

        float s[4][4] = {};
#pragma unroll
        for (int d = 0; d < 64; d++) {
            float4 k4 = *(const float4*)&Ks[d*68 + tx*4];
            float a0 = Qs[(ty*4+0)*68 + d];
            float a1 = Qs[(ty*4+1)*68 + d];
            float a2 = Qs[(ty*4+2)*68 + d];
            float a3 = Qs[(ty*4+3)*68 + d];
            s[0][0] += a0*k4.x; s[0][1] += a0*k4.y; s[0][2] += a0*k4.z; s[0][3] += a0*k4.w;
            s[1][0] += a1*k4.x; s[1][1] += a1*k4.y; s[1][2] += a1*k4.z; s[1][3] += a1*k4.w;
            s[2][0] += a2*k4.x; s[2][1] += a2*k4.y; s[2][2] += a2*k4.z; s[2][3] += a2*k4.w;
            s[3][0] += a3*k4.x; s[3][1] += a3*k4.y; s[3][2] += a3*k4.z; s[3][3] += a3*k4.w;
        }

#pragma unroll
        for (int i = 0; i < 4; i++) {
            float mt = fmaxf(fmaxf(s[i][0], s[i][1]), fmaxf(s[i][2], s[i][3]));
#pragma unroll
            for (int off = 1; off < 16; off <<= 1)
                mt = fmaxf(mt, __shfl_xor_sync(0xffffffffu, mt, off));
            float mn = fmaxf(m[i], mt);
            float corr = __expf(m[i] - mn);
            m[i] = mn;
            l[i] *= corr;
#pragma unroll
            for (int j = 0; j < 4; j++) o[i][j] *= corr;
            float p0 = __expf(s[i][0] - mn);
            float p1 = __expf(s[i][1] - mn);
            float p2 = __expf(s[i][2] - mn);
            float p3 = __expf(s[i][3] - mn);
            l[i] += p0 + p1 + p2 + p3;
            float4 p4 = make_float4(p0, p1, p2, p3);
            *(float4*)&Ps[(ty*4+i)*68 + tx*4] = p4;
        }
        __syncthreads();

#pragma unroll
        for (int k = 0; k < 64; k++) {
            float4 v4 = *(const float4*)&Vs[k*68 + tx*4];
            float p0 = Ps[(ty*4+0)*68 + k];
            float p1 = Ps[(ty*4+1)*68 + k];
            float p2 = Ps[(ty*4+2)*68 + k];
            float p3 = Ps[(ty*4+3)*68 + k];
            o[0][0] += p0*v4.x; o[0][1] += p0*v4.y; o[0][2] += p0*v4.z; o[0][3] += p0*v4.w;
            o[1][0] += p1*v4.x; o[1][1] += p1*v4.y; o[1][2] += p1*v4.z; o[1][3] += p1*v4.w;
            o[2][0] += p2*v4.x; o[2][1] += p2*v4.y; o[2][2] += p2*v4.z; o[2][3] += p2*v4.w;
            o[3][0] += p3*v4.x; o[3][1] += p3*v4.y; o[3][2] += p3*v4.z; o[3][3] += p3*v4.w;
        }
    }

    float* optr = ctx + ((long)(b*Tt + qt*64)) * Dd + h*HD;
#pragma unroll
    for (int i = 0; i < 4; i++) {
        float li = l[i];
#pragma unroll
        for (int off = 1; off < 16; off <<= 1)
            li += __shfl_xor_sync(0xffffffffu, li, off);
        float inv = 1.0f / li;
        float4 r = make_float4(o[i][0]*inv, o[i][1]*inv, o[i][2]*inv, o[i][3]*inv);
        *(float4*)&optr[(long)(ty*4+i)*Dd + tx*4] = r;
    }
}

// ---------------- Gaussian kernel weights + row sums ----------------
__global__ __launch_bounds__(256) void kw_kernel(
    const int* __restrict__ posv, const int* __restrict__ posh,
    float* __restrict__ kw, float* __restrict__ ksum)
{
    long bq = blockIdx.x;
    int b = (int)(bq >> 10), q = (int)(bq & 1023);
    int tid = threadIdx.x;
    const int* pvb = posv + (long)b*Tt;
    const int* phb = posh + (long)b*Tt;
    int qv = pvb[q], qh = phb[q];
    int k0 = tid * 4;
    int4 kv4 = *(const int4*)&pvb[k0];
    int4 kh4 = *(const int4*)&phb[k0];
    const float c = -1.0f / 512.0f;
    int dvx = qv-kv4.x, dhx = qh-kh4.x;
    int dvy = qv-kv4.y, dhy = qh-kh4.y;
    int dvz = qv-kv4.z, dhz = qh-kh4.z;
    int dvw = qv-kv4.w, dhw = qh-kh4.w;
    float4 w4;
    w4.x = __expf((float)(dvx*dvx + dhx*dhx) * c);
    w4.y = __expf((float)(dvy*dvy + dhy*dhy) * c);
    w4.z = __expf((float)(dvz*dvz + dhz*dhz) * c);
    w4.w = __expf((float)(dvw*dvw + dhw*dhw) * c);
    *(float4*)&kw[bq*Tt + k0] = w4;
    float s = w4.x + w4.y + w4.z + w4.w;
#pragma unroll
    for (int o = 16; o; o >>= 1) s += __shfl_xor_sync(0xffffffffu, s, o);
    __shared__ float red[8];
    if ((tid & 31) == 0) red[tid >> 5] = s;
    __syncthreads();
    if (tid == 0) {
        float t = 0.f;
#pragma unroll
        for (int i = 0; i < 8; i++) t += red[i];
        ksum[bq] = t;
    }
}

// ---------------- combine (x1) + LayerNorm2 fused ----------------
__global__ __launch_bounds__(256) void combine_ln2_kernel(
    const float* __restrict__ x, const float* __restrict__ stdo,
    const float* __restrict__ ko, const float* __restrict__ ksum,
    const float* __restrict__ gate,
    const float* __restrict__ w, const float* __restrict__ bb,
    float* __restrict__ x1, float* __restrict__ xn2)
{
    int warp = threadIdx.x >> 5, lane = threadIdx.x & 31;
    long row = (long)blockIdx.x * 8 + warp;
    float g = 1.0f / (1.0f + __expf(-gate[0]));
    float gi = 1.0f - g;
    float inv_ks = 1.0f / ksum[row];
    long base = row * Dd;
    float4 v[4];
    float s = 0.f, sq = 0.f;
#pragma unroll
    for (int i = 0; i < 4; i++) {
        int d = lane*4 + i*128;
        float4 xv = *(const float4*)&x[base + d];
        float4 sv = *(const float4*)&stdo[base + d];
        float4 kv = *(const float4*)&ko[base + d];
        float4 o4;
        o4.x = xv.x + g*sv.x + gi*kv.x*inv_ks;
        o4.y = xv.y + g*sv.y + gi*kv.y*inv_ks;
        o4.z = xv.z + g*sv.z + gi*kv.z*inv_ks;
        o4.w = xv.w + g*sv.w + gi*kv.w*inv_ks;
        *(float4*)&x1[base + d] = o4;
        v[i] = o4;
        s  += o4.x + o4.y + o4.z + o4.w;
        sq += o4.x*o4.x + o4.y*o4.y + o4.z*o4.z + o4.w*o4.w;
    }
#pragma unroll
    for (int o = 16; o; o >>= 1) {
        s  += __shfl_xor_sync(0xffffffffu, s,  o);
        sq += __shfl_xor_sync(0xffffffffu, sq, o);
    }
    float mean = s * (1.0f/512.0f);
    float var  = sq * (1.0f/512.0f) - mean*mean;
    float r    = rsqrtf(var + 1e-5f);
#pragma unroll
    for (int i = 0; i < 4; i++) {
        int d = lane*4 + i*128;
        float4 wv = *(const float4*)&w[d];
        float4 bv = *(const float4*)&bb[d];
        float4 o4;
        o4.x = (v[i].x - mean)*r*wv.x + bv.x;
        o4.y = (v[i].y - mean)*r*wv.y + bv.y;
        o4.z = (v[i].z - mean)*r*wv.z + bv.z;
        o4.w = (v[i].w - mean)*r*wv.w + bv.w;
        *(float4*)&xn2[base + d] = o4;
    }
}

// ---------------- launch ----------------
extern "C" void kernel_launch(void* const* d_in, const int* in_sizes, int n_in,
                              void* d_out, int out_size)
{
    const float* x      = (const float*)d_in[0];
    const int*   posv   = (const int*)  d_in[1];
    const int*   posh   = (const int*)  d_in[2];
    const float* n1w    = (const float*)d_in[3];
    const float* n1b    = (const float*)d_in[4];
    const float* in_w   = (const float*)d_in[5];
    const float* in_b   = (const float*)d_in[6];
    const float* out_w  = (const float*)d_in[7];
    const float* out_b  = (const float*)d_in[8];
    const float* n2w    = (const float*)d_in[9];
    const float* n2b    = (const float*)d_in[10];
    const float* w1     = (const float*)d_in[11];
    const float* b1     = (const float*)d_in[12];
    const float* w2     = (const float*)d_in[13];
    const float* b2     = (const float*)d_in[14];
    const float* gate   = (const float*)d_in[15];
    float* out = (float*)d_out;

    float *xn, *qkv, *ctx, *stdo, *kw, *ksum, *ko, *x1, *xn2, *hbuf;
    cudaGetSymbolAddress((void**)&xn,   g_xn);
    cudaGetSymbolAddress((void**)&qkv,  g_qkv);
    cudaGetSymbolAddress((void**)&ctx,  g_ctx);
    cudaGetSymbolAddress((void**)&stdo, g_std);
    cudaGetSymbolAddress((void**)&kw,   g_kw);
    cudaGetSymbolAddress((void**)&ksum, g_ksum);
    cudaGetSymbolAddress((void**)&ko,   g_ko);
    cudaGetSymbolAddress((void**)&x1,   g_x1);
    cudaGetSymbolAddress((void**)&xn2,  g_xn2);
    cudaGetSymbolAddress((void**)&hbuf, g_h);

    // 1) LN1
    ln_kernel<<<ROWS/8, 256>>>(x, n1w, n1b, xn);

    // 2) QKV = xn @ in_w^T + in_b   [8192 x 1536]
    gemm128<true, 0><<<dim3(3*Dd/128, ROWS/128, 1), 256>>>(
        xn, in_w, in_b, nullptr, qkv, ROWS, 3*Dd, Dd, 0, 0, 0);

    // 3) flash attention -> ctx [8192 x 512]
    {
        static const int SMEM = 4 * 4352 * 4;  // 69632 B
        cudaFuncSetAttribute(attn_kernel, cudaFuncAttributeMaxDynamicSharedMemorySize, SMEM);
        attn_kernel<<<dim3(Tt/64, Hh, Bb), 256, SMEM>>>(qkv, ctx);
    }

    // 4) std_out = ctx @ out_w^T + out_b
    gemm128<true, 0><<<dim3(Dd/128, ROWS/128, 1), 256>>>(
        ctx, out_w, out_b, nullptr, stdo, ROWS, Dd, Dd, 0, 0, 0);

    // 5) Gaussian kernel weights (unnormalized) + row sums
    kw_kernel<<<ROWS, 256>>>(posv, posh, kw, ksum);

    // 6) ko = kw @ xn   (batched, B not transposed)
    gemm128<false, 0><<<dim3(Dd/128, Tt/128, Bb), 256>>>(
        kw, xn, nullptr, nullptr, ko, Tt, Dd, Tt,
        (long)Tt*Tt, (long)Tt*Dd, (long)Tt*Dd);

    // 7) x1 = x + g*std + (1-g)*ko/ksum ; xn2 = LN2(x1)
    combine_ln2_kernel<<<ROWS/8, 256>>>(x, stdo, ko, ksum, gate, n2w, n2b, x1, xn2);

    // 8) h = gelu(xn2 @ w1^T + b1)   [8192 x 2048]
    gemm128<true, 1><<<dim3(D4/128, ROWS/128, 1), 256>>>(
        xn2, w1, b1, nullptr, hbuf, ROWS, D4, Dd, 0, 0, 0);

    // 9) out = x1 + h @ w2^T + b2    [8192 x 512]
    gemm128<true, 2><<<dim3(Dd/128, ROWS/128, 1), 256>>>(
        hbuf, w2, b2, x1, out, ROWS, Dd, D4, 0, 0, 0);
}

// round 4
// speedup vs baseline: 1.2072x; 1.0542x over previous
#include <cuda_runtime.h>
#include <cuda_bf16.h>
#include <mma.h>
#include <math.h>
#include <stdint.h>

using namespace nvcuda;

#define Bb 8
#define Tt 1024
#define Dd 512
#define Hh 8
#define HD 64
#define D4 2048
#define ROWS (Bb*Tt)

// ---------------- scratch (device globals) ----------------
__device__ __nv_bfloat16 g_xnA [ROWS*3*Dd];        // LN1 out, A-form [hi|lo|hi]
__device__ __nv_bfloat16 g_xnB [Bb*3*Tt*Dd];       // LN1 out, B-form rows [hi;hi;lo]
__device__ float         g_qkv [ROWS*3*Dd];
__device__ __nv_bfloat16 g_ctxA[ROWS*3*Dd];        // attn out, A-form
__device__ float         g_stdo[ROWS*Dd];
__device__ __nv_bfloat16 g_kwA [Bb*Tt*3*Tt];       // kernel weights, A-form
__device__ float         g_ksum[ROWS];
__device__ float         g_ko  [ROWS*Dd];
__device__ float         g_x1  [ROWS*Dd];
__device__ __nv_bfloat16 g_xn2A[ROWS*3*Dd];        // LN2 out, A-form
__device__ __nv_bfloat16 g_hA  [ROWS*3*D4];        // MLP hidden, A-form
__device__ __nv_bfloat16 g_wIN [3*Dd*3*Dd];        // in_w',  B-form [hi|hi|lo]
__device__ __nv_bfloat16 g_wOUT[Dd*3*Dd];
__device__ __nv_bfloat16 g_w1  [D4*3*Dd];
__device__ __nv_bfloat16 g_w2  [Dd*3*D4];

// ---------------- split helpers ----------------
__device__ __forceinline__ void split_bf(float v, __nv_bfloat16& h, __nv_bfloat16& l) {
    h = __float2bfloat16(v);
    l = __float2bfloat16(v - __bfloat162float(h));
}
__device__ __forceinline__ void split4_u2(float4 v, uint2& H, uint2& L) {
    __nv_bfloat16 hx,lx,hy,ly,hz,lz,hw,lw;
    split_bf(v.x,hx,lx); split_bf(v.y,hy,ly);
    split_bf(v.z,hz,lz); split_bf(v.w,hw,lw);
    __nv_bfloat162 h01 = __halves2bfloat162(hx,hy);
    __nv_bfloat162 h23 = __halves2bfloat162(hz,hw);
    __nv_bfloat162 l01 = __halves2bfloat162(lx,ly);
    __nv_bfloat162 l23 = __halves2bfloat162(lz,lw);
    H.x = *reinterpret_cast<unsigned*>(&h01); H.y = *reinterpret_cast<unsigned*>(&h23);
    L.x = *reinterpret_cast<unsigned*>(&l01); L.y = *reinterpret_cast<unsigned*>(&l23);
}
__device__ __forceinline__ float gelu_exact(float v) {
    return 0.5f * v * (1.0f + erff(v * 0.7071067811865476f));
}

// ---------------- weight conversion: W[N][K] -> W'[N][3K] = [hi|hi|lo] ----------------
__global__ __launch_bounds__(256) void conv_w_kernel(
    const float* __restrict__ W, __nv_bfloat16* __restrict__ Wp, int K, int total4)
{
    int idx = blockIdx.x * 256 + threadIdx.x;
    if (idx >= total4) return;
    long e = (long)idx * 4;
    int r = (int)(e / K), c = (int)(e % K);
    float4 v = *(const float4*)&W[(long)r * K + c];
    uint2 H, L; split4_u2(v, H, L);
    __nv_bfloat16* row = Wp + (long)r * 3 * K;
    *(uint2*)&row[c]         = H;
    *(uint2*)&row[K + c]     = H;
    *(uint2*)&row[2*K + c]   = L;
}

// ---------------- bf16-split GEMM: C = A'[M][3K] x B' (+bias, epi) ----------------
// BROW=false: B' [N][3K] row-major (weights, col_major frags)
// BROW=true : B' [3K][N] row-major (xnB, row_major frags)
// EPI: 0 fp32+bias, 1 bias+gelu -> bf16 A-form triple, 2 fp32+bias+residual
template<bool BROW, int EPI>
__global__ __launch_bounds__(256) void gemm_bf16(
    const __nv_bfloat16* __restrict__ A, const __nv_bfloat16* __restrict__ B,
    const float* __restrict__ bias, const float* __restrict__ res,
    void* __restrict__ Cout, int N, int Kp,
    long sA, long sB, long sC)
{
    __shared__ __align__(128) __nv_bfloat16 As[2][128*48];
    __shared__ __align__(128) __nv_bfloat16 Bs[2][128*48];

    int z = blockIdx.z;
    const int tid = threadIdx.x;
    int w = tid >> 5, lane = tid & 31, wm = w >> 2, wn = w & 3;
    int m0 = blockIdx.y << 7, n0 = blockIdx.x << 7;
    A += z * sA; B += z * sB;

    const __nv_bfloat16* Ap = A + (long)(m0 + (tid >> 1)) * Kp + (tid & 1) * 16;
    const __nv_bfloat16* Bp = BROW
        ? (B + (long)(tid >> 3) * N + n0 + (tid & 7) * 16)
        : (B + (long)(n0 + (tid >> 1)) * Kp + (tid & 1) * 16);

    int nk = Kp >> 5;
    wmma::fragment<wmma::accumulator, 16, 16, 16, float> acc[4][2];
#pragma unroll
    for (int i = 0; i < 4; i++)
#pragma unroll
        for (int j = 0; j < 2; j++) wmma::fill_fragment(acc[i][j], 0.f);

    uint4 ra0, ra1, rb0, rb1;
#define LOAD_REGS(kt) do { \
        long ko = (long)(kt) * 32; \
        ra0 = *(const uint4*)(Ap + ko); \
        ra1 = *(const uint4*)(Ap + ko + 8); \
        if (BROW) { rb0 = *(const uint4*)(Bp + ko * N); rb1 = *(const uint4*)(Bp + ko * N + 8); } \
        else      { rb0 = *(const uint4*)(Bp + ko);     rb1 = *(const uint4*)(Bp + ko + 8); } \
    } while (0)
#define STORE_REGS(st) do { \
        int ar = tid >> 1, ac = (tid & 1) * 16; \
        *(uint4*)&As[st][ar*48 + ac]     = ra0; \
        *(uint4*)&As[st][ar*48 + ac + 8] = ra1; \
        if (BROW) { int br = tid >> 3, bc = (tid & 7) * 16; \
            *(uint4*)&Bs[st][br*144 + bc]     = rb0; \
            *(uint4*)&Bs[st][br*144 + bc + 8] = rb1; } \
        else { \
            *(uint4*)&Bs[st][ar*48 + ac]     = rb0; \
            *(uint4*)&Bs[st][ar*48 + ac + 8] = rb1; } \
    } while (0)

    LOAD_REGS(0); STORE_REGS(0); __syncthreads();
    if (nk > 1) LOAD_REGS(1);

    for (int kt = 0; kt < nk; kt++) {
        int st = kt & 1;
#pragma unroll
        for (int kk = 0; kk < 2; kk++) {
            wmma::fragment<wmma::matrix_a, 16, 16, 16, __nv_bfloat16, wmma::row_major> af[4];
#pragma unroll
            for (int i = 0; i < 4; i++)
                wmma::load_matrix_sync(af[i], &As[st][(wm*64 + i*16)*48 + kk*16], 48);
            if (BROW) {
                wmma::fragment<wmma::matrix_b, 16, 16, 16, __nv_bfloat16, wmma::row_major> bf[2];
#pragma unroll
                for (int j = 0; j < 2; j++)
                    wmma::load_matrix_sync(bf[j], &Bs[st][(kk*16)*144 + wn*32 + j*16], 144);
#pragma unroll
                for (int i = 0; i < 4; i++)
#pragma unroll
                    for (int j = 0; j < 2; j++)
                        wmma::mma_sync(acc[i][j], af[i], bf[j], acc[i][j]);
            } else {
                wmma::fragment<wmma::matrix_b, 16, 16, 16, __nv_bfloat16, wmma::col_major> bf[2];
#pragma unroll
                for (int j = 0; j < 2; j++)
                    wmma::load_matrix_sync(bf[j], &Bs[st][(wn*32 + j*16)*48 + kk*16], 48);
#pragma unroll
                for (int i = 0; i < 4; i++)
#pragma unroll
                    for (int j = 0; j < 2; j++)
                        wmma::mma_sync(acc[i][j], af[i], bf[j], acc[i][j]);
            }
        }
        if (kt + 1 < nk) {
            STORE_REGS(st ^ 1);
            __syncthreads();
            if (kt + 2 < nk) LOAD_REGS(kt + 2);
        }
    }
    __syncthreads();

    // epilogue through smem staging (reuse As)
    float* EP = (float*)&As[0][0] + w * 256;
    int r = lane >> 1, c0 = (lane & 1) * 8;
    long ldc = (EPI == 1) ? (long)3 * N : (long)N;
#pragma unroll
    for (int i = 0; i < 4; i++) {
#pragma unroll
        for (int j = 0; j < 2; j++) {
            wmma::store_matrix_sync(EP, acc[i][j], 16, wmma::mem_row_major);
            __syncwarp();
            long grow = m0 + wm*64 + i*16 + r;
            int  gcol = n0 + wn*32 + j*16 + c0;
            float4 v0 = *(float4*)&EP[r*16 + c0];
            float4 v1 = *(float4*)&EP[r*16 + c0 + 4];
            if (bias) {
                float4 b0 = *(const float4*)&bias[gcol];
                float4 b1 = *(const float4*)&bias[gcol + 4];
                v0.x += b0.x; v0.y += b0.y; v0.z += b0.z; v0.w += b0.w;
                v1.x += b1.x; v1.y += b1.y; v1.z += b1.z; v1.w += b1.w;
            }
            if (EPI == 1) {
                v0.x = gelu_exact(v0.x); v0.y = gelu_exact(v0.y);
                v0.z = gelu_exact(v0.z); v0.w = gelu_exact(v0.w);
                v1.x = gelu_exact(v1.x); v1.y = gelu_exact(v1.y);
                v1.z = gelu_exact(v1.z); v1.w = gelu_exact(v1.w);
                uint2 H0,L0,H1,L1;
                split4_u2(v0,H0,L0); split4_u2(v1,H1,L1);
                __nv_bfloat16* Crow = (__nv_bfloat16*)Cout + grow * ldc;
                uint4 Hq = make_uint4(H0.x,H0.y,H1.x,H1.y);
                uint4 Lq = make_uint4(L0.x,L0.y,L1.x,L1.y);
                *(uint4*)&Crow[gcol]         = Hq;
                *(uint4*)&Crow[N + gcol]     = Lq;
                *(uint4*)&Crow[2*N + gcol]   = Hq;
            } else {
                float* C = (float*)Cout + z * sC;
                if (EPI == 2) {
                    float4 r0 = *(const float4*)&res[grow*N + gcol];
                    float4 r1 = *(const float4*)&res[grow*N + gcol + 4];
                    v0.x += r0.x; v0.y += r0.y; v0.z += r0.z; v0.w += r0.w;
                    v1.x += r1.x; v1.y += r1.y; v1.z += r1.z; v1.w += r1.w;
                }
                *(float4*)&C[grow*ldc + gcol]     = v0;
                *(float4*)&C[grow*ldc + gcol + 4] = v1;
            }
            __syncwarp();
        }
    }
#undef LOAD_REGS
#undef STORE_REGS
}

// ---------------- LN1: fp32 in -> A-form + B-form bf16 out ----------------
__global__ __launch_bounds__(256) void ln1_kernel(
    const float* __restrict__ x, const float* __restrict__ w,
    const float* __restrict__ b,
    __nv_bfloat16* __restrict__ xnA, __nv_bfloat16* __restrict__ xnB)
{
    int warp = threadIdx.x >> 5, lane = threadIdx.x & 31;
    long row = (long)blockIdx.x * 8 + warp;
    const float* xr = x + row * Dd;
    float4 v[4];
    float s = 0.f, sq = 0.f;
#pragma unroll
    for (int i = 0; i < 4; i++) {
        v[i] = *(const float4*)&xr[lane*4 + i*128];
        s  += v[i].x + v[i].y + v[i].z + v[i].w;
        sq += v[i].x*v[i].x + v[i].y*v[i].y + v[i].z*v[i].z + v[i].w*v[i].w;
    }
#pragma unroll
    for (int o = 16; o; o >>= 1) {
        s  += __shfl_xor_sync(0xffffffffu, s,  o);
        sq += __shfl_xor_sync(0xffffffffu, sq, o);
    }
    float mean = s * (1.0f/512.0f);
    float var  = sq * (1.0f/512.0f) - mean*mean;
    float rr   = rsqrtf(var + 1e-5f);
    int bz = (int)(row >> 10), rz = (int)(row & 1023);
    __nv_bfloat16* arow = xnA + row * (3*Dd);
    __nv_bfloat16* bbase = xnB + (long)bz * 3*Tt*Dd;
#pragma unroll
    for (int i = 0; i < 4; i++) {
        int d = lane*4 + i*128;
        float4 wv = *(const float4*)&w[d];
        float4 bv = *(const float4*)&b[d];
        float4 o4;
        o4.x = (v[i].x - mean)*rr*wv.x + bv.x;
        o4.y = (v[i].y - mean)*rr*wv.y + bv.y;
        o4.z = (v[i].z - mean)*rr*wv.z + bv.z;
        o4.w = (v[i].w - mean)*rr*wv.w + bv.w;
        uint2 H, L; split4_u2(o4, H, L);
        *(uint2*)&arow[d]          = H;
        *(uint2*)&arow[Dd + d]     = L;
        *(uint2*)&arow[2*Dd + d]   = H;
        *(uint2*)&bbase[(long)rz*Dd + d]            = H;
        *(uint2*)&bbase[(long)(Tt + rz)*Dd + d]     = H;
        *(uint2*)&bbase[(long)(2*Tt + rz)*Dd + d]   = L;
    }
}

// ---------------- flash attention, fp32, writes ctx in A-form bf16 ----------------
__global__ __launch_bounds__(256) void attn_kernel(
    const float* __restrict__ qkv, __nv_bfloat16* __restrict__ ctxA)
{
    extern __shared__ float smf[];
    float* Qs = smf;
    float* Ks = smf + 4352;
    float* Vs = smf + 8704;
    float* Ps = smf + 13056;

    int b = blockIdx.z, h = blockIdx.y, qt = blockIdx.x;
    int tid = threadIdx.x, tx = tid & 15, ty = tid >> 4;
    const int LDR = 3*Dd;
    const float* base = qkv + (long)b * Tt * LDR;
    int row = tid >> 2, cq = (tid & 3) << 2;

    {
        const float* qptr = base + (long)(qt*64) * LDR + h*HD;
#pragma unroll
        for (int w = 0; w < 4; w++) {
            int dd = cq + w*16;
            float4 v = *(const float4*)&qptr[(long)row*LDR + dd];
            v.x *= 0.125f; v.y *= 0.125f; v.z *= 0.125f; v.w *= 0.125f;
            *(float4*)&Qs[row*68 + dd] = v;
        }
    }

    float m[4], l[4], o[4][4];
#pragma unroll
    for (int i = 0; i < 4; i++) {
        m[i] = -1e30f; l[i] = 0.f;
#pragma unroll
        for (int j = 0; j < 4; j++) o[i][j] = 0.f;
    }

    for (int kt = 0; kt < Tt/64; kt++) {
        __syncthreads();
        const float* kptr = base + (long)(kt*64) * LDR + Dd  + h*HD;
        const float* vptr = base + (long)(kt*64) * LDR + 2*Dd + h*HD;
#pragma unroll
        for (int w = 0; w < 4; w++) {
            int dd = cq + w*16;
            float4 kv = *(const float4*)&kptr[(long)row*LDR + dd];
            Ks[(dd+0)*68 + row] = kv.x;
            Ks[(dd+1)*68 + row] = kv.y;
            Ks[(dd+2)*68 + row] = kv.z;
            Ks[(dd+3)*68 + row] = kv.w;
            float4 vv = *(const float4*)&vptr[(long)row*LDR + dd];
            *(float4*)&Vs[row*68 + dd] = vv;
        }
        __syncthreads();

        float s[4][4] = {};
#pragma unroll
        for (int d = 0; d < 64; d++) {
            float4 k4 = *(const float4*)&Ks[d*68 + tx*4];
            float a0 = Qs[(ty*4+0)*68 + d];
            float a1 = Qs[(ty*4+1)*68 + d];
            float a2 = Qs[(ty*4+2)*68 + d];
            float a3 = Qs[(ty*4+3)*68 + d];
            s[0][0] += a0*k4.x; s[0][1] += a0*k4.y; s[0][2] += a0*k4.z; s[0][3] += a0*k4.w;
            s[1][0] += a1*k4.x; s[1][1] += a1*k4.y; s[1][2] += a1*k4.z; s[1][3] += a1*k4.w;
            s[2][0] += a2*k4.x; s[2][1] += a2*k4.y; s[2][2] += a2*k4.z; s[2][3] += a2*k4.w;
            s[3][0] += a3*k4.x; s[3][1] += a3*k4.y; s[3][2] += a3*k4.z; s[3][3] += a3*k4.w;
        }

#pragma unroll
        for (int i = 0; i < 4; i++) {
            float mt = fmaxf(fmaxf(s[i][0], s[i][1]), fmaxf(s[i][2], s[i][3]));
#pragma unroll
            for (int off = 1; off < 16; off <<= 1)
                mt = fmaxf(mt, __shfl_xor_sync(0xffffffffu, mt, off));
            float mn = fmaxf(m[i], mt);
            float corr = __expf(m[i] - mn);
            m[i] = mn;
            l[i] *= corr;
#pragma unroll
            for (int j = 0; j < 4; j++) o[i][j] *= corr;
            float p0 = __expf(s[i][0] - mn);
            float p1 = __expf(s[i][1] - mn);
            float p2 = __expf(s[i][2] - mn);
            float p3 = __expf(s[i][3] - mn);
            l[i] += p0 + p1 + p2 + p3;
            *(float4*)&Ps[(ty*4+i)*68 + tx*4] = make_float4(p0, p1, p2, p3);
        }
        __syncthreads();

#pragma unroll
        for (int k = 0; k < 64; k++) {
            float4 v4 = *(const float4*)&Vs[k*68 + tx*4];
            float p0 = Ps[(ty*4+0)*68 + k];
            float p1 = Ps[(ty*4+1)*68 + k];
            float p2 = Ps[(ty*4+2)*68 + k];
            float p3 = Ps[(ty*4+3)*68 + k];
            o[0][0] += p0*v4.x; o[0][1] += p0*v4.y; o[0][2] += p0*v4.z; o[0][3] += p0*v4.w;
            o[1][0] += p1*v4.x; o[1][1] += p1*v4.y; o[1][2] += p1*v4.z; o[1][3] += p1*v4.w;
            o[2][0] += p2*v4.x; o[2][1] += p2*v4.y; o[2][2] += p2*v4.z; o[2][3] += p2*v4.w;
            o[3][0] += p3*v4.x; o[3][1] += p3*v4.y; o[3][2] += p3*v4.z; o[3][3] += p3*v4.w;
        }
    }

#pragma unroll
    for (int i = 0; i < 4; i++) {
        float li = l[i];
#pragma unroll
        for (int off = 1; off < 16; off <<= 1)
            li += __shfl_xor_sync(0xffffffffu, li, off);
        float inv = 1.0f / li;
        float4 rv = make_float4(o[i][0]*inv, o[i][1]*inv, o[i][2]*inv, o[i][3]*inv);
        long grow = (long)(b*Tt + qt*64 + ty*4 + i);
        int col = h*HD + tx*4;
        uint2 H, L; split4_u2(rv, H, L);
        __nv_bfloat16* crow = ctxA + grow * (3*Dd);
        *(uint2*)&crow[col]          = H;
        *(uint2*)&crow[Dd + col]     = L;
        *(uint2*)&crow[2*Dd + col]   = H;
    }
}

// ---------------- Gaussian kernel weights (A-form bf16) + row sums ----------------
__global__ __launch_bounds__(256) void kw_kernel(
    const int* __restrict__ posv, const int* __restrict__ posh,
    __nv_bfloat16* __restrict__ kwA, float* __restrict__ ksum)
{
    long bq = blockIdx.x;
    int b = (int)(bq >> 10), q = (int)(bq & 1023);
    int tid = threadIdx.x;
    const int* pvb = posv + (long)b*Tt;
    const int* phb = posh + (long)b*Tt;
    int qv = pvb[q], qh = phb[q];
    int k0 = tid * 4;
    int4 kv4 = *(const int4*)&pvb[k0];
    int4 kh4 = *(const int4*)&phb[k0];
    const float c = -1.0f / 512.0f;
    int dvx = qv-kv4.x, dhx = qh-kh4.x;
    int dvy = qv-kv4.y, dhy = qh-kh4.y;
    int dvz = qv-kv4.z, dhz = qh-kh4.z;
    int dvw = qv-kv4.w, dhw = qh-kh4.w;
    float4 w4;
    w4.x = __expf((float)(dvx*dvx + dhx*dhx) * c);
    w4.y = __expf((float)(dvy*dvy + dhy*dhy) * c);
    w4.z = __expf((float)(dvz*dvz + dhz*dhz) * c);
    w4.w = __expf((float)(dvw*dvw + dhw*dhw) * c);
    uint2 H, L; split4_u2(w4, H, L);
    __nv_bfloat16* row = kwA + bq * (3*Tt);
    *(uint2*)&row[k0]          = H;
    *(uint2*)&row[Tt + k0]     = L;
    *(uint2*)&row[2*Tt + k0]   = H;
    float s = w4.x + w4.y + w4.z + w4.w;
#pragma unroll
    for (int o = 16; o; o >>= 1) s += __shfl_xor_sync(0xffffffffu, s, o);
    __shared__ float red[8];
    if ((tid & 31) == 0) red[tid >> 5] = s;
    __syncthreads();
    if (tid == 0) {
        float t = 0.f;
#pragma unroll
        for (int i = 0; i < 8; i++) t += red[i];
        ksum[bq] = t;
    }
}

// ---------------- combine (x1 fp32) + LN2 -> A-form bf16 ----------------
__global__ __launch_bounds__(256) void combine_ln2_kernel(
    const float* __restrict__ x, const float* __restrict__ stdo,
    const float* __restrict__ ko, const float* __restrict__ ksum,
    const float* __restrict__ gate,
    const float* __restrict__ w, const float* __restrict__ bb,
    float* __restrict__ x1, __nv_bfloat16* __restrict__ xn2A)
{
    int warp = threadIdx.x >> 5, lane = threadIdx.x & 31;
    long row = (long)blockIdx.x * 8 + warp;
    float g = 1.0f / (1.0f + __expf(-gate[0]));
    float gi = 1.0f - g;
    float inv_ks = 1.0f / ksum[row];
    long base = row * Dd;
    float4 v[4];
    float s = 0.f, sq = 0.f;
#pragma unroll
    for (int i = 0; i < 4; i++) {
        int d = lane*4 + i*128;
        float4 xv = *(const float4*)&x[base + d];
        float4 sv = *(const float4*)&stdo[base + d];
        float4 kv = *(const float4*)&ko[base + d];
        float4 o4;
        o4.x = xv.x + g*sv.x + gi*kv.x*inv_ks;
        o4.y = xv.y + g*sv.y + gi*kv.y*inv_ks;
        o4.z = xv.z + g*sv.z + gi*kv.z*inv_ks;
        o4.w = xv.w + g*sv.w + gi*kv.w*inv_ks;
        *(float4*)&x1[base + d] = o4;
        v[i] = o4;
        s  += o4.x + o4.y + o4.z + o4.w;
        sq += o4.x*o4.x + o4.y*o4.y + o4.z*o4.z + o4.w*o4.w;
    }
#pragma unroll
    for (int o = 16; o; o >>= 1) {
        s  += __shfl_xor_sync(0xffffffffu, s,  o);
        sq += __shfl_xor_sync(0xffffffffu, sq, o);
    }
    float mean = s * (1.0f/512.0f);
    float var  = sq * (1.0f/512.0f) - mean*mean;
    float rr   = rsqrtf(var + 1e-5f);
    __nv_bfloat16* arow = xn2A + row * (3*Dd);
#pragma unroll
    for (int i = 0; i < 4; i++) {
        int d = lane*4 + i*128;
        float4 wv = *(const float4*)&w[d];
        float4 bv = *(const float4*)&bb[d];
        float4 o4;
        o4.x = (v[i].x - mean)*rr*wv.x + bv.x;
        o4.y = (v[i].y - mean)*rr*wv.y + bv.y;
        o4.z = (v[i].z - mean)*rr*wv.z + bv.z;
        o4.w = (v[i].w - mean)*rr*wv.w + bv.w;
        uint2 H, L; split4_u2(o4, H, L);
        *(uint2*)&arow[d]          = H;
        *(uint2*)&arow[Dd + d]     = L;
        *(uint2*)&arow[2*Dd + d]   = H;
    }
}

// ---------------- launch ----------------
extern "C" void kernel_launch(void* const* d_in, const int* in_sizes, int n_in,
                              void* d_out, int out_size)
{
    const float* x      = (const float*)d_in[0];
    const int*   posv   = (const int*)  d_in[1];
    const int*   posh   = (const int*)  d_in[2];
    const float* n1w    = (const float*)d_in[3];
    const float* n1b    = (const float*)d_in[4];
    const float* in_w   = (const float*)d_in[5];
    const float* in_b   = (const float*)d_in[6];
    const float* out_w  = (const float*)d_in[7];
    const float* out_b  = (const float*)d_in[8];
    const float* n2w    = (const float*)d_in[9];
    const float* n2b    = (const float*)d_in[10];
    const float* w1     = (const float*)d_in[11];
    const float* b1     = (const float*)d_in[12];
    const float* w2     = (const float*)d_in[13];
    const float* b2     = (const float*)d_in[14];
    const float* gate   = (const float*)d_in[15];
    float* out = (float*)d_out;

    __nv_bfloat16 *xnA, *xnB, *ctxA, *kwA, *xn2A, *hA, *wIN, *wOUT, *w1p, *w2p;
    float *qkv, *stdo, *ksum, *ko, *x1;
    cudaGetSymbolAddress((void**)&xnA,  g_xnA);
    cudaGetSymbolAddress((void**)&xnB,  g_xnB);
    cudaGetSymbolAddress((void**)&qkv,  g_qkv);
    cudaGetSymbolAddress((void**)&ctxA, g_ctxA);
    cudaGetSymbolAddress((void**)&stdo, g_stdo);
    cudaGetSymbolAddress((void**)&kwA,  g_kwA);
    cudaGetSymbolAddress((void**)&ksum, g_ksum);
    cudaGetSymbolAddress((void**)&ko,   g_ko);
    cudaGetSymbolAddress((void**)&x1,   g_x1);
    cudaGetSymbolAddress((void**)&xn2A, g_xn2A);
    cudaGetSymbolAddress((void**)&hA,   g_hA);
    cudaGetSymbolAddress((void**)&wIN,  g_wIN);
    cudaGetSymbolAddress((void**)&wOUT, g_wOUT);
    cudaGetSymbolAddress((void**)&w1p,  g_w1);
    cudaGetSymbolAddress((void**)&w2p,  g_w2);

    // weight conversions (B-form [hi|hi|lo])
    conv_w_kernel<<<(3*Dd*Dd/4 + 255)/256, 256>>>(in_w,  wIN,  Dd, 3*Dd*Dd/4);
    conv_w_kernel<<<(Dd*Dd/4   + 255)/256, 256>>>(out_w, wOUT, Dd, Dd*Dd/4);
    conv_w_kernel<<<(D4*Dd/4   + 255)/256, 256>>>(w1,    w1p,  Dd, D4*Dd/4);
    conv_w_kernel<<<(Dd*D4/4   + 255)/256, 256>>>(w2,    w2p,  D4, Dd*D4/4);

    // 1) LN1 -> xnA (A-form), xnB (B-form)
    ln1_kernel<<<ROWS/8, 256>>>(x, n1w, n1b, xnA, xnB);

    // 2) QKV = xn @ in_w^T + in_b
    gemm_bf16<false, 0><<<dim3(3*Dd/128, ROWS/128), 256>>>(
        xnA, wIN, in_b, nullptr, qkv, 3*Dd, 3*Dd, 0, 0, 0);

    // 3) flash attention -> ctxA
    {
        static const int SMEM = 4 * 4352 * 4;
        cudaFuncSetAttribute(attn_kernel, cudaFuncAttributeMaxDynamicSharedMemorySize, SMEM);
        attn_kernel<<<dim3(Tt/64, Hh, Bb), 256, SMEM>>>(qkv, ctxA);
    }

    // 4) std_out = ctx @ out_w^T + out_b
    gemm_bf16<false, 0><<<dim3(Dd/128, ROWS/128), 256>>>(
        ctxA, wOUT, out_b, nullptr, stdo, Dd, 3*Dd, 0, 0, 0);

    // 5) Gaussian kernel weights
    kw_kernel<<<ROWS, 256>>>(posv, posh, kwA, ksum);

    // 6) ko = kw @ xn (batched)
    gemm_bf16<true, 0><<<dim3(Dd/128, Tt/128, Bb), 256>>>(
        kwA, xnB, nullptr, nullptr, ko, Dd, 3*Tt,
        (long)Tt*3*Tt, (long)3*Tt*Dd, (long)Tt*Dd);

    // 7) combine + LN2
    combine_ln2_kernel<<<ROWS/8, 256>>>(x, stdo, ko, ksum, gate, n2w, n2b, x1, xn2A);

    // 8) h = gelu(xn2 @ w1^T + b1) -> hA (A-form bf16)
    gemm_bf16<false, 1><<<dim3(D4/128, ROWS/128), 256>>>(
        xn2A, w1p, b1, nullptr, hA, D4, 3*Dd, 0, 0, 0);

    // 9) out = x1 + h @ w2^T + b2
    gemm_bf16<false, 2><<<dim3(Dd/128, ROWS/128), 256>>>(
        hA, w2p, b2, x1, out, Dd, 3*D4, 0, 0, 0);
}

// round 5
// speedup vs baseline: 1.4750x; 1.2218x over previous
#include <cuda_runtime.h>
#include <cuda_bf16.h>
#include <mma.h>
#include <math.h>
#include <stdint.h>

using namespace nvcuda;

#define Bb 8
#define Tt 1024
#define Dd 512
#define Hh 8
#define HD 64
#define D4 2048
#define ROWS (Bb*Tt)

// ---------------- scratch (device globals) ----------------
__device__ __nv_bfloat16 g_xnA [ROWS*3*Dd];        // LN1 out, A-form [hi|lo|hi]
__device__ __nv_bfloat16 g_xnB [Bb*3*Tt*Dd];       // LN1 out, B-form rows [hi;hi;lo]
__device__ float         g_qkv [ROWS*3*Dd];
__device__ __nv_bfloat16 g_ctxA[ROWS*3*Dd];        // attn out, A-form
__device__ float         g_stdo[ROWS*Dd];
__device__ __nv_bfloat16 g_kwA [Bb*Tt*3*Tt];       // kernel weights, A-form
__device__ float         g_ksum[ROWS];
__device__ float         g_ko  [ROWS*Dd];
__device__ float         g_x1  [ROWS*Dd];
__device__ __nv_bfloat16 g_xn2A[ROWS*3*Dd];        // LN2 out, A-form
__device__ __nv_bfloat16 g_hA  [ROWS*3*D4];        // MLP hidden, A-form
__device__ __nv_bfloat16 g_wIN [3*Dd*3*Dd];        // in_w',  B-form [hi|hi|lo]
__device__ __nv_bfloat16 g_wOUT[Dd*3*Dd];
__device__ __nv_bfloat16 g_w1  [D4*3*Dd];
__device__ __nv_bfloat16 g_w2  [Dd*3*D4];

// ---------------- helpers ----------------
__device__ __forceinline__ uint32_t smem_u32(const void* p) {
    uint32_t a;
    asm("{ .reg .u64 t; cvta.to.shared.u64 t, %1; cvt.u32.u64 %0, t; }" : "=r"(a) : "l"(p));
    return a;
}
__device__ __forceinline__ void cp16(uint32_t sdst, const void* gsrc) {
    asm volatile("cp.async.cg.shared.global [%0], [%1], 16;" :: "r"(sdst), "l"(gsrc));
}
__device__ __forceinline__ void cp_commit() {
    asm volatile("cp.async.commit_group;" ::: "memory");
}
template<int N>
__device__ __forceinline__ void cp_wait() {
    asm volatile("cp.async.wait_group %0;" :: "n"(N) : "memory");
}
__device__ __forceinline__ void split_bf(float v, __nv_bfloat16& h, __nv_bfloat16& l) {
    h = __float2bfloat16(v);
    l = __float2bfloat16(v - __bfloat162float(h));
}
__device__ __forceinline__ void split4_u2(float4 v, uint2& H, uint2& L) {
    __nv_bfloat16 hx,lx,hy,ly,hz,lz,hw,lw;
    split_bf(v.x,hx,lx); split_bf(v.y,hy,ly);
    split_bf(v.z,hz,lz); split_bf(v.w,hw,lw);
    __nv_bfloat162 h01 = __halves2bfloat162(hx,hy);
    __nv_bfloat162 h23 = __halves2bfloat162(hz,hw);
    __nv_bfloat162 l01 = __halves2bfloat162(lx,ly);
    __nv_bfloat162 l23 = __halves2bfloat162(lz,lw);
    H.x = *reinterpret_cast<unsigned*>(&h01); H.y = *reinterpret_cast<unsigned*>(&h23);
    L.x = *reinterpret_cast<unsigned*>(&l01); L.y = *reinterpret_cast<unsigned*>(&l23);
}
__device__ __forceinline__ float gelu_exact(float v) {
    return 0.5f * v * (1.0f + erff(v * 0.7071067811865476f));
}

// ---------------- weight conversion: W[N][K] -> W'[N][3K] = [hi|hi|lo] ----------------
__global__ __launch_bounds__(256) void conv_w_kernel(
    const float* __restrict__ W, __nv_bfloat16* __restrict__ Wp, int K, int total4)
{
    int idx = blockIdx.x * 256 + threadIdx.x;
    if (idx >= total4) return;
    long e = (long)idx * 4;
    int r = (int)(e / K), c = (int)(e % K);
    float4 v = *(const float4*)&W[(long)r * K + c];
    uint2 H, L; split4_u2(v, H, L);
    __nv_bfloat16* row = Wp + (long)r * 3 * K;
    *(uint2*)&row[c]         = H;
    *(uint2*)&row[K + c]     = H;
    *(uint2*)&row[2*K + c]   = L;
}

// ================ bf16-split GEMM v2: padded smem + cp.async 4-stage ================
// C[M,N] = A'[M][Kp] x B' (+bias, epi)
// BROW=false: B' [N][Kp] row-major (weights; col_major frags), smem stride 40
// BROW=true : B' [Kp][N] row-major (xnB; row_major frags), smem stride 136
// EPI: 0 fp32+bias, 1 bias+gelu -> bf16 A-form triple, 2 fp32+bias+residual
#define GSTAGES 4
#define ASTR 40     // halves; 80B = 5*16B
#define BSTR 136    // halves; 272B = 17*16B
#define ASZ (128*ASTR*2)            // 10240 B per stage
#define BSZ_W (128*ASTR*2)          // weights B tile: 128 rows x 32 k
#define BSZ_R (32*BSTR*2)           // BROW B tile: 32 k-rows x 128 n
#define GSMEM_W (GSTAGES*(ASZ+BSZ_W))   // 81920
#define GSMEM_R (GSTAGES*(ASZ+BSZ_R))   // 75776

template<bool BROW, int EPI>
__global__ __launch_bounds__(256) void gemm_bf16(
    const __nv_bfloat16* __restrict__ A, const __nv_bfloat16* __restrict__ B,
    const float* __restrict__ bias, const float* __restrict__ res,
    void* __restrict__ Cout, int N, int Kp,
    long sA, long sB, long sC)
{
    extern __shared__ __align__(128) char sm[];
    const int BSZ = BROW ? BSZ_R : BSZ_W;
    char* Abase = sm;
    char* Bbase = sm + GSTAGES * ASZ;

    int z = blockIdx.z;
    const int tid = threadIdx.x;
    int w = tid >> 5, lane = tid & 31, wm = w >> 2, wn = w & 3;
    int m0 = blockIdx.y << 7, n0 = blockIdx.x << 7;
    A += z * sA; B += z * sB;

    // loader mapping
    int ar = tid >> 1, ac = (tid & 1) * 16;            // A/weightB: row, half-col
    int br = tid >> 3, bc = (tid & 7) * 16;            // BROW B: k-row, n-col
    const __nv_bfloat16* Ag = A + (long)(m0 + ar) * Kp + ac;
    const __nv_bfloat16* Bg = BROW
        ? (B + (long)br * N + n0 + bc)
        : (B + (long)(n0 + ar) * Kp + ac);
    uint32_t Asw = smem_u32(Abase) + (uint32_t)(ar * (ASTR*2) + ac * 2);
    uint32_t Bsw = BROW
        ? smem_u32(Bbase) + (uint32_t)(br * (BSTR*2) + bc * 2)
        : smem_u32(Bbase) + (uint32_t)(ar * (ASTR*2) + ac * 2);

    int nk = Kp >> 5;

#define GISSUE(kt) do { \
        if ((kt) < nk) { \
            int st_ = (kt) % GSTAGES; \
            long ko_ = (long)(kt) * 32; \
            uint32_t ad = Asw + (uint32_t)st_ * ASZ; \
            cp16(ad,      Ag + ko_); \
            cp16(ad + 16, Ag + ko_ + 8); \
            uint32_t bd = Bsw + (uint32_t)st_ * BSZ; \
            if (BROW) { \
                cp16(bd,      Bg + ko_ * N); \
                cp16(bd + 16, Bg + ko_ * N + 8); \
            } else { \
                cp16(bd,      Bg + ko_); \
                cp16(bd + 16, Bg + ko_ + 8); \
            } \
        } \
        cp_commit(); \
    } while (0)

    wmma::fragment<wmma::accumulator, 16, 16, 16, float> acc[4][2];
#pragma unroll
    for (int i = 0; i < 4; i++)
#pragma unroll
        for (int j = 0; j < 2; j++) wmma::fill_fragment(acc[i][j], 0.f);

#pragma unroll
    for (int i = 0; i < GSTAGES - 1; i++) GISSUE(i);

    for (int kt = 0; kt < nk; kt++) {
        cp_wait<GSTAGES - 2>();
        __syncthreads();
        GISSUE(kt + GSTAGES - 1);
        int st = kt % GSTAGES;
        const __nv_bfloat16* Asm = (const __nv_bfloat16*)(Abase + st * ASZ);
        const __nv_bfloat16* Bsm = (const __nv_bfloat16*)(Bbase + st * BSZ);
#pragma unroll
        for (int kk = 0; kk < 2; kk++) {
            wmma::fragment<wmma::matrix_a, 16, 16, 16, __nv_bfloat16, wmma::row_major> af[4];
#pragma unroll
            for (int i = 0; i < 4; i++)
                wmma::load_matrix_sync(af[i], Asm + (wm*64 + i*16)*ASTR + kk*16, ASTR);
            if (BROW) {
                wmma::fragment<wmma::matrix_b, 16, 16, 16, __nv_bfloat16, wmma::row_major> bf[2];
#pragma unroll
                for (int j = 0; j < 2; j++)
                    wmma::load_matrix_sync(bf[j], Bsm + (kk*16)*BSTR + wn*32 + j*16, BSTR);
#pragma unroll
                for (int i = 0; i < 4; i++)
#pragma unroll
                    for (int j = 0; j < 2; j++)
                        wmma::mma_sync(acc[i][j], af[i], bf[j], acc[i][j]);
            } else {
                wmma::fragment<wmma::matrix_b, 16, 16, 16, __nv_bfloat16, wmma::col_major> bf[2];
#pragma unroll
                for (int j = 0; j < 2; j++)
                    wmma::load_matrix_sync(bf[j], Bsm + (wn*32 + j*16)*ASTR + kk*16, ASTR);
#pragma unroll
                for (int i = 0; i < 4; i++)
#pragma unroll
                    for (int j = 0; j < 2; j++)
                        wmma::mma_sync(acc[i][j], af[i], bf[j], acc[i][j]);
            }
        }
        __syncthreads();
    }
#undef GISSUE

    // epilogue via smem staging
    float* EP = (float*)sm + w * 256;
    int r = lane >> 1, c0 = (lane & 1) * 8;
    long ldc = (EPI == 1) ? (long)3 * N : (long)N;
#pragma unroll
    for (int i = 0; i < 4; i++) {
#pragma unroll
        for (int j = 0; j < 2; j++) {
            wmma::store_matrix_sync(EP, acc[i][j], 16, wmma::mem_row_major);
            __syncwarp();
            long grow = m0 + wm*64 + i*16 + r;
            int  gcol = n0 + wn*32 + j*16 + c0;
            float4 v0 = *(float4*)&EP[r*16 + c0];
            float4 v1 = *(float4*)&EP[r*16 + c0 + 4];
            if (bias) {
                float4 b0 = *(const float4*)&bias[gcol];
                float4 b1 = *(const float4*)&bias[gcol + 4];
                v0.x += b0.x; v0.y += b0.y; v0.z += b0.z; v0.w += b0.w;
                v1.x += b1.x; v1.y += b1.y; v1.z += b1.z; v1.w += b1.w;
            }
            if (EPI == 1) {
                v0.x = gelu_exact(v0.x); v0.y = gelu_exact(v0.y);
                v0.z = gelu_exact(v0.z); v0.w = gelu_exact(v0.w);
                v1.x = gelu_exact(v1.x); v1.y = gelu_exact(v1.y);
                v1.z = gelu_exact(v1.z); v1.w = gelu_exact(v1.w);
                uint2 H0,L0,H1,L1;
                split4_u2(v0,H0,L0); split4_u2(v1,H1,L1);
                __nv_bfloat16* Crow = (__nv_bfloat16*)Cout + grow * ldc;
                uint4 Hq = make_uint4(H0.x,H0.y,H1.x,H1.y);
                uint4 Lq = make_uint4(L0.x,L0.y,L1.x,L1.y);
                *(uint4*)&Crow[gcol]         = Hq;
                *(uint4*)&Crow[N + gcol]     = Lq;
                *(uint4*)&Crow[2*N + gcol]   = Hq;
            } else {
                float* C = (float*)Cout + z * sC;
                if (EPI == 2) {
                    float4 r0 = *(const float4*)&res[grow*N + gcol];
                    float4 r1 = *(const float4*)&res[grow*N + gcol + 4];
                    v0.x += r0.x; v0.y += r0.y; v0.z += r0.z; v0.w += r0.w;
                    v1.x += r1.x; v1.y += r1.y; v1.z += r1.z; v1.w += r1.w;
                }
                *(float4*)&C[grow*ldc + gcol]     = v0;
                *(float4*)&C[grow*ldc + gcol + 4] = v1;
            }
            __syncwarp();
        }
    }
}

// ---------------- LN1: fp32 in -> A-form + B-form bf16 out ----------------
__global__ __launch_bounds__(256) void ln1_kernel(
    const float* __restrict__ x, const float* __restrict__ w,
    const float* __restrict__ b,
    __nv_bfloat16* __restrict__ xnA, __nv_bfloat16* __restrict__ xnB)
{
    int warp = threadIdx.x >> 5, lane = threadIdx.x & 31;
    long row = (long)blockIdx.x * 8 + warp;
    const float* xr = x + row * Dd;
    float4 v[4];
    float s = 0.f, sq = 0.f;
#pragma unroll
    for (int i = 0; i < 4; i++) {
        v[i] = *(const float4*)&xr[lane*4 + i*128];
        s  += v[i].x + v[i].y + v[i].z + v[i].w;
        sq += v[i].x*v[i].x + v[i].y*v[i].y + v[i].z*v[i].z + v[i].w*v[i].w;
    }
#pragma unroll
    for (int o = 16; o; o >>= 1) {
        s  += __shfl_xor_sync(0xffffffffu, s,  o);
        sq += __shfl_xor_sync(0xffffffffu, sq, o);
    }
    float mean = s * (1.0f/512.0f);
    float var  = sq * (1.0f/512.0f) - mean*mean;
    float rr   = rsqrtf(var + 1e-5f);
    int bz = (int)(row >> 10), rz = (int)(row & 1023);
    __nv_bfloat16* arow = xnA + row * (3*Dd);
    __nv_bfloat16* bbase = xnB + (long)bz * 3*Tt*Dd;
#pragma unroll
    for (int i = 0; i < 4; i++) {
        int d = lane*4 + i*128;
        float4 wv = *(const float4*)&w[d];
        float4 bv = *(const float4*)&b[d];
        float4 o4;
        o4.x = (v[i].x - mean)*rr*wv.x + bv.x;
        o4.y = (v[i].y - mean)*rr*wv.y + bv.y;
        o4.z = (v[i].z - mean)*rr*wv.z + bv.z;
        o4.w = (v[i].w - mean)*rr*wv.w + bv.w;
        uint2 H, L; split4_u2(o4, H, L);
        *(uint2*)&arow[d]          = H;
        *(uint2*)&arow[Dd + d]     = L;
        *(uint2*)&arow[2*Dd + d]   = H;
        *(uint2*)&bbase[(long)rz*Dd + d]            = H;
        *(uint2*)&bbase[(long)(Tt + rz)*Dd + d]     = H;
        *(uint2*)&bbase[(long)(2*Tt + rz)*Dd + d]   = L;
    }
}

// ---------------- flash attention, fp32, writes ctx in A-form bf16 ----------------
__global__ __launch_bounds__(256) void attn_kernel(
    const float* __restrict__ qkv, __nv_bfloat16* __restrict__ ctxA)
{
    extern __shared__ float smf[];
    float* Qs = smf;
    float* Ks = smf + 4352;
    float* Vs = smf + 8704;
    float* Ps = smf + 13056;

    int b = blockIdx.z, h = blockIdx.y, qt = blockIdx.x;
    int tid = threadIdx.x, tx = tid & 15, ty = tid >> 4;
    const int LDR = 3*Dd;
    const float* base = qkv + (long)b * Tt * LDR;
    int row = tid >> 2, cq = (tid & 3) << 2;

    {
        const float* qptr = base + (long)(qt*64) * LDR + h*HD;
#pragma unroll
        for (int w = 0; w < 4; w++) {
            int dd = cq + w*16;
            float4 v = *(const float4*)&qptr[(long)row*LDR + dd];
            v.x *= 0.125f; v.y *= 0.125f; v.z *= 0.125f; v.w *= 0.125f;
            *(float4*)&Qs[row*68 + dd] = v;
        }
    }

    float m[4], l[4], o[4][4];
#pragma unroll
    for (int i = 0; i < 4; i++) {
        m[i] = -1e30f; l[i] = 0.f;
#pragma unroll
        for (int j = 0; j < 4; j++) o[i][j] = 0.f;
    }

    for (int kt = 0; kt < Tt/64; kt++) {
        __syncthreads();
        const float* kptr = base + (long)(kt*64) * LDR + Dd  + h*HD;
        const float* vptr = base + (long)(kt*64) * LDR + 2*Dd + h*HD;
#pragma unroll
        for (int w = 0; w < 4; w++) {
            int dd = cq + w*16;
            float4 kv = *(const float4*)&kptr[(long)row*LDR + dd];
            Ks[(dd+0)*68 + row] = kv.x;
            Ks[(dd+1)*68 + row] = kv.y;
            Ks[(dd+2)*68 + row] = kv.z;
            Ks[(dd+3)*68 + row] = kv.w;
            float4 vv = *(const float4*)&vptr[(long)row*LDR + dd];
            *(float4*)&Vs[row*68 + dd] = vv;
        }
        __syncthreads();

        float s[4][4] = {};
#pragma unroll
        for (int d = 0; d < 64; d++) {
            float4 k4 = *(const float4*)&Ks[d*68 + tx*4];
            float a0 = Qs[(ty*4+0)*68 + d];
            float a1 = Qs[(ty*4+1)*68 + d];
            float a2 = Qs[(ty*4+2)*68 + d];
            float a3 = Qs[(ty*4+3)*68 + d];
            s[0][0] += a0*k4.x; s[0][1] += a0*k4.y; s[0][2] += a0*k4.z; s[0][3] += a0*k4.w;
            s[1][0] += a1*k4.x; s[1][1] += a1*k4.y; s[1][2] += a1*k4.z; s[1][3] += a1*k4.w;
            s[2][0] += a2*k4.x; s[2][1] += a2*k4.y; s[2][2] += a2*k4.z; s[2][3] += a2*k4.w;
            s[3][0] += a3*k4.x; s[3][1] += a3*k4.y; s[3][2] += a3*k4.z; s[3][3] += a3*k4.w;
        }

#pragma unroll
        for (int i = 0; i < 4; i++) {
            float mt = fmaxf(fmaxf(s[i][0], s[i][1]), fmaxf(s[i][2], s[i][3]));
#pragma unroll
            for (int off = 1; off < 16; off <<= 1)
                mt = fmaxf(mt, __shfl_xor_sync(0xffffffffu, mt, off));
            float mn = fmaxf(m[i], mt);
            float corr = __expf(m[i] - mn);
            m[i] = mn;
            l[i] *= corr;
#pragma unroll
            for (int j = 0; j < 4; j++) o[i][j] *= corr;
            float p0 = __expf(s[i][0] - mn);
            float p1 = __expf(s[i][1] - mn);
            float p2 = __expf(s[i][2] - mn);
            float p3 = __expf(s[i][3] - mn);
            l[i] += p0 + p1 + p2 + p3;
            *(float4*)&Ps[(ty*4+i)*68 + tx*4] = make_float4(p0, p1, p2, p3);
        }
        __syncthreads();

#pragma unroll
        for (int k = 0; k < 64; k++) {
            float4 v4 = *(const float4*)&Vs[k*68 + tx*4];
            float p0 = Ps[(ty*4+0)*68 + k];
            float p1 = Ps[(ty*4+1)*68 + k];
            float p2 = Ps[(ty*4+2)*68 + k];
            float p3 = Ps[(ty*4+3)*68 + k];
            o[0][0] += p0*v4.x; o[0][1] += p0*v4.y; o[0][2] += p0*v4.z; o[0][3] += p0*v4.w;
            o[1][0] += p1*v4.x; o[1][1] += p1*v4.y; o[1][2] += p1*v4.z; o[1][3] += p1*v4.w;
            o[2][0] += p2*v4.x; o[2][1] += p2*v4.y; o[2][2] += p2*v4.z; o[2][3] += p2*v4.w;
            o[3][0] += p3*v4.x; o[3][1] += p3*v4.y; o[3][2] += p3*v4.z; o[3][3] += p3*v4.w;
        }
    }

#pragma unroll
    for (int i = 0; i < 4; i++) {
        float li = l[i];
#pragma unroll
        for (int off = 1; off < 16; off <<= 1)
            li += __shfl_xor_sync(0xffffffffu, li, off);
        float inv = 1.0f / li;
        float4 rv = make_float4(o[i][0]*inv, o[i][1]*inv, o[i][2]*inv, o[i][3]*inv);
        long grow = (long)(b*Tt + qt*64 + ty*4 + i);
        int col = h*HD + tx*4;
        uint2 H, L; split4_u2(rv, H, L);
        __nv_bfloat16* crow = ctxA + grow * (3*Dd);
        *(uint2*)&crow[col]          = H;
        *(uint2*)&crow[Dd + col]     = L;
        *(uint2*)&crow[2*Dd + col]   = H;
    }
}

// ---------------- Gaussian kernel weights (A-form bf16) + row sums ----------------
__global__ __launch_bounds__(256) void kw_kernel(
    const int* __restrict__ posv, const int* __restrict__ posh,
    __nv_bfloat16* __restrict__ kwA, float* __restrict__ ksum)
{
    long bq = blockIdx.x;
    int b = (int)(bq >> 10), q = (int)(bq & 1023);
    int tid = threadIdx.x;
    const int* pvb = posv + (long)b*Tt;
    const int* phb = posh + (long)b*Tt;
    int qv = pvb[q], qh = phb[q];
    int k0 = tid * 4;
    int4 kv4 = *(const int4*)&pvb[k0];
    int4 kh4 = *(const int4*)&phb[k0];
    const float c = -1.0f / 512.0f;
    int dvx = qv-kv4.x, dhx = qh-kh4.x;
    int dvy = qv-kv4.y, dhy = qh-kh4.y;
    int dvz = qv-kv4.z, dhz = qh-kh4.z;
    int dvw = qv-kv4.w, dhw = qh-kh4.w;
    float4 w4;
    w4.x = __expf((float)(dvx*dvx + dhx*dhx) * c);
    w4.y = __expf((float)(dvy*dvy + dhy*dhy) * c);
    w4.z = __expf((float)(dvz*dvz + dhz*dhz) * c);
    w4.w = __expf((float)(dvw*dvw + dhw*dhw) * c);
    uint2 H, L; split4_u2(w4, H, L);
    __nv_bfloat16* row = kwA + bq * (3*Tt);
    *(uint2*)&row[k0]          = H;
    *(uint2*)&row[Tt + k0]     = L;
    *(uint2*)&row[2*Tt + k0]   = H;
    float s = w4.x + w4.y + w4.z + w4.w;
#pragma unroll
    for (int o = 16; o; o >>= 1) s += __shfl_xor_sync(0xffffffffu, s, o);
    __shared__ float red[8];
    if ((tid & 31) == 0) red[tid >> 5] = s;
    __syncthreads();
    if (tid == 0) {
        float t = 0.f;
#pragma unroll
        for (int i = 0; i < 8; i++) t += red[i];
        ksum[bq] = t;
    }
}

// ---------------- combine (x1 fp32) + LN2 -> A-form bf16 ----------------
__global__ __launch_bounds__(256) void combine_ln2_kernel(
    const float* __restrict__ x, const float* __restrict__ stdo,
    const float* __restrict__ ko, const float* __restrict__ ksum,
    const float* __restrict__ gate,
    const float* __restrict__ w, const float* __restrict__ bb,
    float* __restrict__ x1, __nv_bfloat16* __restrict__ xn2A)
{
    int warp = threadIdx.x >> 5, lane = threadIdx.x & 31;
    long row = (long)blockIdx.x * 8 + warp;
    float g = 1.0f / (1.0f + __expf(-gate[0]));
    float gi = 1.0f - g;
    float inv_ks = 1.0f / ksum[row];
    long base = row * Dd;
    float4 v[4];
    float s = 0.f, sq = 0.f;
#pragma unroll
    for (int i = 0; i < 4; i++) {
        int d = lane*4 + i*128;
        float4 xv = *(const float4*)&x[base + d];
        float4 sv = *(const float4*)&stdo[base + d];
        float4 kv = *(const float4*)&ko[base + d];
        float4 o4;
        o4.x = xv.x + g*sv.x + gi*kv.x*inv_ks;
        o4.y = xv.y + g*sv.y + gi*kv.y*inv_ks;
        o4.z = xv.z + g*sv.z + gi*kv.z*inv_ks;
        o4.w = xv.w + g*sv.w + gi*kv.w*inv_ks;
        *(float4*)&x1[base + d] = o4;
        v[i] = o4;
        s  += o4.x + o4.y + o4.z + o4.w;
        sq += o4.x*o4.x + o4.y*o4.y + o4.z*o4.z + o4.w*o4.w;
    }
#pragma unroll
    for (int o = 16; o; o >>= 1) {
        s  += __shfl_xor_sync(0xffffffffu, s,  o);
        sq += __shfl_xor_sync(0xffffffffu, sq, o);
    }
    float mean = s * (1.0f/512.0f);
    float var  = sq * (1.0f/512.0f) - mean*mean;
    float rr   = rsqrtf(var + 1e-5f);
    __nv_bfloat16* arow = xn2A + row * (3*Dd);
#pragma unroll
    for (int i = 0; i < 4; i++) {
        int d = lane*4 + i*128;
        float4 wv = *(const float4*)&w[d];
        float4 bv = *(const float4*)&bb[d];
        float4 o4;
        o4.x = (v[i].x - mean)*rr*wv.x + bv.x;
        o4.y = (v[i].y - mean)*rr*wv.y + bv.y;
        o4.z = (v[i].z - mean)*rr*wv.z + bv.z;
        o4.w = (v[i].w - mean)*rr*wv.w + bv.w;
        uint2 H, L; split4_u2(o4, H, L);
        *(uint2*)&arow[d]          = H;
        *(uint2*)&arow[Dd + d]     = L;
        *(uint2*)&arow[2*Dd + d]   = H;
    }
}

// ---------------- launch ----------------
extern "C" void kernel_launch(void* const* d_in, const int* in_sizes, int n_in,
                              void* d_out, int out_size)
{
    const float* x      = (const float*)d_in[0];
    const int*   posv   = (const int*)  d_in[1];
    const int*   posh   = (const int*)  d_in[2];
    const float* n1w    = (const float*)d_in[3];
    const float* n1b    = (const float*)d_in[4];
    const float* in_w   = (const float*)d_in[5];
    const float* in_b   = (const float*)d_in[6];
    const float* out_w  = (const float*)d_in[7];
    const float* out_b  = (const float*)d_in[8];
    const float* n2w    = (const float*)d_in[9];
    const float* n2b    = (const float*)d_in[10];
    const float* w1     = (const float*)d_in[11];
    const float* b1     = (const float*)d_in[12];
    const float* w2     = (const float*)d_in[13];
    const float* b2     = (const float*)d_in[14];
    const float* gate   = (const float*)d_in[15];
    float* out = (float*)d_out;

    __nv_bfloat16 *xnA, *xnB, *ctxA, *kwA, *xn2A, *hA, *wIN, *wOUT, *w1p, *w2p;
    float *qkv, *stdo, *ksum, *ko, *x1;
    cudaGetSymbolAddress((void**)&xnA,  g_xnA);
    cudaGetSymbolAddress((void**)&xnB,  g_xnB);
    cudaGetSymbolAddress((void**)&qkv,  g_qkv);
    cudaGetSymbolAddress((void**)&ctxA, g_ctxA);
    cudaGetSymbolAddress((void**)&stdo, g_stdo);
    cudaGetSymbolAddress((void**)&kwA,  g_kwA);
    cudaGetSymbolAddress((void**)&ksum, g_ksum);
    cudaGetSymbolAddress((void**)&ko,   g_ko);
    cudaGetSymbolAddress((void**)&x1,   g_x1);
    cudaGetSymbolAddress((void**)&xn2A, g_xn2A);
    cudaGetSymbolAddress((void**)&hA,   g_hA);
    cudaGetSymbolAddress((void**)&wIN,  g_wIN);
    cudaGetSymbolAddress((void**)&wOUT, g_wOUT);
    cudaGetSymbolAddress((void**)&w1p,  g_w1);
    cudaGetSymbolAddress((void**)&w2p,  g_w2);

    cudaFuncSetAttribute(gemm_bf16<false,0>, cudaFuncAttributeMaxDynamicSharedMemorySize, GSMEM_W);
    cudaFuncSetAttribute(gemm_bf16<false,1>, cudaFuncAttributeMaxDynamicSharedMemorySize, GSMEM_W);
    cudaFuncSetAttribute(gemm_bf16<false,2>, cudaFuncAttributeMaxDynamicSharedMemorySize, GSMEM_W);
    cudaFuncSetAttribute(gemm_bf16<true,0>,  cudaFuncAttributeMaxDynamicSharedMemorySize, GSMEM_R);

    // weight conversions (B-form [hi|hi|lo])
    conv_w_kernel<<<(3*Dd*Dd/4 + 255)/256, 256>>>(in_w,  wIN,  Dd, 3*Dd*Dd/4);
    conv_w_kernel<<<(Dd*Dd/4   + 255)/256, 256>>>(out_w, wOUT, Dd, Dd*Dd/4);
    conv_w_kernel<<<(D4*Dd/4   + 255)/256, 256>>>(w1,    w1p,  Dd, D4*Dd/4);
    conv_w_kernel<<<(Dd*D4/4   + 255)/256, 256>>>(w2,    w2p,  D4, Dd*D4/4);

    // 1) LN1 -> xnA (A-form), xnB (B-form)
    ln1_kernel<<<ROWS/8, 256>>>(x, n1w, n1b, xnA, xnB);

    // 2) QKV = xn @ in_w^T + in_b
    gemm_bf16<false, 0><<<dim3(3*Dd/128, ROWS/128), 256, GSMEM_W>>>(
        xnA, wIN, in_b, nullptr, qkv, 3*Dd, 3*Dd, 0, 0, 0);

    // 3) flash attention -> ctxA
    {
        static const int SMEM = 4 * 4352 * 4;
        cudaFuncSetAttribute(attn_kernel, cudaFuncAttributeMaxDynamicSharedMemorySize, SMEM);
        attn_kernel<<<dim3(Tt/64, Hh, Bb), 256, SMEM>>>(qkv, ctxA);
    }

    // 4) std_out = ctx @ out_w^T + out_b
    gemm_bf16<false, 0><<<dim3(Dd/128, ROWS/128), 256, GSMEM_W>>>(
        ctxA, wOUT, out_b, nullptr, stdo, Dd, 3*Dd, 0, 0, 0);

    // 5) Gaussian kernel weights
    kw_kernel<<<ROWS, 256>>>(posv, posh, kwA, ksum);

    // 6) ko = kw @ xn (batched)
    gemm_bf16<true, 0><<<dim3(Dd/128, Tt/128, Bb), 256, GSMEM_R>>>(
        kwA, xnB, nullptr, nullptr, ko, Dd, 3*Tt,
        (long)Tt*3*Tt, (long)3*Tt*Dd, (long)Tt*Dd);

    // 7) combine + LN2
    combine_ln2_kernel<<<ROWS/8, 256>>>(x, stdo, ko, ksum, gate, n2w, n2b, x1, xn2A);

    // 8) h = gelu(xn2 @ w1^T + b1) -> hA (A-form bf16)
    gemm_bf16<false, 1><<<dim3(D4/128, ROWS/128), 256, GSMEM_W>>>(
        xn2A, w1p, b1, nullptr, hA, D4, 3*Dd, 0, 0, 0);

    // 9) out = x1 + h @ w2^T + b2
    gemm_bf16<false, 2><<<dim3(Dd/128, ROWS/128), 256, GSMEM_W>>>(
        hA, w2p, b2, x1, out, Dd, 3*D4, 0, 0, 0);
}

// round 6
// speedup vs baseline: 1.6142x; 1.0944x over previous
#include <cuda_runtime.h>
#include <cuda_bf16.h>
#include <mma.h>
#include <math.h>
#include <stdint.h>

using namespace nvcuda;

#define Bb 8
#define Tt 1024
#define Dd 512
#define Hh 8
#define HD 64
#define D4 2048
#define ROWS (Bb*Tt)

// ---------------- scratch (device globals) ----------------
__device__ __nv_bfloat16 g_xnA [ROWS*3*Dd];
__device__ __nv_bfloat16 g_xnB [Bb*3*Tt*Dd];
__device__ float         g_qkv [ROWS*3*Dd];
__device__ __nv_bfloat16 g_ctxA[ROWS*3*Dd];
__device__ float         g_stdo[ROWS*Dd];
__device__ __nv_bfloat16 g_kwA [Bb*Tt*3*Tt];
__device__ float         g_ksum[ROWS];
__device__ float         g_ko  [ROWS*Dd];
__device__ float         g_x1  [ROWS*Dd];
__device__ __nv_bfloat16 g_xn2A[ROWS*3*Dd];
__device__ __nv_bfloat16 g_hA  [ROWS*3*D4];
__device__ __nv_bfloat16 g_wIN [3*Dd*3*Dd];
__device__ __nv_bfloat16 g_wOUT[Dd*3*Dd];
__device__ __nv_bfloat16 g_w1  [D4*3*Dd];
__device__ __nv_bfloat16 g_w2  [Dd*3*D4];

// ---------------- helpers ----------------
__device__ __forceinline__ uint32_t smem_u32(const void* p) {
    uint32_t a;
    asm("{ .reg .u64 t; cvta.to.shared.u64 t, %1; cvt.u32.u64 %0, t; }" : "=r"(a) : "l"(p));
    return a;
}
__device__ __forceinline__ void cp16(uint32_t sdst, const void* gsrc) {
    asm volatile("cp.async.cg.shared.global [%0], [%1], 16;" :: "r"(sdst), "l"(gsrc));
}
__device__ __forceinline__ void cp_commit() {
    asm volatile("cp.async.commit_group;" ::: "memory");
}
template<int N>
__device__ __forceinline__ void cp_wait() {
    asm volatile("cp.async.wait_group %0;" :: "n"(N) : "memory");
}
__device__ __forceinline__ void split_bf(float v, __nv_bfloat16& h, __nv_bfloat16& l) {
    h = __float2bfloat16(v);
    l = __float2bfloat16(v - __bfloat162float(h));
}
__device__ __forceinline__ void split4_u2(float4 v, uint2& H, uint2& L) {
    __nv_bfloat16 hx,lx,hy,ly,hz,lz,hw,lw;
    split_bf(v.x,hx,lx); split_bf(v.y,hy,ly);
    split_bf(v.z,hz,lz); split_bf(v.w,hw,lw);
    __nv_bfloat162 h01 = __halves2bfloat162(hx,hy);
    __nv_bfloat162 h23 = __halves2bfloat162(hz,hw);
    __nv_bfloat162 l01 = __halves2bfloat162(lx,ly);
    __nv_bfloat162 l23 = __halves2bfloat162(lz,lw);
    H.x = *reinterpret_cast<unsigned*>(&h01); H.y = *reinterpret_cast<unsigned*>(&h23);
    L.x = *reinterpret_cast<unsigned*>(&l01); L.y = *reinterpret_cast<unsigned*>(&l23);
}
__device__ __forceinline__ float gelu_exact(float v) {
    return 0.5f * v * (1.0f + erff(v * 0.7071067811865476f));
}

// ---------------- weight conversion: W[N][K] -> W'[N][3K] = [hi|hi|lo] ----------------
__global__ __launch_bounds__(256) void conv_w_kernel(
    const float* __restrict__ W, __nv_bfloat16* __restrict__ Wp, int K, int total4)
{
    int idx = blockIdx.x * 256 + threadIdx.x;
    if (idx >= total4) return;
    long e = (long)idx * 4;
    int r = (int)(e / K), c = (int)(e % K);
    float4 v = *(const float4*)&W[(long)r * K + c];
    uint2 H, L; split4_u2(v, H, L);
    __nv_bfloat16* row = Wp + (long)r * 3 * K;
    *(uint2*)&row[c]         = H;
    *(uint2*)&row[K + c]     = H;
    *(uint2*)&row[2*K + c]   = L;
}

// ================ bf16-split GEMM v3: 128x256 CTA tile, 64x64 warp tile ================
// BROW=false: B' [N][Kp] row-major (weights; col_major frags), smem stride 40
// BROW=true : B' [Kp][N] row-major (xnB; row_major frags), smem stride 264
// EPI: 0 fp32+bias, 1 bias+gelu -> bf16 A-form triple, 2 fp32+bias+residual
#define GSTAGES 3
#define ASTR 40
#define BSTR_R 264
#define ASZ   (128*ASTR*2)          // 10240
#define BSZ_W (256*ASTR*2)          // 20480
#define BSZ_R (32*BSTR_R*2)         // 16896
#define GSMEM_W (GSTAGES*(ASZ+BSZ_W))   // 92160
#define GSMEM_R (GSTAGES*(ASZ+BSZ_R))   // 81408

template<bool BROW, int EPI>
__global__ __launch_bounds__(256) void gemm_bf16(
    const __nv_bfloat16* __restrict__ A, const __nv_bfloat16* __restrict__ B,
    const float* __restrict__ bias, const float* __restrict__ res,
    void* __restrict__ Cout, int N, int Kp,
    long sA, long sB, long sC)
{
    extern __shared__ __align__(128) char sm[];
    const int BSZ = BROW ? BSZ_R : BSZ_W;
    char* Abase = sm;
    char* Bbase = sm + GSTAGES * ASZ;

    int z = blockIdx.z;
    const int tid = threadIdx.x;
    int w = tid >> 5, lane = tid & 31, wm = w >> 2, wn = w & 3;
    int m0 = blockIdx.y << 7, n0 = blockIdx.x << 8;
    A += z * sA; B += z * sB;

    // loader mapping
    int ar = tid >> 2, ac = (tid & 3) * 8;        // A / weight-B rows, 8-half cols
    int br = tid >> 5, bc = (tid & 31) * 8;       // BROW B: k-rows, n cols
    const __nv_bfloat16* Ag = A + (long)(m0 + ar) * Kp + ac;
    const __nv_bfloat16* Bg = BROW
        ? (B + (long)br * N + n0 + bc)
        : (B + (long)(n0 + ar) * Kp + ac);
    uint32_t Asw = smem_u32(Abase) + (uint32_t)(ar * (ASTR*2) + ac * 2);
    uint32_t Bsw = BROW
        ? smem_u32(Bbase) + (uint32_t)(br * (BSTR_R*2) + bc * 2)
        : smem_u32(Bbase) + (uint32_t)(ar * (ASTR*2) + ac * 2);

    int nk = Kp >> 5;

#define GISSUE(kt) do { \
        if ((kt) < nk) { \
            int st_ = (kt) % GSTAGES; \
            long ko_ = (long)(kt) * 32; \
            uint32_t ad = Asw + (uint32_t)st_ * ASZ; \
            cp16(ad,                Ag + ko_); \
            cp16(ad + 64*(ASTR*2),  Ag + ko_ + (long)64*Kp); \
            uint32_t bd = Bsw + (uint32_t)st_ * BSZ; \
            if (BROW) { \
                cp16(bd,                 Bg + ko_ * N); \
                cp16(bd +  8*(BSTR_R*2), Bg + (ko_ + 8)  * N); \
                cp16(bd + 16*(BSTR_R*2), Bg + (ko_ + 16) * N); \
                cp16(bd + 24*(BSTR_R*2), Bg + (ko_ + 24) * N); \
            } else { \
                cp16(bd,                 Bg + ko_); \
                cp16(bd +  64*(ASTR*2),  Bg + ko_ + (long)64*Kp); \
                cp16(bd + 128*(ASTR*2),  Bg + ko_ + (long)128*Kp); \
                cp16(bd + 192*(ASTR*2),  Bg + ko_ + (long)192*Kp); \
            } \
        } \
        cp_commit(); \
    } while (0)

    wmma::fragment<wmma::accumulator, 16, 16, 16, float> acc[4][4];
#pragma unroll
    for (int i = 0; i < 4; i++)
#pragma unroll
        for (int j = 0; j < 4; j++) wmma::fill_fragment(acc[i][j], 0.f);

#pragma unroll
    for (int i = 0; i < GSTAGES - 1; i++) GISSUE(i);

    for (int kt = 0; kt < nk; kt++) {
        cp_wait<GSTAGES - 2>();
        __syncthreads();
        GISSUE(kt + GSTAGES - 1);
        int st = kt % GSTAGES;
        const __nv_bfloat16* Asm = (const __nv_bfloat16*)(Abase + st * ASZ);
        const __nv_bfloat16* Bsm = (const __nv_bfloat16*)(Bbase + st * BSZ);
#pragma unroll
        for (int kk = 0; kk < 2; kk++) {
            wmma::fragment<wmma::matrix_a, 16, 16, 16, __nv_bfloat16, wmma::row_major> af[4];
#pragma unroll
            for (int i = 0; i < 4; i++)
                wmma::load_matrix_sync(af[i], Asm + (wm*64 + i*16)*ASTR + kk*16, ASTR);
#pragma unroll
            for (int jh = 0; jh < 2; jh++) {
                if (BROW) {
                    wmma::fragment<wmma::matrix_b, 16, 16, 16, __nv_bfloat16, wmma::row_major> bf[2];
#pragma unroll
                    for (int j = 0; j < 2; j++)
                        wmma::load_matrix_sync(bf[j], Bsm + (kk*16)*BSTR_R + wn*64 + jh*32 + j*16, BSTR_R);
#pragma unroll
                    for (int i = 0; i < 4; i++)
#pragma unroll
                        for (int j = 0; j < 2; j++)
                            wmma::mma_sync(acc[i][jh*2+j], af[i], bf[j], acc[i][jh*2+j]);
                } else {
                    wmma::fragment<wmma::matrix_b, 16, 16, 16, __nv_bfloat16, wmma::col_major> bf[2];
#pragma unroll
                    for (int j = 0; j < 2; j++)
                        wmma::load_matrix_sync(bf[j], Bsm + (wn*64 + jh*32 + j*16)*ASTR + kk*16, ASTR);
#pragma unroll
                    for (int i = 0; i < 4; i++)
#pragma unroll
                        for (int j = 0; j < 2; j++)
                            wmma::mma_sync(acc[i][jh*2+j], af[i], bf[j], acc[i][jh*2+j]);
                }
            }
        }
        __syncthreads();
    }
#undef GISSUE

    // epilogue via smem staging
    float* EP = (float*)sm + w * 256;
    int r = lane >> 1, c0 = (lane & 1) * 8;
    long ldc = (EPI == 1) ? (long)3 * N : (long)N;
#pragma unroll
    for (int i = 0; i < 4; i++) {
#pragma unroll
        for (int j = 0; j < 4; j++) {
            wmma::store_matrix_sync(EP, acc[i][j], 16, wmma::mem_row_major);
            __syncwarp();
            long grow = m0 + wm*64 + i*16 + r;
            int  gcol = n0 + wn*64 + j*16 + c0;
            float4 v0 = *(float4*)&EP[r*16 + c0];
            float4 v1 = *(float4*)&EP[r*16 + c0 + 4];
            if (bias) {
                float4 b0 = *(const float4*)&bias[gcol];
                float4 b1 = *(const float4*)&bias[gcol + 4];
                v0.x += b0.x; v0.y += b0.y; v0.z += b0.z; v0.w += b0.w;
                v1.x += b1.x; v1.y += b1.y; v1.z += b1.z; v1.w += b1.w;
            }
            if (EPI == 1) {
                v0.x = gelu_exact(v0.x); v0.y = gelu_exact(v0.y);
                v0.z = gelu_exact(v0.z); v0.w = gelu_exact(v0.w);
                v1.x = gelu_exact(v1.x); v1.y = gelu_exact(v1.y);
                v1.z = gelu_exact(v1.z); v1.w = gelu_exact(v1.w);
                uint2 H0,L0,H1,L1;
                split4_u2(v0,H0,L0); split4_u2(v1,H1,L1);
                __nv_bfloat16* Crow = (__nv_bfloat16*)Cout + grow * ldc;
                uint4 Hq = make_uint4(H0.x,H0.y,H1.x,H1.y);
                uint4 Lq = make_uint4(L0.x,L0.y,L1.x,L1.y);
                *(uint4*)&Crow[gcol]         = Hq;
                *(uint4*)&Crow[N + gcol]     = Lq;
                *(uint4*)&Crow[2*N + gcol]   = Hq;
            } else {
                float* C = (float*)Cout + z * sC;
                if (EPI == 2) {
                    float4 r0 = *(const float4*)&res[grow*N + gcol];
                    float4 r1 = *(const float4*)&res[grow*N + gcol + 4];
                    v0.x += r0.x; v0.y += r0.y; v0.z += r0.z; v0.w += r0.w;
                    v1.x += r1.x; v1.y += r1.y; v1.z += r1.z; v1.w += r1.w;
                }
                *(float4*)&C[grow*ldc + gcol]     = v0;
                *(float4*)&C[grow*ldc + gcol + 4] = v1;
            }
            __syncwarp();
        }
    }
}

// ---------------- LN1: fp32 in -> A-form + B-form bf16 out ----------------
__global__ __launch_bounds__(256) void ln1_kernel(
    const float* __restrict__ x, const float* __restrict__ w,
    const float* __restrict__ b,
    __nv_bfloat16* __restrict__ xnA, __nv_bfloat16* __restrict__ xnB)
{
    int warp = threadIdx.x >> 5, lane = threadIdx.x & 31;
    long row = (long)blockIdx.x * 8 + warp;
    const float* xr = x + row * Dd;
    float4 v[4];
    float s = 0.f, sq = 0.f;
#pragma unroll
    for (int i = 0; i < 4; i++) {
        v[i] = *(const float4*)&xr[lane*4 + i*128];
        s  += v[i].x + v[i].y + v[i].z + v[i].w;
        sq += v[i].x*v[i].x + v[i].y*v[i].y + v[i].z*v[i].z + v[i].w*v[i].w;
    }
#pragma unroll
    for (int o = 16; o; o >>= 1) {
        s  += __shfl_xor_sync(0xffffffffu, s,  o);
        sq += __shfl_xor_sync(0xffffffffu, sq, o);
    }
    float mean = s * (1.0f/512.0f);
    float var  = sq * (1.0f/512.0f) - mean*mean;
    float rr   = rsqrtf(var + 1e-5f);
    int bz = (int)(row >> 10), rz = (int)(row & 1023);
    __nv_bfloat16* arow = xnA + row * (3*Dd);
    __nv_bfloat16* bbase = xnB + (long)bz * 3*Tt*Dd;
#pragma unroll
    for (int i = 0; i < 4; i++) {
        int d = lane*4 + i*128;
        float4 wv = *(const float4*)&w[d];
        float4 bv = *(const float4*)&b[d];
        float4 o4;
        o4.x = (v[i].x - mean)*rr*wv.x + bv.x;
        o4.y = (v[i].y - mean)*rr*wv.y + bv.y;
        o4.z = (v[i].z - mean)*rr*wv.z + bv.z;
        o4.w = (v[i].w - mean)*rr*wv.w + bv.w;
        uint2 H, L; split4_u2(o4, H, L);
        *(uint2*)&arow[d]          = H;
        *(uint2*)&arow[Dd + d]     = L;
        *(uint2*)&arow[2*Dd + d]   = H;
        *(uint2*)&bbase[(long)rz*Dd + d]            = H;
        *(uint2*)&bbase[(long)(Tt + rz)*Dd + d]     = H;
        *(uint2*)&bbase[(long)(2*Tt + rz)*Dd + d]   = L;
    }
}

// ---------------- flash attention, fp32, writes ctx in A-form bf16 ----------------
__global__ __launch_bounds__(256) void attn_kernel(
    const float* __restrict__ qkv, __nv_bfloat16* __restrict__ ctxA)
{
    extern __shared__ float smf[];
    float* Qs = smf;
    float* Ks = smf + 4352;
    float* Vs = smf + 8704;
    float* Ps = smf + 13056;

    int b = blockIdx.z, h = blockIdx.y, qt = blockIdx.x;
    int tid = threadIdx.x, tx = tid & 15, ty = tid >> 4;
    const int LDR = 3*Dd;
    const float* base = qkv + (long)b * Tt * LDR;
    int row = tid >> 2, cq = (tid & 3) << 2;

    {
        const float* qptr = base + (long)(qt*64) * LDR + h*HD;
#pragma unroll
        for (int w = 0; w < 4; w++) {
            int dd = cq + w*16;
            float4 v = *(const float4*)&qptr[(long)row*LDR + dd];
            v.x *= 0.125f; v.y *= 0.125f; v.z *= 0.125f; v.w *= 0.125f;
            *(float4*)&Qs[row*68 + dd] = v;
        }
    }

    float m[4], l[4], o[4][4];
#pragma unroll
    for (int i = 0; i < 4; i++) {
        m[i] = -1e30f; l[i] = 0.f;
#pragma unroll
        for (int j = 0; j < 4; j++) o[i][j] = 0.f;
    }

    for (int kt = 0; kt < Tt/64; kt++) {
        __syncthreads();
        const float* kptr = base + (long)(kt*64) * LDR + Dd  + h*HD;
        const float* vptr = base + (long)(kt*64) * LDR + 2*Dd + h*HD;
#pragma unroll
        for (int w = 0; w < 4; w++) {
            int dd = cq + w*16;
            float4 kv = *(const float4*)&kptr[(long)row*LDR + dd];
            Ks[(dd+0)*68 + row] = kv.x;
            Ks[(dd+1)*68 + row] = kv.y;
            Ks[(dd+2)*68 + row] = kv.z;
            Ks[(dd+3)*68 + row] = kv.w;
            float4 vv = *(const float4*)&vptr[(long)row*LDR + dd];
            *(float4*)&Vs[row*68 + dd] = vv;
        }
        __syncthreads();

        float s[4][4] = {};
#pragma unroll
        for (int d = 0; d < 64; d++) {
            float4 k4 = *(const float4*)&Ks[d*68 + tx*4];
            float a0 = Qs[(ty*4+0)*68 + d];
            float a1 = Qs[(ty*4+1)*68 + d];
            float a2 = Qs[(ty*4+2)*68 + d];
            float a3 = Qs[(ty*4+3)*68 + d];
            s[0][0] += a0*k4.x; s[0][1] += a0*k4.y; s[0][2] += a0*k4.z; s[0][3] += a0*k4.w;
            s[1][0] += a1*k4.x; s[1][1] += a1*k4.y; s[1][2] += a1*k4.z; s[1][3] += a1*k4.w;
            s[2][0] += a2*k4.x; s[2][1] += a2*k4.y; s[2][2] += a2*k4.z; s[2][3] += a2*k4.w;
            s[3][0] += a3*k4.x; s[3][1] += a3*k4.y; s[3][2] += a3*k4.z; s[3][3] += a3*k4.w;
        }

#pragma unroll
        for (int i = 0; i < 4; i++) {
            float mt = fmaxf(fmaxf(s[i][0], s[i][1]), fmaxf(s[i][2], s[i][3]));
#pragma unroll
            for (int off = 1; off < 16; off <<= 1)
                mt = fmaxf(mt, __shfl_xor_sync(0xffffffffu, mt, off));
            float mn = fmaxf(m[i], mt);
            float corr = __expf(m[i] - mn);
            m[i] = mn;
            l[i] *= corr;
#pragma unroll
            for (int j = 0; j < 4; j++) o[i][j] *= corr;
            float p0 = __expf(s[i][0] - mn);
            float p1 = __expf(s[i][1] - mn);
            float p2 = __expf(s[i][2] - mn);
            float p3 = __expf(s[i][3] - mn);
            l[i] += p0 + p1 + p2 + p3;
            *(float4*)&Ps[(ty*4+i)*68 + tx*4] = make_float4(p0, p1, p2, p3);
        }
        __syncthreads();

#pragma unroll
        for (int k = 0; k < 64; k++) {
            float4 v4 = *(const float4*)&Vs[k*68 + tx*4];
            float p0 = Ps[(ty*4+0)*68 + k];
            float p1 = Ps[(ty*4+1)*68 + k];
            float p2 = Ps[(ty*4+2)*68 + k];
            float p3 = Ps[(ty*4+3)*68 + k];
            o[0][0] += p0*v4.x; o[0][1] += p0*v4.y; o[0][2] += p0*v4.z; o[0][3] += p0*v4.w;
            o[1][0] += p1*v4.x; o[1][1] += p1*v4.y; o[1][2] += p1*v4.z; o[1][3] += p1*v4.w;
            o[2][0] += p2*v4.x; o[2][1] += p2*v4.y; o[2][2] += p2*v4.z; o[2][3] += p2*v4.w;
            o[3][0] += p3*v4.x; o[3][1] += p3*v4.y; o[3][2] += p3*v4.z; o[3][3] += p3*v4.w;
        }
    }

#pragma unroll
    for (int i = 0; i < 4; i++) {
        float li = l[i];
#pragma unroll
        for (int off = 1; off < 16; off <<= 1)
            li += __shfl_xor_sync(0xffffffffu, li, off);
        float inv = 1.0f / li;
        float4 rv = make_float4(o[i][0]*inv, o[i][1]*inv, o[i][2]*inv, o[i][3]*inv);
        long grow = (long)(b*Tt + qt*64 + ty*4 + i);
        int col = h*HD + tx*4;
        uint2 H, L; split4_u2(rv, H, L);
        __nv_bfloat16* crow = ctxA + grow * (3*Dd);
        *(uint2*)&crow[col]          = H;
        *(uint2*)&crow[Dd + col]     = L;
        *(uint2*)&crow[2*Dd + col]   = H;
    }
}

// ---------------- Gaussian kernel weights (A-form bf16) + row sums ----------------
__global__ __launch_bounds__(256) void kw_kernel(
    const int* __restrict__ posv, const int* __restrict__ posh,
    __nv_bfloat16* __restrict__ kwA, float* __restrict__ ksum)
{
    long bq = blockIdx.x;
    int b = (int)(bq >> 10), q = (int)(bq & 1023);
    int tid = threadIdx.x;
    const int* pvb = posv + (long)b*Tt;
    const int* phb = posh + (long)b*Tt;
    int qv = pvb[q], qh = phb[q];
    int k0 = tid * 4;
    int4 kv4 = *(const int4*)&pvb[k0];
    int4 kh4 = *(const int4*)&phb[k0];
    const float c = -1.0f / 512.0f;
    int dvx = qv-kv4.x, dhx = qh-kh4.x;
    int dvy = qv-kv4.y, dhy = qh-kh4.y;
    int dvz = qv-kv4.z, dhz = qh-kh4.z;
    int dvw = qv-kv4.w, dhw = qh-kh4.w;
    float4 w4;
    w4.x = __expf((float)(dvx*dvx + dhx*dhx) * c);
    w4.y = __expf((float)(dvy*dvy + dhy*dhy) * c);
    w4.z = __expf((float)(dvz*dvz + dhz*dhz) * c);
    w4.w = __expf((float)(dvw*dvw + dhw*dhw) * c);
    uint2 H, L; split4_u2(w4, H, L);
    __nv_bfloat16* row = kwA + bq * (3*Tt);
    *(uint2*)&row[k0]          = H;
    *(uint2*)&row[Tt + k0]     = L;
    *(uint2*)&row[2*Tt + k0]   = H;
    float s = w4.x + w4.y + w4.z + w4.w;
#pragma unroll
    for (int o = 16; o; o >>= 1) s += __shfl_xor_sync(0xffffffffu, s, o);
    __shared__ float red[8];
    if ((tid & 31) == 0) red[tid >> 5] = s;
    __syncthreads();
    if (tid == 0) {
        float t = 0.f;
#pragma unroll
        for (int i = 0; i < 8; i++) t += red[i];
        ksum[bq] = t;
    }
}

// ---------------- combine (x1 fp32) + LN2 -> A-form bf16 ----------------
__global__ __launch_bounds__(256) void combine_ln2_kernel(
    const float* __restrict__ x, const float* __restrict__ stdo,
    const float* __restrict__ ko, const float* __restrict__ ksum,
    const float* __restrict__ gate,
    const float* __restrict__ w, const float* __restrict__ bb,
    float* __restrict__ x1, __nv_bfloat16* __restrict__ xn2A)
{
    int warp = threadIdx.x >> 5, lane = threadIdx.x & 31;
    long row = (long)blockIdx.x * 8 + warp;
    float g = 1.0f / (1.0f + __expf(-gate[0]));
    float gi = 1.0f - g;
    float inv_ks = 1.0f / ksum[row];
    long base = row * Dd;
    float4 v[4];
    float s = 0.f, sq = 0.f;
#pragma unroll
    for (int i = 0; i < 4; i++) {
        int d = lane*4 + i*128;
        float4 xv = *(const float4*)&x[base + d];
        float4 sv = *(const float4*)&stdo[base + d];
        float4 kv = *(const float4*)&ko[base + d];
        float4 o4;
        o4.x = xv.x + g*sv.x + gi*kv.x*inv_ks;
        o4.y = xv.y + g*sv.y + gi*kv.y*inv_ks;
        o4.z = xv.z + g*sv.z + gi*kv.z*inv_ks;
        o4.w = xv.w + g*sv.w + gi*kv.w*inv_ks;
        *(float4*)&x1[base + d] = o4;
        v[i] = o4;
        s  += o4.x + o4.y + o4.z + o4.w;
        sq += o4.x*o4.x + o4.y*o4.y + o4.z*o4.z + o4.w*o4.w;
    }
#pragma unroll
    for (int o = 16; o; o >>= 1) {
        s  += __shfl_xor_sync(0xffffffffu, s,  o);
        sq += __shfl_xor_sync(0xffffffffu, sq, o);
    }
    float mean = s * (1.0f/512.0f);
    float var  = sq * (1.0f/512.0f) - mean*mean;
    float rr   = rsqrtf(var + 1e-5f);
    __nv_bfloat16* arow = xn2A + row * (3*Dd);
#pragma unroll
    for (int i = 0; i < 4; i++) {
        int d = lane*4 + i*128;
        float4 wv = *(const float4*)&w[d];
        float4 bv = *(const float4*)&bb[d];
        float4 o4;
        o4.x = (v[i].x - mean)*rr*wv.x + bv.x;
        o4.y = (v[i].y - mean)*rr*wv.y + bv.y;
        o4.z = (v[i].z - mean)*rr*wv.z + bv.z;
        o4.w = (v[i].w - mean)*rr*wv.w + bv.w;
        uint2 H, L; split4_u2(o4, H, L);
        *(uint2*)&arow[d]          = H;
        *(uint2*)&arow[Dd + d]     = L;
        *(uint2*)&arow[2*Dd + d]   = H;
    }
}

// ---------------- launch ----------------
extern "C" void kernel_launch(void* const* d_in, const int* in_sizes, int n_in,
                              void* d_out, int out_size)
{
    const float* x      = (const float*)d_in[0];
    const int*   posv   = (const int*)  d_in[1];
    const int*   posh   = (const int*)  d_in[2];
    const float* n1w    = (const float*)d_in[3];
    const float* n1b    = (const float*)d_in[4];
    const float* in_w   = (const float*)d_in[5];
    const float* in_b   = (const float*)d_in[6];
    const float* out_w  = (const float*)d_in[7];
    const float* out_b  = (const float*)d_in[8];
    const float* n2w    = (const float*)d_in[9];
    const float* n2b    = (const float*)d_in[10];
    const float* w1     = (const float*)d_in[11];
    const float* b1     = (const float*)d_in[12];
    const float* w2     = (const float*)d_in[13];
    const float* b2     = (const float*)d_in[14];
    const float* gate   = (const float*)d_in[15];
    float* out = (float*)d_out;

    __nv_bfloat16 *xnA, *xnB, *ctxA, *kwA, *xn2A, *hA, *wIN, *wOUT, *w1p, *w2p;
    float *qkv, *stdo, *ksum, *ko, *x1;
    cudaGetSymbolAddress((void**)&xnA,  g_xnA);
    cudaGetSymbolAddress((void**)&xnB,  g_xnB);
    cudaGetSymbolAddress((void**)&qkv,  g_qkv);
    cudaGetSymbolAddress((void**)&ctxA, g_ctxA);
    cudaGetSymbolAddress((void**)&stdo, g_stdo);
    cudaGetSymbolAddress((void**)&kwA,  g_kwA);
    cudaGetSymbolAddress((void**)&ksum, g_ksum);
    cudaGetSymbolAddress((void**)&ko,   g_ko);
    cudaGetSymbolAddress((void**)&x1,   g_x1);
    cudaGetSymbolAddress((void**)&xn2A, g_xn2A);
    cudaGetSymbolAddress((void**)&hA,   g_hA);
    cudaGetSymbolAddress((void**)&wIN,  g_wIN);
    cudaGetSymbolAddress((void**)&wOUT, g_wOUT);
    cudaGetSymbolAddress((void**)&w1p,  g_w1);
    cudaGetSymbolAddress((void**)&w2p,  g_w2);

    cudaFuncSetAttribute(gemm_bf16<false,0>, cudaFuncAttributeMaxDynamicSharedMemorySize, GSMEM_W);
    cudaFuncSetAttribute(gemm_bf16<false,1>, cudaFuncAttributeMaxDynamicSharedMemorySize, GSMEM_W);
    cudaFuncSetAttribute(gemm_bf16<false,2>, cudaFuncAttributeMaxDynamicSharedMemorySize, GSMEM_W);
    cudaFuncSetAttribute(gemm_bf16<true,0>,  cudaFuncAttributeMaxDynamicSharedMemorySize, GSMEM_R);

    // weight conversions (B-form [hi|hi|lo])
    conv_w_kernel<<<(3*Dd*Dd/4 + 255)/256, 256>>>(in_w,  wIN,  Dd, 3*Dd*Dd/4);
    conv_w_kernel<<<(Dd*Dd/4   + 255)/256, 256>>>(out_w, wOUT, Dd, Dd*Dd/4);
    conv_w_kernel<<<(D4*Dd/4   + 255)/256, 256>>>(w1,    w1p,  Dd, D4*Dd/4);
    conv_w_kernel<<<(Dd*D4/4   + 255)/256, 256>>>(w2,    w2p,  D4, Dd*D4/4);

    // 1) LN1 -> xnA (A-form), xnB (B-form)
    ln1_kernel<<<ROWS/8, 256>>>(x, n1w, n1b, xnA, xnB);

    // 2) QKV = xn @ in_w^T + in_b   grid (1536/256, 8192/128)
    gemm_bf16<false, 0><<<dim3(6, 64), 256, GSMEM_W>>>(
        xnA, wIN, in_b, nullptr, qkv, 3*Dd, 3*Dd, 0, 0, 0);

    // 3) flash attention -> ctxA
    {
        static const int SMEM = 4 * 4352 * 4;
        cudaFuncSetAttribute(attn_kernel, cudaFuncAttributeMaxDynamicSharedMemorySize, SMEM);
        attn_kernel<<<dim3(Tt/64, Hh, Bb), 256, SMEM>>>(qkv, ctxA);
    }

    // 4) std_out = ctx @ out_w^T + out_b   grid (2, 64)
    gemm_bf16<false, 0><<<dim3(2, 64), 256, GSMEM_W>>>(
        ctxA, wOUT, out_b, nullptr, stdo, Dd, 3*Dd, 0, 0, 0);

    // 5) Gaussian kernel weights
    kw_kernel<<<ROWS, 256>>>(posv, posh, kwA, ksum);

    // 6) ko = kw @ xn (batched)   grid (2, 8, 8)
    gemm_bf16<true, 0><<<dim3(2, 8, Bb), 256, GSMEM_R>>>(
        kwA, xnB, nullptr, nullptr, ko, Dd, 3*Tt,
        (long)Tt*3*Tt, (long)3*Tt*Dd, (long)Tt*Dd);

    // 7) combine + LN2
    combine_ln2_kernel<<<ROWS/8, 256>>>(x, stdo, ko, ksum, gate, n2w, n2b, x1, xn2A);

    // 8) h = gelu(xn2 @ w1^T + b1)   grid (8, 64)
    gemm_bf16<false, 1><<<dim3(8, 64), 256, GSMEM_W>>>(
        xn2A, w1p, b1, nullptr, hA, D4, 3*Dd, 0, 0, 0);

    // 9) out = x1 + h @ w2^T + b2    grid (2, 64)
    gemm_bf16<false, 2><<<dim3(2, 64), 256, GSMEM_W>>>(
        hA, w2p, b2, x1, out, Dd, 3*D4, 0, 0, 0);
}

// round 7
// speedup vs baseline: 1.7326x; 1.0734x over previous
#include <cuda_runtime.h>
#include <cuda_bf16.h>
#include <mma.h>
#include <math.h>
#include <stdint.h>

using namespace nvcuda;

#define Bb 8
#define Tt 1024
#define Dd 512
#define Hh 8
#define HD 64
#define D4 2048
#define ROWS (Bb*Tt)

// ---------------- scratch (device globals) ----------------
__device__ __nv_bfloat16 g_xnA [ROWS*3*Dd];
__device__ __nv_bfloat16 g_xnB [Bb*3*Tt*Dd];
__device__ float         g_qkv [ROWS*3*Dd];
__device__ __nv_bfloat16 g_ctxA[ROWS*3*Dd];
__device__ float         g_stdo[ROWS*Dd];
__device__ __nv_bfloat16 g_kwA [Bb*Tt*3*Tt];
__device__ float         g_ksum[ROWS];
__device__ float         g_ko  [ROWS*Dd];
__device__ float         g_x1  [ROWS*Dd];
__device__ __nv_bfloat16 g_xn2A[ROWS*3*Dd];
__device__ __nv_bfloat16 g_hA  [ROWS*3*D4];
__device__ __nv_bfloat16 g_wIN [3*Dd*3*Dd];
__device__ __nv_bfloat16 g_wOUT[Dd*3*Dd];
__device__ __nv_bfloat16 g_w1  [D4*3*Dd];
__device__ __nv_bfloat16 g_w2  [Dd*3*D4];

// ---------------- helpers ----------------
__device__ __forceinline__ uint32_t smem_u32(const void* p) {
    uint32_t a;
    asm("{ .reg .u64 t; cvta.to.shared.u64 t, %1; cvt.u32.u64 %0, t; }" : "=r"(a) : "l"(p));
    return a;
}
__device__ __forceinline__ void cp16(uint32_t sdst, const void* gsrc) {
    asm volatile("cp.async.cg.shared.global [%0], [%1], 16;" :: "r"(sdst), "l"(gsrc));
}
__device__ __forceinline__ void cp_commit() {
    asm volatile("cp.async.commit_group;" ::: "memory");
}
template<int N>
__device__ __forceinline__ void cp_wait() {
    asm volatile("cp.async.wait_group %0;" :: "n"(N) : "memory");
}
__device__ __forceinline__ void split_bf(float v, __nv_bfloat16& h, __nv_bfloat16& l) {
    h = __float2bfloat16(v);
    l = __float2bfloat16(v - __bfloat162float(h));
}
__device__ __forceinline__ void split4_u2(float4 v, uint2& H, uint2& L) {
    __nv_bfloat16 hx,lx,hy,ly,hz,lz,hw,lw;
    split_bf(v.x,hx,lx); split_bf(v.y,hy,ly);
    split_bf(v.z,hz,lz); split_bf(v.w,hw,lw);
    __nv_bfloat162 h01 = __halves2bfloat162(hx,hy);
    __nv_bfloat162 h23 = __halves2bfloat162(hz,hw);
    __nv_bfloat162 l01 = __halves2bfloat162(lx,ly);
    __nv_bfloat162 l23 = __halves2bfloat162(lz,lw);
    H.x = *reinterpret_cast<unsigned*>(&h01); H.y = *reinterpret_cast<unsigned*>(&h23);
    L.x = *reinterpret_cast<unsigned*>(&l01); L.y = *reinterpret_cast<unsigned*>(&l23);
}
__device__ __forceinline__ float gelu_exact(float v) {
    return 0.5f * v * (1.0f + erff(v * 0.7071067811865476f));
}

// ---------------- mma / ldmatrix primitives ----------------
__device__ __forceinline__ void ldsm_x4(uint32_t& r0, uint32_t& r1, uint32_t& r2, uint32_t& r3, uint32_t a) {
    asm volatile("ldmatrix.sync.aligned.m8n8.x4.shared.b16 {%0,%1,%2,%3}, [%4];"
                 : "=r"(r0),"=r"(r1),"=r"(r2),"=r"(r3) : "r"(a));
}
__device__ __forceinline__ void ldsm_x2(uint32_t& r0, uint32_t& r1, uint32_t a) {
    asm volatile("ldmatrix.sync.aligned.m8n8.x2.shared.b16 {%0,%1}, [%2];"
                 : "=r"(r0),"=r"(r1) : "r"(a));
}
__device__ __forceinline__ void ldsm_x2t(uint32_t& r0, uint32_t& r1, uint32_t a) {
    asm volatile("ldmatrix.sync.aligned.m8n8.x2.trans.shared.b16 {%0,%1}, [%2];"
                 : "=r"(r0),"=r"(r1) : "r"(a));
}
__device__ __forceinline__ void mma16816(float* c, uint32_t a0, uint32_t a1, uint32_t a2, uint32_t a3,
                                         uint32_t b0, uint32_t b1) {
    asm volatile("mma.sync.aligned.m16n8k16.row.col.f32.bf16.bf16.f32 "
                 "{%0,%1,%2,%3}, {%4,%5,%6,%7}, {%8,%9}, {%0,%1,%2,%3};"
                 : "+f"(c[0]),"+f"(c[1]),"+f"(c[2]),"+f"(c[3])
                 : "r"(a0),"r"(a1),"r"(a2),"r"(a3),"r"(b0),"r"(b1));
}

// ---------------- weight conversion: W[N][K] -> W'[N][3K] = [hi|hi|lo] ----------------
__global__ __launch_bounds__(256) void conv_w_kernel(
    const float* __restrict__ W, __nv_bfloat16* __restrict__ Wp, int K, int total4)
{
    int idx = blockIdx.x * 256 + threadIdx.x;
    if (idx >= total4) return;
    long e = (long)idx * 4;
    int r = (int)(e / K), c = (int)(e % K);
    float4 v = *(const float4*)&W[(long)r * K + c];
    uint2 H, L; split4_u2(v, H, L);
    __nv_bfloat16* row = Wp + (long)r * 3 * K;
    *(uint2*)&row[c]         = H;
    *(uint2*)&row[K + c]     = H;
    *(uint2*)&row[2*K + c]   = L;
}

// ================ bf16-split GEMM, tile width templated ================
#define GSTAGES 3
#define ASTR 40
#define ASZ   (128*ASTR*2)          // 10240

template<int NT, bool BROW, int EPI>
__global__ __launch_bounds__(256) void gemm_bf16(
    const __nv_bfloat16* __restrict__ A, const __nv_bfloat16* __restrict__ B,
    const float* __restrict__ bias, const float* __restrict__ res,
    void* __restrict__ Cout, int N, int Kp,
    long sA, long sB, long sC)
{
    constexpr int NFR  = NT/64;          // n-frags per warp
    constexpr int BSTR = NT + 8;         // BROW smem stride (halves)
    constexpr int BSZ  = BROW ? 32*BSTR*2 : NT*ASTR*2;

    extern __shared__ __align__(128) char sm[];
    char* Abase = sm;
    char* Bbase = sm + GSTAGES * ASZ;

    int z = blockIdx.z;
    const int tid = threadIdx.x;
    int w = tid >> 5, lane = tid & 31, wm = w >> 2, wn = w & 3;
    int m0 = blockIdx.y << 7, n0 = blockIdx.x * NT;
    A += z * sA; B += z * sB;

    int ar = tid >> 2, ac = (tid & 3) * 8;
    constexpr int TPR = NT/8;                 // BROW threads per row
    constexpr int RS  = 2048/NT;              // BROW rows per pass
    int br = tid / TPR, bc = (tid % TPR) * 8;

    const __nv_bfloat16* Ag = A + (long)(m0 + ar) * Kp + ac;
    const __nv_bfloat16* Bg = BROW
        ? (B + (long)br * N + n0 + bc)
        : (B + (long)(n0 + ar) * Kp + ac);
    uint32_t Asw = smem_u32(Abase) + (uint32_t)(ar * (ASTR*2) + ac * 2);
    uint32_t Bsw = BROW
        ? smem_u32(Bbase) + (uint32_t)(br * (BSTR*2) + bc * 2)
        : smem_u32(Bbase) + (uint32_t)(ar * (ASTR*2) + ac * 2);

    int nk = Kp >> 5;

#define GISSUE(kt) do { \
        if ((kt) < nk) { \
            int st_ = (kt) % GSTAGES; \
            long ko_ = (long)(kt) * 32; \
            uint32_t ad = Asw + (uint32_t)st_ * ASZ; \
            cp16(ad,                Ag + ko_); \
            cp16(ad + 64*(ASTR*2),  Ag + ko_ + (long)64*Kp); \
            uint32_t bd = Bsw + (uint32_t)st_ * BSZ; \
            if (BROW) { \
                _Pragma("unroll") \
                for (int i_ = 0; i_ < 32/RS; i_++) \
                    cp16(bd + i_*RS*(BSTR*2), Bg + (ko_ + i_*RS) * N); \
            } else { \
                _Pragma("unroll") \
                for (int i_ = 0; i_ < NT/64; i_++) \
                    cp16(bd + i_*64*(ASTR*2), Bg + ko_ + (long)(i_*64)*Kp); \
            } \
        } \
        cp_commit(); \
    } while (0)

    wmma::fragment<wmma::accumulator, 16, 16, 16, float> acc[4][NFR];
#pragma unroll
    for (int i = 0; i < 4; i++)
#pragma unroll
        for (int j = 0; j < NFR; j++) wmma::fill_fragment(acc[i][j], 0.f);

#pragma unroll
    for (int i = 0; i < GSTAGES - 1; i++) GISSUE(i);

    for (int kt = 0; kt < nk; kt++) {
        cp_wait<GSTAGES - 2>();
        __syncthreads();
        GISSUE(kt + GSTAGES - 1);
        int st = kt % GSTAGES;
        const __nv_bfloat16* Asm = (const __nv_bfloat16*)(Abase + st * ASZ);
        const __nv_bfloat16* Bsm = (const __nv_bfloat16*)(Bbase + st * BSZ);
#pragma unroll
        for (int kk = 0; kk < 2; kk++) {
            wmma::fragment<wmma::matrix_a, 16, 16, 16, __nv_bfloat16, wmma::row_major> af[4];
#pragma unroll
            for (int i = 0; i < 4; i++)
                wmma::load_matrix_sync(af[i], Asm + (wm*64 + i*16)*ASTR + kk*16, ASTR);
#pragma unroll
            for (int jh = 0; jh < NFR/2; jh++) {
                if (BROW) {
                    wmma::fragment<wmma::matrix_b, 16, 16, 16, __nv_bfloat16, wmma::row_major> bf[2];
#pragma unroll
                    for (int j = 0; j < 2; j++)
                        wmma::load_matrix_sync(bf[j], Bsm + (kk*16)*BSTR + wn*(NT/4) + jh*32 + j*16, BSTR);
#pragma unroll
                    for (int i = 0; i < 4; i++)
#pragma unroll
                        for (int j = 0; j < 2; j++)
                            wmma::mma_sync(acc[i][jh*2+j], af[i], bf[j], acc[i][jh*2+j]);
                } else {
                    wmma::fragment<wmma::matrix_b, 16, 16, 16, __nv_bfloat16, wmma::col_major> bf[2];
#pragma unroll
                    for (int j = 0; j < 2; j++)
                        wmma::load_matrix_sync(bf[j], Bsm + (wn*(NT/4) + jh*32 + j*16)*ASTR + kk*16, ASTR);
#pragma unroll
                    for (int i = 0; i < 4; i++)
#pragma unroll
                        for (int j = 0; j < 2; j++)
                            wmma::mma_sync(acc[i][jh*2+j], af[i], bf[j], acc[i][jh*2+j]);
                }
            }
        }
        __syncthreads();
    }
#undef GISSUE

    // epilogue via smem staging
    float* EP = (float*)sm + w * 256;
    int r = lane >> 1, c0 = (lane & 1) * 8;
    long ldc = (EPI == 1) ? (long)3 * N : (long)N;
#pragma unroll
    for (int i = 0; i < 4; i++) {
#pragma unroll
        for (int j = 0; j < NFR; j++) {
            wmma::store_matrix_sync(EP, acc[i][j], 16, wmma::mem_row_major);
            __syncwarp();
            long grow = m0 + wm*64 + i*16 + r;
            int  gcol = n0 + wn*(NT/4) + j*16 + c0;
            float4 v0 = *(float4*)&EP[r*16 + c0];
            float4 v1 = *(float4*)&EP[r*16 + c0 + 4];
            if (bias) {
                float4 b0 = *(const float4*)&bias[gcol];
                float4 b1 = *(const float4*)&bias[gcol + 4];
                v0.x += b0.x; v0.y += b0.y; v0.z += b0.z; v0.w += b0.w;
                v1.x += b1.x; v1.y += b1.y; v1.z += b1.z; v1.w += b1.w;
            }
            if (EPI == 1) {
                v0.x = gelu_exact(v0.x); v0.y = gelu_exact(v0.y);
                v0.z = gelu_exact(v0.z); v0.w = gelu_exact(v0.w);
                v1.x = gelu_exact(v1.x); v1.y = gelu_exact(v1.y);
                v1.z = gelu_exact(v1.z); v1.w = gelu_exact(v1.w);
                uint2 H0,L0,H1,L1;
                split4_u2(v0,H0,L0); split4_u2(v1,H1,L1);
                __nv_bfloat16* Crow = (__nv_bfloat16*)Cout + grow * ldc;
                uint4 Hq = make_uint4(H0.x,H0.y,H1.x,H1.y);
                uint4 Lq = make_uint4(L0.x,L0.y,L1.x,L1.y);
                *(uint4*)&Crow[gcol]         = Hq;
                *(uint4*)&Crow[N + gcol]     = Lq;
                *(uint4*)&Crow[2*N + gcol]   = Hq;
            } else {
                float* C = (float*)Cout + z * sC;
                if (EPI == 2) {
                    float4 r0 = *(const float4*)&res[grow*N + gcol];
                    float4 r1 = *(const float4*)&res[grow*N + gcol + 4];
                    v0.x += r0.x; v0.y += r0.y; v0.z += r0.z; v0.w += r0.w;
                    v1.x += r1.x; v1.y += r1.y; v1.z += r1.z; v1.w += r1.w;
                }
                *(float4*)&C[grow*ldc + gcol]     = v0;
                *(float4*)&C[grow*ldc + gcol + 4] = v1;
            }
            __syncwarp();
        }
    }
}

#define GSMEM_W256 (GSTAGES*(ASZ + 256*ASTR*2))   // 92160
#define GSMEM_W128 (GSTAGES*(ASZ + 128*ASTR*2))   // 61440
#define GSMEM_R128 (GSTAGES*(ASZ + 32*136*2))     // 56832

// ---------------- LN1: fp32 in -> A-form + B-form bf16 out ----------------
__global__ __launch_bounds__(256) void ln1_kernel(
    const float* __restrict__ x, const float* __restrict__ w,
    const float* __restrict__ b,
    __nv_bfloat16* __restrict__ xnA, __nv_bfloat16* __restrict__ xnB)
{
    int warp = threadIdx.x >> 5, lane = threadIdx.x & 31;
    long row = (long)blockIdx.x * 8 + warp;
    const float* xr = x + row * Dd;
    float4 v[4];
    float s = 0.f, sq = 0.f;
#pragma unroll
    for (int i = 0; i < 4; i++) {
        v[i] = *(const float4*)&xr[lane*4 + i*128];
        s  += v[i].x + v[i].y + v[i].z + v[i].w;
        sq += v[i].x*v[i].x + v[i].y*v[i].y + v[i].z*v[i].z + v[i].w*v[i].w;
    }
#pragma unroll
    for (int o = 16; o; o >>= 1) {
        s  += __shfl_xor_sync(0xffffffffu, s,  o);
        sq += __shfl_xor_sync(0xffffffffu, sq, o);
    }
    float mean = s * (1.0f/512.0f);
    float var  = sq * (1.0f/512.0f) - mean*mean;
    float rr   = rsqrtf(var + 1e-5f);
    int bz = (int)(row >> 10), rz = (int)(row & 1023);
    __nv_bfloat16* arow = xnA + row * (3*Dd);
    __nv_bfloat16* bbase = xnB + (long)bz * 3*Tt*Dd;
#pragma unroll
    for (int i = 0; i < 4; i++) {
        int d = lane*4 + i*128;
        float4 wv = *(const float4*)&w[d];
        float4 bv = *(const float4*)&b[d];
        float4 o4;
        o4.x = (v[i].x - mean)*rr*wv.x + bv.x;
        o4.y = (v[i].y - mean)*rr*wv.y + bv.y;
        o4.z = (v[i].z - mean)*rr*wv.z + bv.z;
        o4.w = (v[i].w - mean)*rr*wv.w + bv.w;
        uint2 H, L; split4_u2(o4, H, L);
        *(uint2*)&arow[d]          = H;
        *(uint2*)&arow[Dd + d]     = L;
        *(uint2*)&arow[2*Dd + d]   = H;
        *(uint2*)&bbase[(long)rz*Dd + d]            = H;
        *(uint2*)&bbase[(long)(Tt + rz)*Dd + d]     = H;
        *(uint2*)&bbase[(long)(2*Tt + rz)*Dd + d]   = L;
    }
}

// ---------------- flash attention on mma.sync (split-bf16 scores, bf16 PV) ----------------
#define QSTR 200
#define VSTR 72
#define ATTN_SMEM ((2*64*QSTR + 64*VSTR)*2)   // 60416 bytes

__global__ __launch_bounds__(128) void attn_mma_kernel(
    const float* __restrict__ qkv, __nv_bfloat16* __restrict__ ctxA)
{
    extern __shared__ __nv_bfloat16 smh[];
    __nv_bfloat16* Qs = smh;
    __nv_bfloat16* Ks = smh + 64*QSTR;
    __nv_bfloat16* Vs = smh + 2*64*QSTR;

    int b = blockIdx.z, h = blockIdx.y, qt = blockIdx.x;
    int tid = threadIdx.x, wq = tid >> 5, lane = tid & 31;
    const int LDR = 3*Dd;
    const float* base = qkv + (long)b * Tt * LDR;

    // fill Q once (scaled by 1/8, A-form triple [hi|lo|hi])
    {
        int row = tid >> 1, cb = (tid & 1) * 32;
        const float* qp = base + (long)(qt*64 + row) * LDR + h*HD + cb;
#pragma unroll
        for (int i = 0; i < 8; i++) {
            float4 v = *(const float4*)(qp + i*4);
            v.x *= 0.125f; v.y *= 0.125f; v.z *= 0.125f; v.w *= 0.125f;
            uint2 H, L; split4_u2(v, H, L);
            int c = cb + i*4;
            *(uint2*)&Qs[row*QSTR + c]       = H;
            *(uint2*)&Qs[row*QSTR + 64 + c]  = L;
            *(uint2*)&Qs[row*QSTR + 128 + c] = H;
        }
    }

    float cf[8][4];
#pragma unroll
    for (int j = 0; j < 8; j++) { cf[j][0]=0.f; cf[j][1]=0.f; cf[j][2]=0.f; cf[j][3]=0.f; }
    float m0 = -1e30f, m1 = -1e30f, l0 = 0.f, l1 = 0.f;

    uint32_t qaddr = smem_u32(&Qs[(16*wq + (lane & 15))*QSTR + 8*(lane >> 4)]);

    for (int kt = 0; kt < 16; kt++) {
        __syncthreads();
        // fill K (B-form triple [hi|hi|lo]) and V (bf16)
        {
            int row = tid >> 1, cb = (tid & 1) * 32;
            const float* kp = base + (long)(kt*64 + row) * LDR + Dd   + h*HD + cb;
            const float* vp = base + (long)(kt*64 + row) * LDR + 2*Dd + h*HD + cb;
#pragma unroll
            for (int i = 0; i < 8; i++) {
                float4 v = *(const float4*)(kp + i*4);
                uint2 H, L; split4_u2(v, H, L);
                int c = cb + i*4;
                *(uint2*)&Ks[row*QSTR + c]       = H;
                *(uint2*)&Ks[row*QSTR + 64 + c]  = H;
                *(uint2*)&Ks[row*QSTR + 128 + c] = L;
                float4 vv = *(const float4*)(vp + i*4);
                __nv_bfloat162 p0 = __floats2bfloat162_rn(vv.x, vv.y);
                __nv_bfloat162 p1 = __floats2bfloat162_rn(vv.z, vv.w);
                uint2 P; P.x = *(unsigned*)&p0; P.y = *(unsigned*)&p1;
                *(uint2*)&Vs[row*VSTR + c] = P;
            }
        }
        __syncthreads();

        // S = Q K^T over 192 split-k
        float sf[8][4] = {};
#pragma unroll
        for (int kc = 0; kc < 12; kc++) {
            uint32_t a0, a1, a2, a3;
            ldsm_x4(a0, a1, a2, a3, qaddr + kc*32);
#pragma unroll
            for (int n8 = 0; n8 < 8; n8++) {
                uint32_t b0, b1;
                uint32_t ka = smem_u32(&Ks[(8*n8 + (lane & 7))*QSTR + 16*kc + 8*((lane >> 3) & 1)]);
                ldsm_x2(b0, b1, ka);
                mma16816(sf[n8], a0, a1, a2, a3, b0, b1);
            }
        }

        // online softmax
        float mt0 = -1e30f, mt1 = -1e30f;
#pragma unroll
        for (int j = 0; j < 8; j++) {
            mt0 = fmaxf(mt0, fmaxf(sf[j][0], sf[j][1]));
            mt1 = fmaxf(mt1, fmaxf(sf[j][2], sf[j][3]));
        }
        mt0 = fmaxf(mt0, __shfl_xor_sync(0xffffffffu, mt0, 1));
        mt0 = fmaxf(mt0, __shfl_xor_sync(0xffffffffu, mt0, 2));
        mt1 = fmaxf(mt1, __shfl_xor_sync(0xffffffffu, mt1, 1));
        mt1 = fmaxf(mt1, __shfl_xor_sync(0xffffffffu, mt1, 2));
        float mn0 = fmaxf(m0, mt0), mn1 = fmaxf(m1, mt1);
        float cr0 = __expf(m0 - mn0), cr1 = __expf(m1 - mn1);
        m0 = mn0; m1 = mn1; l0 *= cr0; l1 *= cr1;
#pragma unroll
        for (int j = 0; j < 8; j++) {
            cf[j][0] *= cr0; cf[j][1] *= cr0; cf[j][2] *= cr1; cf[j][3] *= cr1;
        }

        // P in A-fragment registers, directly from S fragments
        uint32_t pa[4][4];
#pragma unroll
        for (int jk = 0; jk < 4; jk++) {
            float e00 = __expf(sf[2*jk][0]   - mn0), e01 = __expf(sf[2*jk][1]   - mn0);
            float e10 = __expf(sf[2*jk][2]   - mn1), e11 = __expf(sf[2*jk][3]   - mn1);
            float e20 = __expf(sf[2*jk+1][0] - mn0), e21 = __expf(sf[2*jk+1][1] - mn0);
            float e30 = __expf(sf[2*jk+1][2] - mn1), e31 = __expf(sf[2*jk+1][3] - mn1);
            l0 += e00 + e01 + e20 + e21;
            l1 += e10 + e11 + e30 + e31;
            __nv_bfloat162 t;
            t = __floats2bfloat162_rn(e00, e01); pa[jk][0] = *(unsigned*)&t;
            t = __floats2bfloat162_rn(e10, e11); pa[jk][1] = *(unsigned*)&t;
            t = __floats2bfloat162_rn(e20, e21); pa[jk][2] = *(unsigned*)&t;
            t = __floats2bfloat162_rn(e30, e31); pa[jk][3] = *(unsigned*)&t;
        }

        // ctx += P @ V
#pragma unroll
        for (int jk = 0; jk < 4; jk++) {
#pragma unroll
            for (int jd = 0; jd < 8; jd++) {
                uint32_t b0, b1;
                uint32_t va = smem_u32(&Vs[(16*jk + (lane & 15))*VSTR + 8*jd]);
                ldsm_x2t(b0, b1, va);
                mma16816(cf[jd], pa[jk][0], pa[jk][1], pa[jk][2], pa[jk][3], b0, b1);
            }
        }
    }

    l0 += __shfl_xor_sync(0xffffffffu, l0, 1);
    l0 += __shfl_xor_sync(0xffffffffu, l0, 2);
    l1 += __shfl_xor_sync(0xffffffffu, l1, 1);
    l1 += __shfl_xor_sync(0xffffffffu, l1, 2);
    float inv0 = 1.0f / l0, inv1 = 1.0f / l1;

    long grow0 = (long)b*Tt + qt*64 + 16*wq + (lane >> 2);
    long grow1 = grow0 + 8;
    int colb = h*HD + 2*(lane & 3);
    __nv_bfloat16* cr0p = ctxA + grow0 * (3*Dd);
    __nv_bfloat16* cr1p = ctxA + grow1 * (3*Dd);
#pragma unroll
    for (int jd = 0; jd < 8; jd++) {
        int col = colb + 8*jd;
        {
            float v0 = cf[jd][0]*inv0, v1 = cf[jd][1]*inv0;
            __nv_bfloat16 h0,lo0,h1,lo1; split_bf(v0,h0,lo0); split_bf(v1,h1,lo1);
            __nv_bfloat162 Hp = __halves2bfloat162(h0,h1), Lp = __halves2bfloat162(lo0,lo1);
            *(unsigned*)&cr0p[col]        = *(unsigned*)&Hp;
            *(unsigned*)&cr0p[Dd + col]   = *(unsigned*)&Lp;
            *(unsigned*)&cr0p[2*Dd + col] = *(unsigned*)&Hp;
        }
        {
            float v0 = cf[jd][2]*inv1, v1 = cf[jd][3]*inv1;
            __nv_bfloat16 h0,lo0,h1,lo1; split_bf(v0,h0,lo0); split_bf(v1,h1,lo1);
            __nv_bfloat162 Hp = __halves2bfloat162(h0,h1), Lp = __halves2bfloat162(lo0,lo1);
            *(unsigned*)&cr1p[col]        = *(unsigned*)&Hp;
            *(unsigned*)&cr1p[Dd + col]   = *(unsigned*)&Lp;
            *(unsigned*)&cr1p[2*Dd + col] = *(unsigned*)&Hp;
        }
    }
}

// ---------------- Gaussian kernel weights (A-form bf16) + row sums ----------------
__global__ __launch_bounds__(256) void kw_kernel(
    const int* __restrict__ posv, const int* __restrict__ posh,
    __nv_bfloat16* __restrict__ kwA, float* __restrict__ ksum)
{
    long bq = blockIdx.x;
    int b = (int)(bq >> 10), q = (int)(bq & 1023);
    int tid = threadIdx.x;
    const int* pvb = posv + (long)b*Tt;
    const int* phb = posh + (long)b*Tt;
    int qv = pvb[q], qh = phb[q];
    int k0 = tid * 4;
    int4 kv4 = *(const int4*)&pvb[k0];
    int4 kh4 = *(const int4*)&phb[k0];
    const float c = -1.0f / 512.0f;
    int dvx = qv-kv4.x, dhx = qh-kh4.x;
    int dvy = qv-kv4.y, dhy = qh-kh4.y;
    int dvz = qv-kv4.z, dhz = qh-kh4.z;
    int dvw = qv-kv4.w, dhw = qh-kh4.w;
    float4 w4;
    w4.x = __expf((float)(dvx*dvx + dhx*dhx) * c);
    w4.y = __expf((float)(dvy*dvy + dhy*dhy) * c);
    w4.z = __expf((float)(dvz*dvz + dhz*dhz) * c);
    w4.w = __expf((float)(dvw*dvw + dhw*dhw) * c);
    uint2 H, L; split4_u2(w4, H, L);
    __nv_bfloat16* row = kwA + bq * (3*Tt);
    *(uint2*)&row[k0]          = H;
    *(uint2*)&row[Tt + k0]     = L;
    *(uint2*)&row[2*Tt + k0]   = H;
    float s = w4.x + w4.y + w4.z + w4.w;
#pragma unroll
    for (int o = 16; o; o >>= 1) s += __shfl_xor_sync(0xffffffffu, s, o);
    __shared__ float red[8];
    if ((tid & 31) == 0) red[tid >> 5] = s;
    __syncthreads();
    if (tid == 0) {
        float t = 0.f;
#pragma unroll
        for (int i = 0; i < 8; i++) t += red[i];
        ksum[bq] = t;
    }
}

// ---------------- combine (x1 fp32) + LN2 -> A-form bf16 ----------------
__global__ __launch_bounds__(256) void combine_ln2_kernel(
    const float* __restrict__ x, const float* __restrict__ stdo,
    const float* __restrict__ ko, const float* __restrict__ ksum,
    const float* __restrict__ gate,
    const float* __restrict__ w, const float* __restrict__ bb,
    float* __restrict__ x1, __nv_bfloat16* __restrict__ xn2A)
{
    int warp = threadIdx.x >> 5, lane = threadIdx.x & 31;
    long row = (long)blockIdx.x * 8 + warp;
    float g = 1.0f / (1.0f + __expf(-gate[0]));
    float gi = 1.0f - g;
    float inv_ks = 1.0f / ksum[row];
    long base = row * Dd;
    float4 v[4];
    float s = 0.f, sq = 0.f;
#pragma unroll
    for (int i = 0; i < 4; i++) {
        int d = lane*4 + i*128;
        float4 xv = *(const float4*)&x[base + d];
        float4 sv = *(const float4*)&stdo[base + d];
        float4 kv = *(const float4*)&ko[base + d];
        float4 o4;
        o4.x = xv.x + g*sv.x + gi*kv.x*inv_ks;
        o4.y = xv.y + g*sv.y + gi*kv.y*inv_ks;
        o4.z = xv.z + g*sv.z + gi*kv.z*inv_ks;
        o4.w = xv.w + g*sv.w + gi*kv.w*inv_ks;
        *(float4*)&x1[base + d] = o4;
        v[i] = o4;
        s  += o4.x + o4.y + o4.z + o4.w;
        sq += o4.x*o4.x + o4.y*o4.y + o4.z*o4.z + o4.w*o4.w;
    }
#pragma unroll
    for (int o = 16; o; o >>= 1) {
        s  += __shfl_xor_sync(0xffffffffu, s,  o);
        sq += __shfl_xor_sync(0xffffffffu, sq, o);
    }
    float mean = s * (1.0f/512.0f);
    float var  = sq * (1.0f/512.0f) - mean*mean;
    float rr   = rsqrtf(var + 1e-5f);
    __nv_bfloat16* arow = xn2A + row * (3*Dd);
#pragma unroll
    for (int i = 0; i < 4; i++) {
        int d = lane*4 + i*128;
        float4 wv = *(const float4*)&w[d];
        float4 bv = *(const float4*)&bb[d];
        float4 o4;
        o4.x = (v[i].x - mean)*rr*wv.x + bv.x;
        o4.y = (v[i].y - mean)*rr*wv.y + bv.y;
        o4.z = (v[i].z - mean)*rr*wv.z + bv.z;
        o4.w = (v[i].w - mean)*rr*wv.w + bv.w;
        uint2 H, L; split4_u2(o4, H, L);
        *(uint2*)&arow[d]          = H;
        *(uint2*)&arow[Dd + d]     = L;
        *(uint2*)&arow[2*Dd + d]   = H;
    }
}

// ---------------- launch ----------------
extern "C" void kernel_launch(void* const* d_in, const int* in_sizes, int n_in,
                              void* d_out, int out_size)
{
    const float* x      = (const float*)d_in[0];
    const int*   posv   = (const int*)  d_in[1];
    const int*   posh   = (const int*)  d_in[2];
    const float* n1w    = (const float*)d_in[3];
    const float* n1b    = (const float*)d_in[4];
    const float* in_w   = (const float*)d_in[5];
    const float* in_b   = (const float*)d_in[6];
    const float* out_w  = (const float*)d_in[7];
    const float* out_b  = (const float*)d_in[8];
    const float* n2w    = (const float*)d_in[9];
    const float* n2b    = (const float*)d_in[10];
    const float* w1     = (const float*)d_in[11];
    const float* b1     = (const float*)d_in[12];
    const float* w2     = (const float*)d_in[13];
    const float* b2     = (const float*)d_in[14];
    const float* gate   = (const float*)d_in[15];
    float* out = (float*)d_out;

    __nv_bfloat16 *xnA, *xnB, *ctxA, *kwA, *xn2A, *hA, *wIN, *wOUT, *w1p, *w2p;
    float *qkv, *stdo, *ksum, *ko, *x1;
    cudaGetSymbolAddress((void**)&xnA,  g_xnA);
    cudaGetSymbolAddress((void**)&xnB,  g_xnB);
    cudaGetSymbolAddress((void**)&qkv,  g_qkv);
    cudaGetSymbolAddress((void**)&ctxA, g_ctxA);
    cudaGetSymbolAddress((void**)&stdo, g_stdo);
    cudaGetSymbolAddress((void**)&kwA,  g_kwA);
    cudaGetSymbolAddress((void**)&ksum, g_ksum);
    cudaGetSymbolAddress((void**)&ko,   g_ko);
    cudaGetSymbolAddress((void**)&x1,   g_x1);
    cudaGetSymbolAddress((void**)&xn2A, g_xn2A);
    cudaGetSymbolAddress((void**)&hA,   g_hA);
    cudaGetSymbolAddress((void**)&wIN,  g_wIN);
    cudaGetSymbolAddress((void**)&wOUT, g_wOUT);
    cudaGetSymbolAddress((void**)&w1p,  g_w1);
    cudaGetSymbolAddress((void**)&w2p,  g_w2);

    cudaFuncSetAttribute(gemm_bf16<256,false,0>, cudaFuncAttributeMaxDynamicSharedMemorySize, GSMEM_W256);
    cudaFuncSetAttribute(gemm_bf16<256,false,1>, cudaFuncAttributeMaxDynamicSharedMemorySize, GSMEM_W256);
    cudaFuncSetAttribute(gemm_bf16<128,false,0>, cudaFuncAttributeMaxDynamicSharedMemorySize, GSMEM_W128);
    cudaFuncSetAttribute(gemm_bf16<128,false,2>, cudaFuncAttributeMaxDynamicSharedMemorySize, GSMEM_W128);
    cudaFuncSetAttribute(gemm_bf16<128,true,0>,  cudaFuncAttributeMaxDynamicSharedMemorySize, GSMEM_R128);
    cudaFuncSetAttribute(attn_mma_kernel,        cudaFuncAttributeMaxDynamicSharedMemorySize, ATTN_SMEM);

    // weight conversions (B-form [hi|hi|lo])
    conv_w_kernel<<<(3*Dd*Dd/4 + 255)/256, 256>>>(in_w,  wIN,  Dd, 3*Dd*Dd/4);
    conv_w_kernel<<<(Dd*Dd/4   + 255)/256, 256>>>(out_w, wOUT, Dd, Dd*Dd/4);
    conv_w_kernel<<<(D4*Dd/4   + 255)/256, 256>>>(w1,    w1p,  Dd, D4*Dd/4);
    conv_w_kernel<<<(Dd*D4/4   + 255)/256, 256>>>(w2,    w2p,  D4, Dd*D4/4);

    // 1) LN1 -> xnA (A-form), xnB (B-form)
    ln1_kernel<<<ROWS/8, 256>>>(x, n1w, n1b, xnA, xnB);

    // 2) QKV = xn @ in_w^T + in_b   grid (1536/256, 64)
    gemm_bf16<256, false, 0><<<dim3(6, 64), 256, GSMEM_W256>>>(
        xnA, wIN, in_b, nullptr, qkv, 3*Dd, 3*Dd, 0, 0, 0);

    // 3) flash attention (mma.sync) -> ctxA
    attn_mma_kernel<<<dim3(Tt/64, Hh, Bb), 128, ATTN_SMEM>>>(qkv, ctxA);

    // 4) std_out = ctx @ out_w^T + out_b   grid (4, 64)
    gemm_bf16<128, false, 0><<<dim3(4, 64), 256, GSMEM_W128>>>(
        ctxA, wOUT, out_b, nullptr, stdo, Dd, 3*Dd, 0, 0, 0);

    // 5) Gaussian kernel weights
    kw_kernel<<<ROWS, 256>>>(posv, posh, kwA, ksum);

    // 6) ko = kw @ xn (batched)   grid (4, 8, 8)
    gemm_bf16<128, true, 0><<<dim3(4, 8, Bb), 256, GSMEM_R128>>>(
        kwA, xnB, nullptr, nullptr, ko, Dd, 3*Tt,
        (long)Tt*3*Tt, (long)3*Tt*Dd, (long)Tt*Dd);

    // 7) combine + LN2
    combine_ln2_kernel<<<ROWS/8, 256>>>(x, stdo, ko, ksum, gate, n2w, n2b, x1, xn2A);

    // 8) h = gelu(xn2 @ w1^T + b1)   grid (8, 64)
    gemm_bf16<256, false, 1><<<dim3(8, 64), 256, GSMEM_W256>>>(
        xn2A, w1p, b1, nullptr, hA, D4, 3*Dd, 0, 0, 0);

    // 9) out = x1 + h @ w2^T + b2    grid (4, 64)
    gemm_bf16<128, false, 2><<<dim3(4, 64), 256, GSMEM_W128>>>(
        hA, w2p, b2, x1, out, Dd, 3*D4, 0, 0, 0);
}

// round 8
// speedup vs baseline: 1.7476x; 1.0087x over previous
#include <cuda_runtime.h>
#include <cuda_bf16.h>
#include <cuda_fp16.h>
#include <mma.h>
#include <math.h>
#include <stdint.h>

using namespace nvcuda;

#define Bb 8
#define Tt 1024
#define Dd 512
#define Hh 8
#define HD 64
#define D4 2048
#define ROWS (Bb*Tt)

// ---------------- scratch (device globals) ----------------
__device__ __half g_xnA [ROWS*2*Dd];      // LN1 out, A-form [hi|lo] fp16
__device__ float  g_qkv [ROWS*3*Dd];
__device__ __half g_ctxA[ROWS*2*Dd];      // attn out, A-form fp16
__device__ float  g_stdo[ROWS*Dd];
__device__ float  g_G   [Bb*64*64*512];   // position-grid sums / later O
__device__ float  g_T1  [Bb*64*64*512];
__device__ float  g_cnt [Bb*4096];
__device__ float  g_dcnt[Bb*4096];        // inverse denominators
__device__ float  g_Av  [4096];           // 64x64 Gaussian matrix
__device__ float  g_x1  [ROWS*Dd];
__device__ __half g_xn2A[ROWS*2*Dd];
__device__ __half g_hA  [ROWS*2*D4];
__device__ __half g_wIN [3*Dd*2*Dd];      // weights, B-form [hi|hi] fp16
__device__ __half g_wOUT[Dd*2*Dd];
__device__ __half g_w1  [D4*2*Dd];
__device__ __half g_w2  [Dd*2*D4];

// ---------------- helpers ----------------
__device__ __forceinline__ uint32_t smem_u32(const void* p) {
    uint32_t a;
    asm("{ .reg .u64 t; cvta.to.shared.u64 t, %1; cvt.u32.u64 %0, t; }" : "=r"(a) : "l"(p));
    return a;
}
__device__ __forceinline__ void cp16(uint32_t sdst, const void* gsrc) {
    asm volatile("cp.async.cg.shared.global [%0], [%1], 16;" :: "r"(sdst), "l"(gsrc));
}
__device__ __forceinline__ void cp_commit() {
    asm volatile("cp.async.commit_group;" ::: "memory");
}
template<int N>
__device__ __forceinline__ void cp_wait() {
    asm volatile("cp.async.wait_group %0;" :: "n"(N) : "memory");
}
// fp16 split
__device__ __forceinline__ void split_h(float v, __half& h, __half& l) {
    h = __float2half_rn(v);
    l = __float2half_rn(v - __half2float(h));
}
__device__ __forceinline__ void split4_h(float4 v, uint2& H, uint2& L) {
    __half hx,lx,hy,ly,hz,lz,hw,lw;
    split_h(v.x,hx,lx); split_h(v.y,hy,ly);
    split_h(v.z,hz,lz); split_h(v.w,hw,lw);
    __half2 h01 = __halves2half2(hx,hy), h23 = __halves2half2(hz,hw);
    __half2 l01 = __halves2half2(lx,ly), l23 = __halves2half2(lz,lw);
    H.x = *reinterpret_cast<unsigned*>(&h01); H.y = *reinterpret_cast<unsigned*>(&h23);
    L.x = *reinterpret_cast<unsigned*>(&l01); L.y = *reinterpret_cast<unsigned*>(&l23);
}
// bf16 split (attention internals)
__device__ __forceinline__ void split_bf(float v, __nv_bfloat16& h, __nv_bfloat16& l) {
    h = __float2bfloat16(v);
    l = __float2bfloat16(v - __bfloat162float(h));
}
__device__ __forceinline__ void split4_u2(float4 v, uint2& H, uint2& L) {
    __nv_bfloat16 hx,lx,hy,ly,hz,lz,hw,lw;
    split_bf(v.x,hx,lx); split_bf(v.y,hy,ly);
    split_bf(v.z,hz,lz); split_bf(v.w,hw,lw);
    __nv_bfloat162 h01 = __halves2bfloat162(hx,hy);
    __nv_bfloat162 h23 = __halves2bfloat162(hz,hw);
    __nv_bfloat162 l01 = __halves2bfloat162(lx,ly);
    __nv_bfloat162 l23 = __halves2bfloat162(lz,lw);
    H.x = *reinterpret_cast<unsigned*>(&h01); H.y = *reinterpret_cast<unsigned*>(&h23);
    L.x = *reinterpret_cast<unsigned*>(&l01); L.y = *reinterpret_cast<unsigned*>(&l23);
}
__device__ __forceinline__ float gelu_exact(float v) {
    return 0.5f * v * (1.0f + erff(v * 0.7071067811865476f));
}

// ---------------- mma / ldmatrix primitives (attention, bf16) ----------------
__device__ __forceinline__ void ldsm_x4(uint32_t& r0, uint32_t& r1, uint32_t& r2, uint32_t& r3, uint32_t a) {
    asm volatile("ldmatrix.sync.aligned.m8n8.x4.shared.b16 {%0,%1,%2,%3}, [%4];"
                 : "=r"(r0),"=r"(r1),"=r"(r2),"=r"(r3) : "r"(a));
}
__device__ __forceinline__ void ldsm_x2(uint32_t& r0, uint32_t& r1, uint32_t a) {
    asm volatile("ldmatrix.sync.aligned.m8n8.x2.shared.b16 {%0,%1}, [%2];"
                 : "=r"(r0),"=r"(r1) : "r"(a));
}
__device__ __forceinline__ void ldsm_x2t(uint32_t& r0, uint32_t& r1, uint32_t a) {
    asm volatile("ldmatrix.sync.aligned.m8n8.x2.trans.shared.b16 {%0,%1}, [%2];"
                 : "=r"(r0),"=r"(r1) : "r"(a));
}
__device__ __forceinline__ void mma16816(float* c, uint32_t a0, uint32_t a1, uint32_t a2, uint32_t a3,
                                         uint32_t b0, uint32_t b1) {
    asm volatile("mma.sync.aligned.m16n8k16.row.col.f32.bf16.bf16.f32 "
                 "{%0,%1,%2,%3}, {%4,%5,%6,%7}, {%8,%9}, {%0,%1,%2,%3};"
                 : "+f"(c[0]),"+f"(c[1]),"+f"(c[2]),"+f"(c[3])
                 : "r"(a0),"r"(a1),"r"(a2),"r"(a3),"r"(b0),"r"(b1));
}

// ---------------- zero kernel ----------------
__global__ __launch_bounds__(256) void zero_kernel(float* __restrict__ p, int n4) {
    int i = blockIdx.x * 256 + threadIdx.x;
    if (i < n4) *(float4*)&p[i*4] = make_float4(0.f,0.f,0.f,0.f);
}

// ---------------- weight conversion: W[N][K] -> W'[N][2K] = [hi|hi] fp16 ----------------
__global__ __launch_bounds__(256) void conv_w_kernel(
    const float* __restrict__ W, __half* __restrict__ Wp, int K, int total4)
{
    int idx = blockIdx.x * 256 + threadIdx.x;
    if (idx >= total4) return;
    long e = (long)idx * 4;
    int r = (int)(e / K), c = (int)(e % K);
    float4 v = *(const float4*)&W[(long)r * K + c];
    uint2 H, L; split4_h(v, H, L);
    __half* row = Wp + (long)r * 2 * K;
    *(uint2*)&row[c]     = H;
    *(uint2*)&row[K + c] = H;
}

// ================ fp16 2-term split GEMM ================
#define GSTAGES 3
#define ASTR 40
#define ASZ   (128*ASTR*2)          // 10240 B

template<int NT, int EPI>
__global__ __launch_bounds__(256) void gemm_fp16(
    const __half* __restrict__ A, const __half* __restrict__ B,
    const float* __restrict__ bias, const float* __restrict__ res,
    void* __restrict__ Cout, int N, int Kp)
{
    constexpr int NFR = NT/64;
    constexpr int BSZ = NT*ASTR*2;

    extern __shared__ __align__(128) char sm[];
    char* Abase = sm;
    char* Bbase = sm + GSTAGES * ASZ;

    const int tid = threadIdx.x;
    int w = tid >> 5, lane = tid & 31, wm = w >> 2, wn = w & 3;
    int m0 = blockIdx.y << 7, n0 = blockIdx.x * NT;

    int ar = tid >> 2, ac = (tid & 3) * 8;
    const __half* Ag = A + (long)(m0 + ar) * Kp + ac;
    const __half* Bg = B + (long)(n0 + ar) * Kp + ac;
    uint32_t Asw = smem_u32(Abase) + (uint32_t)(ar * (ASTR*2) + ac * 2);
    uint32_t Bsw = smem_u32(Bbase) + (uint32_t)(ar * (ASTR*2) + ac * 2);

    int nk = Kp >> 5;

#define GISSUE(kt) do { \
        if ((kt) < nk) { \
            int st_ = (kt) % GSTAGES; \
            long ko_ = (long)(kt) * 32; \
            uint32_t ad = Asw + (uint32_t)st_ * ASZ; \
            cp16(ad,                Ag + ko_); \
            cp16(ad + 64*(ASTR*2),  Ag + ko_ + (long)64*Kp); \
            uint32_t bd = Bsw + (uint32_t)st_ * BSZ; \
            _Pragma("unroll") \
            for (int i_ = 0; i_ < NT/64; i_++) \
                cp16(bd + i_*64*(ASTR*2), Bg + ko_ + (long)(i_*64)*Kp); \
        } \
        cp_commit(); \
    } while (0)

    wmma::fragment<wmma::accumulator, 16, 16, 16, float> acc[4][NFR];
#pragma unroll
    for (int i = 0; i < 4; i++)
#pragma unroll
        for (int j = 0; j < NFR; j++) wmma::fill_fragment(acc[i][j], 0.f);

#pragma unroll
    for (int i = 0; i < GSTAGES - 1; i++) GISSUE(i);

    for (int kt = 0; kt < nk; kt++) {
        cp_wait<GSTAGES - 2>();
        __syncthreads();
        GISSUE(kt + GSTAGES - 1);
        int st = kt % GSTAGES;
        const __half* Asm = (const __half*)(Abase + st * ASZ);
        const __half* Bsm = (const __half*)(Bbase + st * BSZ);
#pragma unroll
        for (int kk = 0; kk < 2; kk++) {
            wmma::fragment<wmma::matrix_a, 16, 16, 16, __half, wmma::row_major> af[4];
#pragma unroll
            for (int i = 0; i < 4; i++)
                wmma::load_matrix_sync(af[i], Asm + (wm*64 + i*16)*ASTR + kk*16, ASTR);
#pragma unroll
            for (int jh = 0; jh < NFR/2; jh++) {
                wmma::fragment<wmma::matrix_b, 16, 16, 16, __half, wmma::col_major> bf[2];
#pragma unroll
                for (int j = 0; j < 2; j++)
                    wmma::load_matrix_sync(bf[j], Bsm + (wn*(NT/4) + jh*32 + j*16)*ASTR + kk*16, ASTR);
#pragma unroll
                for (int i = 0; i < 4; i++)
#pragma unroll
                    for (int j = 0; j < 2; j++)
                        wmma::mma_sync(acc[i][jh*2+j], af[i], bf[j], acc[i][jh*2+j]);
            }
        }
        __syncthreads();
    }
#undef GISSUE

    float* EP = (float*)sm + w * 256;
    int r = lane >> 1, c0 = (lane & 1) * 8;
    long ldc = (EPI == 1) ? (long)2 * N : (long)N;
#pragma unroll
    for (int i = 0; i < 4; i++) {
#pragma unroll
        for (int j = 0; j < NFR; j++) {
            wmma::store_matrix_sync(EP, acc[i][j], 16, wmma::mem_row_major);
            __syncwarp();
            long grow = m0 + wm*64 + i*16 + r;
            int  gcol = n0 + wn*(NT/4) + j*16 + c0;
            float4 v0 = *(float4*)&EP[r*16 + c0];
            float4 v1 = *(float4*)&EP[r*16 + c0 + 4];
            if (bias) {
                float4 b0 = *(const float4*)&bias[gcol];
                float4 b1 = *(const float4*)&bias[gcol + 4];
                v0.x += b0.x; v0.y += b0.y; v0.z += b0.z; v0.w += b0.w;
                v1.x += b1.x; v1.y += b1.y; v1.z += b1.z; v1.w += b1.w;
            }
            if (EPI == 1) {
                v0.x = gelu_exact(v0.x); v0.y = gelu_exact(v0.y);
                v0.z = gelu_exact(v0.z); v0.w = gelu_exact(v0.w);
                v1.x = gelu_exact(v1.x); v1.y = gelu_exact(v1.y);
                v1.z = gelu_exact(v1.z); v1.w = gelu_exact(v1.w);
                uint2 H0,L0,H1,L1;
                split4_h(v0,H0,L0); split4_h(v1,H1,L1);
                __half* Crow = (__half*)Cout + grow * ldc;
                uint4 Hq = make_uint4(H0.x,H0.y,H1.x,H1.y);
                uint4 Lq = make_uint4(L0.x,L0.y,L1.x,L1.y);
                *(uint4*)&Crow[gcol]     = Hq;
                *(uint4*)&Crow[N + gcol] = Lq;
            } else {
                float* C = (float*)Cout;
                if (EPI == 2) {
                    float4 r0 = *(const float4*)&res[grow*N + gcol];
                    float4 r1 = *(const float4*)&res[grow*N + gcol + 4];
                    v0.x += r0.x; v0.y += r0.y; v0.z += r0.z; v0.w += r0.w;
                    v1.x += r1.x; v1.y += r1.y; v1.z += r1.z; v1.w += r1.w;
                }
                *(float4*)&C[grow*ldc + gcol]     = v0;
                *(float4*)&C[grow*ldc + gcol + 4] = v1;
            }
            __syncwarp();
        }
    }
}

#define GSMEM_W256 (GSTAGES*(ASZ + 256*ASTR*2))   // 92160
#define GSMEM_W128 (GSTAGES*(ASZ + 128*ASTR*2))   // 61440

// ---------------- LN1: fp32 in -> A-form fp16 [hi|lo] ----------------
__global__ __launch_bounds__(256) void ln1_kernel(
    const float* __restrict__ x, const float* __restrict__ w,
    const float* __restrict__ b, __half* __restrict__ xnA)
{
    int warp = threadIdx.x >> 5, lane = threadIdx.x & 31;
    long row = (long)blockIdx.x * 8 + warp;
    const float* xr = x + row * Dd;
    float4 v[4];
    float s = 0.f, sq = 0.f;
#pragma unroll
    for (int i = 0; i < 4; i++) {
        v[i] = *(const float4*)&xr[lane*4 + i*128];
        s  += v[i].x + v[i].y + v[i].z + v[i].w;
        sq += v[i].x*v[i].x + v[i].y*v[i].y + v[i].z*v[i].z + v[i].w*v[i].w;
    }
#pragma unroll
    for (int o = 16; o; o >>= 1) {
        s  += __shfl_xor_sync(0xffffffffu, s,  o);
        sq += __shfl_xor_sync(0xffffffffu, sq, o);
    }
    float mean = s * (1.0f/512.0f);
    float var  = sq * (1.0f/512.0f) - mean*mean;
    float rr   = rsqrtf(var + 1e-5f);
    __half* arow = xnA + row * (2*Dd);
#pragma unroll
    for (int i = 0; i < 4; i++) {
        int d = lane*4 + i*128;
        float4 wv = *(const float4*)&w[d];
        float4 bv = *(const float4*)&b[d];
        float4 o4;
        o4.x = (v[i].x - mean)*rr*wv.x + bv.x;
        o4.y = (v[i].y - mean)*rr*wv.y + bv.y;
        o4.z = (v[i].z - mean)*rr*wv.z + bv.z;
        o4.w = (v[i].w - mean)*rr*wv.w + bv.w;
        uint2 H, L; split4_h(o4, H, L);
        *(uint2*)&arow[d]      = H;
        *(uint2*)&arow[Dd + d] = L;
    }
}

// ---------------- flash attention on mma.sync (bf16 internals, fp16 A-form out) ----------------
#define QSTR 200
#define VSTR 72
#define ATTN_SMEM ((2*64*QSTR + 64*VSTR)*2)

__global__ __launch_bounds__(128) void attn_mma_kernel(
    const float* __restrict__ qkv, __half* __restrict__ ctxA)
{
    extern __shared__ __nv_bfloat16 smh[];
    __nv_bfloat16* Qs = smh;
    __nv_bfloat16* Ks = smh + 64*QSTR;
    __nv_bfloat16* Vs = smh + 2*64*QSTR;

    int b = blockIdx.z, h = blockIdx.y, qt = blockIdx.x;
    int tid = threadIdx.x, wq = tid >> 5, lane = tid & 31;
    const int LDR = 3*Dd;
    const float* base = qkv + (long)b * Tt * LDR;

    {
        int row = tid >> 1, cb = (tid & 1) * 32;
        const float* qp = base + (long)(qt*64 + row) * LDR + h*HD + cb;
#pragma unroll
        for (int i = 0; i < 8; i++) {
            float4 v = *(const float4*)(qp + i*4);
            v.x *= 0.125f; v.y *= 0.125f; v.z *= 0.125f; v.w *= 0.125f;
            uint2 H, L; split4_u2(v, H, L);
            int c = cb + i*4;
            *(uint2*)&Qs[row*QSTR + c]       = H;
            *(uint2*)&Qs[row*QSTR + 64 + c]  = L;
            *(uint2*)&Qs[row*QSTR + 128 + c] = H;
        }
    }

    float cf[8][4];
#pragma unroll
    for (int j = 0; j < 8; j++) { cf[j][0]=0.f; cf[j][1]=0.f; cf[j][2]=0.f; cf[j][3]=0.f; }
    float m0 = -1e30f, m1 = -1e30f, l0 = 0.f, l1 = 0.f;

    uint32_t qaddr = smem_u32(&Qs[(16*wq + (lane & 15))*QSTR + 8*(lane >> 4)]);

    for (int kt = 0; kt < 16; kt++) {
        __syncthreads();
        {
            int row = tid >> 1, cb = (tid & 1) * 32;
            const float* kp = base + (long)(kt*64 + row) * LDR + Dd   + h*HD + cb;
            const float* vp = base + (long)(kt*64 + row) * LDR + 2*Dd + h*HD + cb;
#pragma unroll
            for (int i = 0; i < 8; i++) {
                float4 v = *(const float4*)(kp + i*4);
                uint2 H, L; split4_u2(v, H, L);
                int c = cb + i*4;
                *(uint2*)&Ks[row*QSTR + c]       = H;
                *(uint2*)&Ks[row*QSTR + 64 + c]  = H;
                *(uint2*)&Ks[row*QSTR + 128 + c] = L;
                float4 vv = *(const float4*)(vp + i*4);
                __nv_bfloat162 p0 = __floats2bfloat162_rn(vv.x, vv.y);
                __nv_bfloat162 p1 = __floats2bfloat162_rn(vv.z, vv.w);
                uint2 P; P.x = *(unsigned*)&p0; P.y = *(unsigned*)&p1;
                *(uint2*)&Vs[row*VSTR + c] = P;
            }
        }
        __syncthreads();

        float sf[8][4] = {};
#pragma unroll
        for (int kc = 0; kc < 12; kc++) {
            uint32_t a0, a1, a2, a3;
            ldsm_x4(a0, a1, a2, a3, qaddr + kc*32);
#pragma unroll
            for (int n8 = 0; n8 < 8; n8++) {
                uint32_t b0, b1;
                uint32_t ka = smem_u32(&Ks[(8*n8 + (lane & 7))*QSTR + 16*kc + 8*((lane >> 3) & 1)]);
                ldsm_x2(b0, b1, ka);
                mma16816(sf[n8], a0, a1, a2, a3, b0, b1);
            }
        }

        float mt0 = -1e30f, mt1 = -1e30f;
#pragma unroll
        for (int j = 0; j < 8; j++) {
            mt0 = fmaxf(mt0, fmaxf(sf[j][0], sf[j][1]));
            mt1 = fmaxf(mt1, fmaxf(sf[j][2], sf[j][3]));
        }
        mt0 = fmaxf(mt0, __shfl_xor_sync(0xffffffffu, mt0, 1));
        mt0 = fmaxf(mt0, __shfl_xor_sync(0xffffffffu, mt0, 2));
        mt1 = fmaxf(mt1, __shfl_xor_sync(0xffffffffu, mt1, 1));
        mt1 = fmaxf(mt1, __shfl_xor_sync(0xffffffffu, mt1, 2));
        float mn0 = fmaxf(m0, mt0), mn1 = fmaxf(m1, mt1);
        float cr0 = __expf(m0 - mn0), cr1 = __expf(m1 - mn1);
        m0 = mn0; m1 = mn1; l0 *= cr0; l1 *= cr1;
#pragma unroll
        for (int j = 0; j < 8; j++) {
            cf[j][0] *= cr0; cf[j][1] *= cr0; cf[j][2] *= cr1; cf[j][3] *= cr1;
        }

        uint32_t pa[4][4];
#pragma unroll
        for (int jk = 0; jk < 4; jk++) {
            float e00 = __expf(sf[2*jk][0]   - mn0), e01 = __expf(sf[2*jk][1]   - mn0);
            float e10 = __expf(sf[2*jk][2]   - mn1), e11 = __expf(sf[2*jk][3]   - mn1);
            float e20 = __expf(sf[2*jk+1][0] - mn0), e21 = __expf(sf[2*jk+1][1] - mn0);
            float e30 = __expf(sf[2*jk+1][2] - mn1), e31 = __expf(sf[2*jk+1][3] - mn1);
            l0 += e00 + e01 + e20 + e21;
            l1 += e10 + e11 + e30 + e31;
            __nv_bfloat162 t;
            t = __floats2bfloat162_rn(e00, e01); pa[jk][0] = *(unsigned*)&t;
            t = __floats2bfloat162_rn(e10, e11); pa[jk][1] = *(unsigned*)&t;
            t = __floats2bfloat162_rn(e20, e21); pa[jk][2] = *(unsigned*)&t;
            t = __floats2bfloat162_rn(e30, e31); pa[jk][3] = *(unsigned*)&t;
        }

#pragma unroll
        for (int jk = 0; jk < 4; jk++) {
#pragma unroll
            for (int jd = 0; jd < 8; jd++) {
                uint32_t b0, b1;
                uint32_t va = smem_u32(&Vs[(16*jk + (lane & 15))*VSTR + 8*jd]);
                ldsm_x2t(b0, b1, va);
                mma16816(cf[jd], pa[jk][0], pa[jk][1], pa[jk][2], pa[jk][3], b0, b1);
            }
        }
    }

    l0 += __shfl_xor_sync(0xffffffffu, l0, 1);
    l0 += __shfl_xor_sync(0xffffffffu, l0, 2);
    l1 += __shfl_xor_sync(0xffffffffu, l1, 1);
    l1 += __shfl_xor_sync(0xffffffffu, l1, 2);
    float inv0 = 1.0f / l0, inv1 = 1.0f / l1;

    long grow0 = (long)b*Tt + qt*64 + 16*wq + (lane >> 2);
    long grow1 = grow0 + 8;
    int colb = h*HD + 2*(lane & 3);
    __half* cr0p = ctxA + grow0 * (2*Dd);
    __half* cr1p = ctxA + grow1 * (2*Dd);
#pragma unroll
    for (int jd = 0; jd < 8; jd++) {
        int col = colb + 8*jd;
        {
            float v0 = cf[jd][0]*inv0, v1 = cf[jd][1]*inv0;
            __half h0,lo0,h1,lo1; split_h(v0,h0,lo0); split_h(v1,h1,lo1);
            __half2 Hp = __halves2half2(h0,h1), Lp = __halves2half2(lo0,lo1);
            *(unsigned*)&cr0p[col]      = *(unsigned*)&Hp;
            *(unsigned*)&cr0p[Dd + col] = *(unsigned*)&Lp;
        }
        {
            float v0 = cf[jd][2]*inv1, v1 = cf[jd][3]*inv1;
            __half h0,lo0,h1,lo1; split_h(v0,h0,lo0); split_h(v1,h1,lo1);
            __half2 Hp = __halves2half2(h0,h1), Lp = __halves2half2(lo0,lo1);
            *(unsigned*)&cr1p[col]      = *(unsigned*)&Hp;
            *(unsigned*)&cr1p[Dd + col] = *(unsigned*)&Lp;
        }
    }
}

// ---------------- separable Gaussian position attention ----------------
__global__ __launch_bounds__(256) void av_init_kernel(float* __restrict__ Av) {
    int i = blockIdx.x * 256 + threadIdx.x;
    float d = (float)((i >> 6) - (i & 63));
    Av[i] = __expf(-d * d * (1.0f/512.0f));
}

__global__ __launch_bounds__(256) void scatter_kernel(
    const __half* __restrict__ xnA, const int* __restrict__ posv,
    const int* __restrict__ posh, float* __restrict__ G, float* __restrict__ cnt)
{
    int warp = threadIdx.x >> 5, lane = threadIdx.x & 31;
    long row = (long)blockIdx.x * 8 + warp;
    int b = (int)(row >> 10), t = (int)(row & 1023);
    int pv = posv[b*Tt + t], ph = posh[b*Tt + t];
    float* dst = G + (((long)b*64 + pv)*64 + ph) * 512;
    const __half* ar = xnA + row * (2*Dd);
#pragma unroll
    for (int i = 0; i < 16; i++) {
        int d = i*32 + lane;
        float v = __half2float(ar[d]) + __half2float(ar[Dd + d]);
        atomicAdd(&dst[d], v);
    }
    if (lane == 0) atomicAdd(&cnt[((long)b*64 + pv)*64 + ph], 1.0f);
}

// one 64-point Gaussian contraction along a grid axis
__global__ __launch_bounds__(512) void gconv_kernel(
    const float* __restrict__ in, float* __restrict__ out,
    const float* __restrict__ Av, int stride_fix, int stride_c)
{
    __shared__ float AsT[64][64];   // AsT[c'][v] = Av[v][c']
    int fix = blockIdx.x, b = blockIdx.y, tid = threadIdx.x;
    for (int i = tid; i < 4096; i += 512)
        AsT[i & 63][i >> 6] = Av[i];
    __syncthreads();
    const float* ib = in  + (long)b*2097152 + (long)fix*stride_fix + tid;
    float* ob       = out + (long)b*2097152 + (long)fix*stride_fix + tid;
    float acc[64];
#pragma unroll
    for (int v = 0; v < 64; v++) acc[v] = 0.f;
    for (int c = 0; c < 64; c++) {
        float g = ib[(long)c * stride_c];
#pragma unroll
        for (int v4 = 0; v4 < 16; v4++) {
            float4 a4 = *(const float4*)&AsT[c][v4*4];
            acc[v4*4+0] += a4.x*g; acc[v4*4+1] += a4.y*g;
            acc[v4*4+2] += a4.z*g; acc[v4*4+3] += a4.w*g;
        }
    }
#pragma unroll
    for (int v = 0; v < 64; v++) ob[(long)v * stride_c] = acc[v];
}

__global__ __launch_bounds__(1024) void dcnt_kernel(
    const float* __restrict__ cnt, const float* __restrict__ Av,
    float* __restrict__ dcnt)
{
    __shared__ float sc[4096], st[4096];
    int b = blockIdx.x, tid = threadIdx.x;
    for (int i = tid; i < 4096; i += 1024) sc[i] = cnt[(long)b*4096 + i];
    __syncthreads();
    for (int i = tid; i < 4096; i += 1024) {
        int v = i >> 6, hp = i & 63;
        float s = 0.f;
        for (int vp = 0; vp < 64; vp++) s += Av[v*64+vp] * sc[vp*64+hp];
        st[i] = s;
    }
    __syncthreads();
    for (int i = tid; i < 4096; i += 1024) {
        int v = i >> 6, h = i & 63;
        float s = 0.f;
        for (int hp = 0; hp < 64; hp++) s += Av[h*64+hp] * st[v*64+hp];
        dcnt[(long)b*4096 + i] = 1.0f / s;
    }
}

// ---------------- combine (x1 fp32) + LN2 -> A-form fp16 ----------------
__global__ __launch_bounds__(256) void combine_ln2_kernel(
    const float* __restrict__ x, const float* __restrict__ stdo,
    const float* __restrict__ O, const float* __restrict__ dcntInv,
    const int* __restrict__ posv, const int* __restrict__ posh,
    const float* __restrict__ gate,
    const float* __restrict__ w, const float* __restrict__ bb,
    float* __restrict__ x1, __half* __restrict__ xn2A)
{
    int warp = threadIdx.x >> 5, lane = threadIdx.x & 31;
    long row = (long)blockIdx.x * 8 + warp;
    int b = (int)(row >> 10), t = (int)(row & 1023);
    int pv = posv[b*Tt + t], ph = posh[b*Tt + t];
    float g = 1.0f / (1.0f + __expf(-gate[0]));
    float gi = 1.0f - g;
    float inv_ks = dcntInv[((long)b*64 + pv)*64 + ph];
    const float* korow = O + (((long)b*64 + pv)*64 + ph) * 512;
    long base = row * Dd;
    float4 v[4];
    float s = 0.f, sq = 0.f;
#pragma unroll
    for (int i = 0; i < 4; i++) {
        int d = lane*4 + i*128;
        float4 xv = *(const float4*)&x[base + d];
        float4 sv = *(const float4*)&stdo[base + d];
        float4 kv = *(const float4*)&korow[d];
        float4 o4;
        o4.x = xv.x + g*sv.x + gi*kv.x*inv_ks;
        o4.y = xv.y + g*sv.y + gi*kv.y*inv_ks;
        o4.z = xv.z + g*sv.z + gi*kv.z*inv_ks;
        o4.w = xv.w + g*sv.w + gi*kv.w*inv_ks;
        *(float4*)&x1[base + d] = o4;
        v[i] = o4;
        s  += o4.x + o4.y + o4.z + o4.w;
        sq += o4.x*o4.x + o4.y*o4.y + o4.z*o4.z + o4.w*o4.w;
    }
#pragma unroll
    for (int o = 16; o; o >>= 1) {
        s  += __shfl_xor_sync(0xffffffffu, s,  o);
        sq += __shfl_xor_sync(0xffffffffu, sq, o);
    }
    float mean = s * (1.0f/512.0f);
    float var  = sq * (1.0f/512.0f) - mean*mean;
    float rr   = rsqrtf(var + 1e-5f);
    __half* arow = xn2A + row * (2*Dd);
#pragma unroll
    for (int i = 0; i < 4; i++) {
        int d = lane*4 + i*128;
        float4 wv = *(const float4*)&w[d];
        float4 bv = *(const float4*)&bb[d];
        float4 o4;
        o4.x = (v[i].x - mean)*rr*wv.x + bv.x;
        o4.y = (v[i].y - mean)*rr*wv.y + bv.y;
        o4.z = (v[i].z - mean)*rr*wv.z + bv.z;
        o4.w = (v[i].w - mean)*rr*wv.w + bv.w;
        uint2 H, L; split4_h(o4, H, L);
        *(uint2*)&arow[d]      = H;
        *(uint2*)&arow[Dd + d] = L;
    }
}

// ---------------- launch ----------------
extern "C" void kernel_launch(void* const* d_in, const int* in_sizes, int n_in,
                              void* d_out, int out_size)
{
    const float* x      = (const float*)d_in[0];
    const int*   posv   = (const int*)  d_in[1];
    const int*   posh   = (const int*)  d_in[2];
    const float* n1w    = (const float*)d_in[3];
    const float* n1b    = (const float*)d_in[4];
    const float* in_w   = (const float*)d_in[5];
    const float* in_b   = (const float*)d_in[6];
    const float* out_w  = (const float*)d_in[7];
    const float* out_b  = (const float*)d_in[8];
    const float* n2w    = (const float*)d_in[9];
    const float* n2b    = (const float*)d_in[10];
    const float* w1     = (const float*)d_in[11];
    const float* b1     = (const float*)d_in[12];
    const float* w2     = (const float*)d_in[13];
    const float* b2     = (const float*)d_in[14];
    const float* gate   = (const float*)d_in[15];
    float* out = (float*)d_out;

    __half *xnA, *ctxA, *xn2A, *hA, *wIN, *wOUT, *w1p, *w2p;
    float *qkv, *stdo, *G, *T1, *cnt, *dcnt, *Av, *x1;
    cudaGetSymbolAddress((void**)&xnA,  g_xnA);
    cudaGetSymbolAddress((void**)&qkv,  g_qkv);
    cudaGetSymbolAddress((void**)&ctxA, g_ctxA);
    cudaGetSymbolAddress((void**)&stdo, g_stdo);
    cudaGetSymbolAddress((void**)&G,    g_G);
    cudaGetSymbolAddress((void**)&T1,   g_T1);
    cudaGetSymbolAddress((void**)&cnt,  g_cnt);
    cudaGetSymbolAddress((void**)&dcnt, g_dcnt);
    cudaGetSymbolAddress((void**)&Av,   g_Av);
    cudaGetSymbolAddress((void**)&x1,   g_x1);
    cudaGetSymbolAddress((void**)&xn2A, g_xn2A);
    cudaGetSymbolAddress((void**)&hA,   g_hA);
    cudaGetSymbolAddress((void**)&wIN,  g_wIN);
    cudaGetSymbolAddress((void**)&wOUT, g_wOUT);
    cudaGetSymbolAddress((void**)&w1p,  g_w1);
    cudaGetSymbolAddress((void**)&w2p,  g_w2);

    cudaFuncSetAttribute(gemm_fp16<256,0>, cudaFuncAttributeMaxDynamicSharedMemorySize, GSMEM_W256);
    cudaFuncSetAttribute(gemm_fp16<256,1>, cudaFuncAttributeMaxDynamicSharedMemorySize, GSMEM_W256);
    cudaFuncSetAttribute(gemm_fp16<128,0>, cudaFuncAttributeMaxDynamicSharedMemorySize, GSMEM_W128);
    cudaFuncSetAttribute(gemm_fp16<128,2>, cudaFuncAttributeMaxDynamicSharedMemorySize, GSMEM_W128);
    cudaFuncSetAttribute(attn_mma_kernel,  cudaFuncAttributeMaxDynamicSharedMemorySize, ATTN_SMEM);

    // weight conversions (B-form [hi|hi] fp16)
    conv_w_kernel<<<(3*Dd*Dd/4 + 255)/256, 256>>>(in_w,  wIN,  Dd, 3*Dd*Dd/4);
    conv_w_kernel<<<(Dd*Dd/4   + 255)/256, 256>>>(out_w, wOUT, Dd, Dd*Dd/4);
    conv_w_kernel<<<(D4*Dd/4   + 255)/256, 256>>>(w1,    w1p,  Dd, D4*Dd/4);
    conv_w_kernel<<<(Dd*D4/4   + 255)/256, 256>>>(w2,    w2p,  D4, Dd*D4/4);

    // Gaussian prep: Av matrix, zero grid + counts
    av_init_kernel<<<16, 256>>>(Av);
    zero_kernel<<<(Bb*4096*512/4 + 255)/256, 256>>>(G, Bb*4096*512/4);
    zero_kernel<<<(Bb*4096/4 + 255)/256, 256>>>(cnt, Bb*4096/4);

    // 1) LN1 -> xnA [hi|lo]
    ln1_kernel<<<ROWS/8, 256>>>(x, n1w, n1b, xnA);

    // 2) QKV = xn @ in_w^T + in_b   (Kp=1024)
    gemm_fp16<256, 0><<<dim3(6, 64), 256, GSMEM_W256>>>(
        xnA, wIN, in_b, nullptr, qkv, 3*Dd, 2*Dd);

    // 3) flash attention -> ctxA
    attn_mma_kernel<<<dim3(Tt/64, Hh, Bb), 128, ATTN_SMEM>>>(qkv, ctxA);

    // 4) std_out = ctx @ out_w^T + out_b
    gemm_fp16<128, 0><<<dim3(4, 64), 256, GSMEM_W128>>>(
        ctxA, wOUT, out_b, nullptr, stdo, Dd, 2*Dd);

    // 5) separable Gaussian position attention
    scatter_kernel<<<ROWS/8, 256>>>(xnA, posv, posh, G, cnt);
    gconv_kernel<<<dim3(64, Bb), 512>>>(G, T1, Av, 512, 64*512);   // contract v'
    gconv_kernel<<<dim3(64, Bb), 512>>>(T1, G, Av, 64*512, 512);   // contract h' (out in G)
    dcnt_kernel<<<Bb, 1024>>>(cnt, Av, dcnt);

    // 6) combine + LN2 (gathers O = G at token positions)
    combine_ln2_kernel<<<ROWS/8, 256>>>(
        x, stdo, G, dcnt, posv, posh, gate, n2w, n2b, x1, xn2A);

    // 7) h = gelu(xn2 @ w1^T + b1) -> hA [hi|lo]
    gemm_fp16<256, 1><<<dim3(8, 64), 256, GSMEM_W256>>>(
        xn2A, w1p, b1, nullptr, hA, D4, 2*Dd);

    // 8) out = x1 + h @ w2^T + b2   (Kp=4096)
    gemm_fp16<128, 2><<<dim3(4, 64), 256, GSMEM_W128>>>(
        hA, w2p, b2, x1, out, Dd, 2*D4);
}

// round 9
// speedup vs baseline: 1.8217x; 1.0424x over previous
#include <cuda_runtime.h>
#include <cuda_bf16.h>
#include <cuda_fp16.h>
#include <mma.h>
#include <math.h>
#include <stdint.h>

using namespace nvcuda;

#define Bb 8
#define Tt 1024
#define Dd 512
#define Hh 8
#define HD 64
#define D4 2048
#define ROWS (Bb*Tt)

// ---------------- scratch (device globals) ----------------
__device__ __half         g_xnA [ROWS*2*Dd];      // LN1 out, A-form [hi|lo] fp16
__device__ __nv_bfloat16  g_Qb  [Bb*Hh*Tt*192];   // Q split triple [hi|lo|hi], pre-scaled
__device__ __nv_bfloat16  g_Kb  [Bb*Hh*Tt*192];   // K split triple [hi|hi|lo]
__device__ __nv_bfloat16  g_Vb  [Bb*Hh*Tt*64];    // V bf16
__device__ __half         g_ctxA[ROWS*2*Dd];      // attn out, A-form fp16
__device__ float          g_stdo[ROWS*Dd];
__device__ float          g_G   [Bb*64*64*512];
__device__ float          g_T1  [Bb*64*64*512];
__device__ float          g_cnt [Bb*4096];
__device__ float          g_dcnt[Bb*4096];
__device__ float          g_Av  [4096];
__device__ float          g_x1  [ROWS*Dd];
__device__ __half         g_xn2A[ROWS*2*Dd];
__device__ __half         g_hA  [ROWS*2*D4];
__device__ __half         g_wIN [3*Dd*2*Dd];
__device__ __half         g_wOUT[Dd*2*Dd];
__device__ __half         g_w1  [D4*2*Dd];
__device__ __half         g_w2  [Dd*2*D4];

// ---------------- helpers ----------------
__device__ __forceinline__ uint32_t smem_u32(const void* p) {
    uint32_t a;
    asm("{ .reg .u64 t; cvta.to.shared.u64 t, %1; cvt.u32.u64 %0, t; }" : "=r"(a) : "l"(p));
    return a;
}
__device__ __forceinline__ void cp16(uint32_t sdst, const void* gsrc) {
    asm volatile("cp.async.cg.shared.global [%0], [%1], 16;" :: "r"(sdst), "l"(gsrc));
}
__device__ __forceinline__ void cp_commit() {
    asm volatile("cp.async.commit_group;" ::: "memory");
}
template<int N>
__device__ __forceinline__ void cp_wait() {
    asm volatile("cp.async.wait_group %0;" :: "n"(N) : "memory");
}
__device__ __forceinline__ void split_h(float v, __half& h, __half& l) {
    h = __float2half_rn(v);
    l = __float2half_rn(v - __half2float(h));
}
__device__ __forceinline__ void split4_h(float4 v, uint2& H, uint2& L) {
    __half hx,lx,hy,ly,hz,lz,hw,lw;
    split_h(v.x,hx,lx); split_h(v.y,hy,ly);
    split_h(v.z,hz,lz); split_h(v.w,hw,lw);
    __half2 h01 = __halves2half2(hx,hy), h23 = __halves2half2(hz,hw);
    __half2 l01 = __halves2half2(lx,ly), l23 = __halves2half2(lz,lw);
    H.x = *reinterpret_cast<unsigned*>(&h01); H.y = *reinterpret_cast<unsigned*>(&h23);
    L.x = *reinterpret_cast<unsigned*>(&l01); L.y = *reinterpret_cast<unsigned*>(&l23);
}
__device__ __forceinline__ void split_bf(float v, __nv_bfloat16& h, __nv_bfloat16& l) {
    h = __float2bfloat16(v);
    l = __float2bfloat16(v - __bfloat162float(h));
}
__device__ __forceinline__ void split4_u2(float4 v, uint2& H, uint2& L) {
    __nv_bfloat16 hx,lx,hy,ly,hz,lz,hw,lw;
    split_bf(v.x,hx,lx); split_bf(v.y,hy,ly);
    split_bf(v.z,hz,lz); split_bf(v.w,hw,lw);
    __nv_bfloat162 h01 = __halves2bfloat162(hx,hy);
    __nv_bfloat162 h23 = __halves2bfloat162(hz,hw);
    __nv_bfloat162 l01 = __halves2bfloat162(lx,ly);
    __nv_bfloat162 l23 = __halves2bfloat162(lz,lw);
    H.x = *reinterpret_cast<unsigned*>(&h01); H.y = *reinterpret_cast<unsigned*>(&h23);
    L.x = *reinterpret_cast<unsigned*>(&l01); L.y = *reinterpret_cast<unsigned*>(&l23);
}
__device__ __forceinline__ float gelu_exact(float v) {
    return 0.5f * v * (1.0f + erff(v * 0.7071067811865476f));
}

// ---------------- mma / ldmatrix primitives ----------------
__device__ __forceinline__ void ldsm_x4(uint32_t& r0, uint32_t& r1, uint32_t& r2, uint32_t& r3, uint32_t a) {
    asm volatile("ldmatrix.sync.aligned.m8n8.x4.shared.b16 {%0,%1,%2,%3}, [%4];"
                 : "=r"(r0),"=r"(r1),"=r"(r2),"=r"(r3) : "r"(a));
}
__device__ __forceinline__ void ldsm_x2(uint32_t& r0, uint32_t& r1, uint32_t a) {
    asm volatile("ldmatrix.sync.aligned.m8n8.x2.shared.b16 {%0,%1}, [%2];"
                 : "=r"(r0),"=r"(r1) : "r"(a));
}
__device__ __forceinline__ void ldsm_x2t(uint32_t& r0, uint32_t& r1, uint32_t a) {
    asm volatile("ldmatrix.sync.aligned.m8n8.x2.trans.shared.b16 {%0,%1}, [%2];"
                 : "=r"(r0),"=r"(r1) : "r"(a));
}
__device__ __forceinline__ void mma16816(float* c, uint32_t a0, uint32_t a1, uint32_t a2, uint32_t a3,
                                         uint32_t b0, uint32_t b1) {
    asm volatile("mma.sync.aligned.m16n8k16.row.col.f32.bf16.bf16.f32 "
                 "{%0,%1,%2,%3}, {%4,%5,%6,%7}, {%8,%9}, {%0,%1,%2,%3};"
                 : "+f"(c[0]),"+f"(c[1]),"+f"(c[2]),"+f"(c[3])
                 : "r"(a0),"r"(a1),"r"(a2),"r"(a3),"r"(b0),"r"(b1));
}

// ---------------- zero kernel ----------------
__global__ __launch_bounds__(256) void zero_kernel(float* __restrict__ p, int n4) {
    int i = blockIdx.x * 256 + threadIdx.x;
    if (i < n4) *(float4*)&p[i*4] = make_float4(0.f,0.f,0.f,0.f);
}

// ---------------- weight conversion ----------------
__global__ __launch_bounds__(256) void conv_w_kernel(
    const float* __restrict__ W, __half* __restrict__ Wp, int K, int total4)
{
    int idx = blockIdx.x * 256 + threadIdx.x;
    if (idx >= total4) return;
    long e = (long)idx * 4;
    int r = (int)(e / K), c = (int)(e % K);
    float4 v = *(const float4*)&W[(long)r * K + c];
    uint2 H, L; split4_h(v, H, L);
    __half* row = Wp + (long)r * 2 * K;
    *(uint2*)&row[c]     = H;
    *(uint2*)&row[K + c] = H;
}

// ================ fp16 2-term split GEMM ================
// EPI: 0 fp32+bias, 1 bias+gelu->fp16 A-form, 2 fp32+bias+residual,
//      3 QKV writer -> split bf16 attention buffers
#define GSTAGES 3
#define ASTR 40
#define ASZ   (128*ASTR*2)

template<int NT, int EPI>
__global__ __launch_bounds__(256) void gemm_fp16(
    const __half* __restrict__ A, const __half* __restrict__ B,
    const float* __restrict__ bias, const float* __restrict__ res,
    void* __restrict__ Cout, void* __restrict__ aux1, void* __restrict__ aux2,
    int N, int Kp)
{
    constexpr int NFR = NT/64;
    constexpr int BSZ = NT*ASTR*2;

    extern __shared__ __align__(128) char sm[];
    char* Abase = sm;
    char* Bbase = sm + GSTAGES * ASZ;

    const int tid = threadIdx.x;
    int w = tid >> 5, lane = tid & 31, wm = w >> 2, wn = w & 3;
    int m0 = blockIdx.y << 7, n0 = blockIdx.x * NT;

    int ar = tid >> 2, ac = (tid & 3) * 8;
    const __half* Ag = A + (long)(m0 + ar) * Kp + ac;
    const __half* Bg = B + (long)(n0 + ar) * Kp + ac;
    uint32_t Asw = smem_u32(Abase) + (uint32_t)(ar * (ASTR*2) + ac * 2);
    uint32_t Bsw = smem_u32(Bbase) + (uint32_t)(ar * (ASTR*2) + ac * 2);

    int nk = Kp >> 5;

#define GISSUE(kt) do { \
        if ((kt) < nk) { \
            int st_ = (kt) % GSTAGES; \
            long ko_ = (long)(kt) * 32; \
            uint32_t ad = Asw + (uint32_t)st_ * ASZ; \
            cp16(ad,                Ag + ko_); \
            cp16(ad + 64*(ASTR*2),  Ag + ko_ + (long)64*Kp); \
            uint32_t bd = Bsw + (uint32_t)st_ * BSZ; \
            _Pragma("unroll") \
            for (int i_ = 0; i_ < NT/64; i_++) \
                cp16(bd + i_*64*(ASTR*2), Bg + ko_ + (long)(i_*64)*Kp); \
        } \
        cp_commit(); \
    } while (0)

    wmma::fragment<wmma::accumulator, 16, 16, 16, float> acc[4][NFR];
#pragma unroll
    for (int i = 0; i < 4; i++)
#pragma unroll
        for (int j = 0; j < NFR; j++) wmma::fill_fragment(acc[i][j], 0.f);

#pragma unroll
    for (int i = 0; i < GSTAGES - 1; i++) GISSUE(i);

    for (int kt = 0; kt < nk; kt++) {
        cp_wait<GSTAGES - 2>();
        __syncthreads();
        GISSUE(kt + GSTAGES - 1);
        int st = kt % GSTAGES;
        const __half* Asm = (const __half*)(Abase + st * ASZ);
        const __half* Bsm = (const __half*)(Bbase + st * BSZ);
#pragma unroll
        for (int kk = 0; kk < 2; kk++) {
            wmma::fragment<wmma::matrix_a, 16, 16, 16, __half, wmma::row_major> af[4];
#pragma unroll
            for (int i = 0; i < 4; i++)
                wmma::load_matrix_sync(af[i], Asm + (wm*64 + i*16)*ASTR + kk*16, ASTR);
#pragma unroll
            for (int jh = 0; jh < NFR/2; jh++) {
                wmma::fragment<wmma::matrix_b, 16, 16, 16, __half, wmma::col_major> bf[2];
#pragma unroll
                for (int j = 0; j < 2; j++)
                    wmma::load_matrix_sync(bf[j], Bsm + (wn*(NT/4) + jh*32 + j*16)*ASTR + kk*16, ASTR);
#pragma unroll
                for (int i = 0; i < 4; i++)
#pragma unroll
                    for (int j = 0; j < 2; j++)
                        wmma::mma_sync(acc[i][jh*2+j], af[i], bf[j], acc[i][jh*2+j]);
            }
        }
        __syncthreads();
    }
#undef GISSUE

    float* EP = (float*)sm + w * 256;
    int r = lane >> 1, c0 = (lane & 1) * 8;
    long ldc = (EPI == 1) ? (long)2 * N : (long)N;
#pragma unroll
    for (int i = 0; i < 4; i++) {
#pragma unroll
        for (int j = 0; j < NFR; j++) {
            wmma::store_matrix_sync(EP, acc[i][j], 16, wmma::mem_row_major);
            __syncwarp();
            long grow = m0 + wm*64 + i*16 + r;
            int  gcol = n0 + wn*(NT/4) + j*16 + c0;
            float4 v0 = *(float4*)&EP[r*16 + c0];
            float4 v1 = *(float4*)&EP[r*16 + c0 + 4];
            if (bias) {
                float4 b0 = *(const float4*)&bias[gcol];
                float4 b1 = *(const float4*)&bias[gcol + 4];
                v0.x += b0.x; v0.y += b0.y; v0.z += b0.z; v0.w += b0.w;
                v1.x += b1.x; v1.y += b1.y; v1.z += b1.z; v1.w += b1.w;
            }
            if (EPI == 1) {
                v0.x = gelu_exact(v0.x); v0.y = gelu_exact(v0.y);
                v0.z = gelu_exact(v0.z); v0.w = gelu_exact(v0.w);
                v1.x = gelu_exact(v1.x); v1.y = gelu_exact(v1.y);
                v1.z = gelu_exact(v1.z); v1.w = gelu_exact(v1.w);
                uint2 H0,L0,H1,L1;
                split4_h(v0,H0,L0); split4_h(v1,H1,L1);
                __half* Crow = (__half*)Cout + grow * ldc;
                uint4 Hq = make_uint4(H0.x,H0.y,H1.x,H1.y);
                uint4 Lq = make_uint4(L0.x,L0.y,L1.x,L1.y);
                *(uint4*)&Crow[gcol]     = Hq;
                *(uint4*)&Crow[N + gcol] = Lq;
            } else if (EPI == 3) {
                int bidx = (int)(grow >> 10), t = (int)(grow & 1023);
                int sec = gcol >> 9, cc = gcol & 511, h = cc >> 6, d = cc & 63;
                long hrow = ((long)bidx*Hh + h)*Tt + t;
                if (sec == 0) {
                    v0.x *= 0.125f; v0.y *= 0.125f; v0.z *= 0.125f; v0.w *= 0.125f;
                    v1.x *= 0.125f; v1.y *= 0.125f; v1.z *= 0.125f; v1.w *= 0.125f;
                    uint2 H0,L0,H1,L1; split4_u2(v0,H0,L0); split4_u2(v1,H1,L1);
                    __nv_bfloat16* row = (__nv_bfloat16*)Cout + hrow*192;
                    *(uint2*)&row[d]       = H0; *(uint2*)&row[d+4]     = H1;
                    *(uint2*)&row[64+d]    = L0; *(uint2*)&row[68+d]    = L1;
                    *(uint2*)&row[128+d]   = H0; *(uint2*)&row[132+d]   = H1;
                } else if (sec == 1) {
                    uint2 H0,L0,H1,L1; split4_u2(v0,H0,L0); split4_u2(v1,H1,L1);
                    __nv_bfloat16* row = (__nv_bfloat16*)aux1 + hrow*192;
                    *(uint2*)&row[d]       = H0; *(uint2*)&row[d+4]     = H1;
                    *(uint2*)&row[64+d]    = H0; *(uint2*)&row[68+d]    = H1;
                    *(uint2*)&row[128+d]   = L0; *(uint2*)&row[132+d]   = L1;
                } else {
                    __nv_bfloat162 p0 = __floats2bfloat162_rn(v0.x, v0.y);
                    __nv_bfloat162 p1 = __floats2bfloat162_rn(v0.z, v0.w);
                    __nv_bfloat162 p2 = __floats2bfloat162_rn(v1.x, v1.y);
                    __nv_bfloat162 p3 = __floats2bfloat162_rn(v1.z, v1.w);
                    uint4 P = make_uint4(*(unsigned*)&p0, *(unsigned*)&p1,
                                         *(unsigned*)&p2, *(unsigned*)&p3);
                    *(uint4*)((__nv_bfloat16*)aux2 + hrow*64 + d) = P;
                }
            } else {
                float* C = (float*)Cout;
                if (EPI == 2) {
                    float4 r0 = *(const float4*)&res[grow*N + gcol];
                    float4 r1 = *(const float4*)&res[grow*N + gcol + 4];
                    v0.x += r0.x; v0.y += r0.y; v0.z += r0.z; v0.w += r0.w;
                    v1.x += r1.x; v1.y += r1.y; v1.z += r1.z; v1.w += r1.w;
                }
                *(float4*)&C[grow*ldc + gcol]     = v0;
                *(float4*)&C[grow*ldc + gcol + 4] = v1;
            }
            __syncwarp();
        }
    }
}

#define GSMEM_W256 (GSTAGES*(ASZ + 256*ASTR*2))
#define GSMEM_W128 (GSTAGES*(ASZ + 128*ASTR*2))

// ---------------- LN1 ----------------
__global__ __launch_bounds__(256) void ln1_kernel(
    const float* __restrict__ x, const float* __restrict__ w,
    const float* __restrict__ b, __half* __restrict__ xnA)
{
    int warp = threadIdx.x >> 5, lane = threadIdx.x & 31;
    long row = (long)blockIdx.x * 8 + warp;
    const float* xr = x + row * Dd;
    float4 v[4];
    float s = 0.f, sq = 0.f;
#pragma unroll
    for (int i = 0; i < 4; i++) {
        v[i] = *(const float4*)&xr[lane*4 + i*128];
        s  += v[i].x + v[i].y + v[i].z + v[i].w;
        sq += v[i].x*v[i].x + v[i].y*v[i].y + v[i].z*v[i].z + v[i].w*v[i].w;
    }
#pragma unroll
    for (int o = 16; o; o >>= 1) {
        s  += __shfl_xor_sync(0xffffffffu, s,  o);
        sq += __shfl_xor_sync(0xffffffffu, sq, o);
    }
    float mean = s * (1.0f/512.0f);
    float var  = sq * (1.0f/512.0f) - mean*mean;
    float rr   = rsqrtf(var + 1e-5f);
    __half* arow = xnA + row * (2*Dd);
#pragma unroll
    for (int i = 0; i < 4; i++) {
        int d = lane*4 + i*128;
        float4 wv = *(const float4*)&w[d];
        float4 bv = *(const float4*)&b[d];
        float4 o4;
        o4.x = (v[i].x - mean)*rr*wv.x + bv.x;
        o4.y = (v[i].y - mean)*rr*wv.y + bv.y;
        o4.z = (v[i].z - mean)*rr*wv.z + bv.z;
        o4.w = (v[i].w - mean)*rr*wv.w + bv.w;
        uint2 H, L; split4_h(o4, H, L);
        *(uint2*)&arow[d]      = H;
        *(uint2*)&arow[Dd + d] = L;
    }
}

// ---------------- flash attention: cp.async pipelined, pre-split inputs ----------------
#define QSTR 200
#define VSTR 72
#define KBUF (64*QSTR)
#define VBUF (64*VSTR)
#define ATTN_SMEM ((3*KBUF + 2*VBUF)*2)   // 95232 B

__global__ __launch_bounds__(128) void attn_mma_kernel(
    const __nv_bfloat16* __restrict__ Qb, const __nv_bfloat16* __restrict__ Kb,
    const __nv_bfloat16* __restrict__ Vb, __half* __restrict__ ctxA)
{
    extern __shared__ __nv_bfloat16 smh[];
    __nv_bfloat16* Qs  = smh;
    __nv_bfloat16* Ks0 = smh + KBUF;
    __nv_bfloat16* Vs0 = smh + 3*KBUF;

    int b = blockIdx.z, h = blockIdx.y, qt = blockIdx.x;
    int tid = threadIdx.x, wq = tid >> 5, lane = tid & 31;
    long hbase = ((long)b*Hh + h)*Tt;

    const __nv_bfloat16* Qg = Qb + (hbase + qt*64)*192;
    const __nv_bfloat16* Kg = Kb + hbase*192;
    const __nv_bfloat16* Vg = Vb + hbase*64;

    int lr = tid >> 1, lc = tid & 1;
    uint32_t QsA  = smem_u32(Qs)  + lr*(QSTR*2) + lc*192;
    uint32_t KsA  = smem_u32(Ks0) + lr*(QSTR*2) + lc*192;
    uint32_t VsA  = smem_u32(Vs0) + lr*(VSTR*2) + lc*64;

    // prologue: Q + tile 0
#pragma unroll
    for (int i = 0; i < 12; i++)
        cp16(QsA + i*16, Qg + lr*192 + lc*96 + i*8);
#define ISSUE_KV(kt, buf) do { \
        const __nv_bfloat16* kg_ = Kg + (long)((kt)*64 + lr)*192 + lc*96; \
        uint32_t kd_ = KsA + (buf)*(KBUF*2); \
        _Pragma("unroll") \
        for (int i_ = 0; i_ < 12; i_++) cp16(kd_ + i_*16, kg_ + i_*8); \
        const __nv_bfloat16* vg_ = Vg + (long)((kt)*64 + lr)*64 + lc*32; \
        uint32_t vd_ = VsA + (buf)*(VBUF*2); \
        _Pragma("unroll") \
        for (int i_ = 0; i_ < 4; i_++) cp16(vd_ + i_*16, vg_ + i_*8); \
    } while (0)
    ISSUE_KV(0, 0);
    cp_commit();

    float cf[8][4];
#pragma unroll
    for (int j = 0; j < 8; j++) { cf[j][0]=0.f; cf[j][1]=0.f; cf[j][2]=0.f; cf[j][3]=0.f; }
    float m0 = -1e30f, m1 = -1e30f, l0 = 0.f, l1 = 0.f;

    uint32_t qaddr = smem_u32(&Qs[(16*wq + (lane & 15))*QSTR + 8*(lane >> 4)]);

    for (int kt = 0; kt < 16; kt++) {
        if (kt + 1 < 16) ISSUE_KV(kt + 1, (kt + 1) & 1);
        cp_commit();
        cp_wait<1>();
        __syncthreads();
        const __nv_bfloat16* Kbuf = Ks0 + (kt & 1)*KBUF;
        const __nv_bfloat16* Vbuf = Vs0 + (kt & 1)*VBUF;

        float sf[8][4] = {};
#pragma unroll
        for (int kc = 0; kc < 12; kc++) {
            uint32_t a0, a1, a2, a3;
            ldsm_x4(a0, a1, a2, a3, qaddr + kc*32);
#pragma unroll
            for (int n8 = 0; n8 < 8; n8++) {
                uint32_t b0, b1;
                uint32_t ka = smem_u32(&Kbuf[(8*n8 + (lane & 7))*QSTR + 16*kc + 8*((lane >> 3) & 1)]);
                ldsm_x2(b0, b1, ka);
                mma16816(sf[n8], a0, a1, a2, a3, b0, b1);
            }
        }

        float mt0 = -1e30f, mt1 = -1e30f;
#pragma unroll
        for (int j = 0; j < 8; j++) {
            mt0 = fmaxf(mt0, fmaxf(sf[j][0], sf[j][1]));
            mt1 = fmaxf(mt1, fmaxf(sf[j][2], sf[j][3]));
        }
        mt0 = fmaxf(mt0, __shfl_xor_sync(0xffffffffu, mt0, 1));
        mt0 = fmaxf(mt0, __shfl_xor_sync(0xffffffffu, mt0, 2));
        mt1 = fmaxf(mt1, __shfl_xor_sync(0xffffffffu, mt1, 1));
        mt1 = fmaxf(mt1, __shfl_xor_sync(0xffffffffu, mt1, 2));
        float mn0 = fmaxf(m0, mt0), mn1 = fmaxf(m1, mt1);
        float cr0 = __expf(m0 - mn0), cr1 = __expf(m1 - mn1);
        m0 = mn0; m1 = mn1; l0 *= cr0; l1 *= cr1;
#pragma unroll
        for (int j = 0; j < 8; j++) {
            cf[j][0] *= cr0; cf[j][1] *= cr0; cf[j][2] *= cr1; cf[j][3] *= cr1;
        }

        uint32_t pa[4][4];
#pragma unroll
        for (int jk = 0; jk < 4; jk++) {
            float e00 = __expf(sf[2*jk][0]   - mn0), e01 = __expf(sf[2*jk][1]   - mn0);
            float e10 = __expf(sf[2*jk][2]   - mn1), e11 = __expf(sf[2*jk][3]   - mn1);
            float e20 = __expf(sf[2*jk+1][0] - mn0), e21 = __expf(sf[2*jk+1][1] - mn0);
            float e30 = __expf(sf[2*jk+1][2] - mn1), e31 = __expf(sf[2*jk+1][3] - mn1);
            l0 += e00 + e01 + e20 + e21;
            l1 += e10 + e11 + e30 + e31;
            __nv_bfloat162 t;
            t = __floats2bfloat162_rn(e00, e01); pa[jk][0] = *(unsigned*)&t;
            t = __floats2bfloat162_rn(e10, e11); pa[jk][1] = *(unsigned*)&t;
            t = __floats2bfloat162_rn(e20, e21); pa[jk][2] = *(unsigned*)&t;
            t = __floats2bfloat162_rn(e30, e31); pa[jk][3] = *(unsigned*)&t;
        }

#pragma unroll
        for (int jk = 0; jk < 4; jk++) {
#pragma unroll
            for (int jd = 0; jd < 8; jd++) {
                uint32_t b0, b1;
                uint32_t va = smem_u32(&Vbuf[(16*jk + (lane & 15))*VSTR + 8*jd]);
                ldsm_x2t(b0, b1, va);
                mma16816(cf[jd], pa[jk][0], pa[jk][1], pa[jk][2], pa[jk][3], b0, b1);
            }
        }
        __syncthreads();
    }
#undef ISSUE_KV

    l0 += __shfl_xor_sync(0xffffffffu, l0, 1);
    l0 += __shfl_xor_sync(0xffffffffu, l0, 2);
    l1 += __shfl_xor_sync(0xffffffffu, l1, 1);
    l1 += __shfl_xor_sync(0xffffffffu, l1, 2);
    float inv0 = 1.0f / l0, inv1 = 1.0f / l1;

    long grow0 = (long)b*Tt + qt*64 + 16*wq + (lane >> 2);
    long grow1 = grow0 + 8;
    int colb = h*HD + 2*(lane & 3);
    __half* cr0p = ctxA + grow0 * (2*Dd);
    __half* cr1p = ctxA + grow1 * (2*Dd);
#pragma unroll
    for (int jd = 0; jd < 8; jd++) {
        int col = colb + 8*jd;
        {
            float v0 = cf[jd][0]*inv0, v1 = cf[jd][1]*inv0;
            __half h0,lo0,h1,lo1; split_h(v0,h0,lo0); split_h(v1,h1,lo1);
            __half2 Hp = __halves2half2(h0,h1), Lp = __halves2half2(lo0,lo1);
            *(unsigned*)&cr0p[col]      = *(unsigned*)&Hp;
            *(unsigned*)&cr0p[Dd + col] = *(unsigned*)&Lp;
        }
        {
            float v0 = cf[jd][2]*inv1, v1 = cf[jd][3]*inv1;
            __half h0,lo0,h1,lo1; split_h(v0,h0,lo0); split_h(v1,h1,lo1);
            __half2 Hp = __halves2half2(h0,h1), Lp = __halves2half2(lo0,lo1);
            *(unsigned*)&cr1p[col]      = *(unsigned*)&Hp;
            *(unsigned*)&cr1p[Dd + col] = *(unsigned*)&Lp;
        }
    }
}

// ---------------- separable Gaussian position attention ----------------
__global__ __launch_bounds__(256) void av_init_kernel(float* __restrict__ Av) {
    int i = blockIdx.x * 256 + threadIdx.x;
    float d = (float)((i >> 6) - (i & 63));
    Av[i] = __expf(-d * d * (1.0f/512.0f));
}

__global__ __launch_bounds__(256) void scatter_kernel(
    const __half* __restrict__ xnA, const int* __restrict__ posv,
    const int* __restrict__ posh, float* __restrict__ G, float* __restrict__ cnt)
{
    int warp = threadIdx.x >> 5, lane = threadIdx.x & 31;
    long row = (long)blockIdx.x * 8 + warp;
    int b = (int)(row >> 10), t = (int)(row & 1023);
    int pv = posv[b*Tt + t], ph = posh[b*Tt + t];
    float* dst = G + (((long)b*64 + pv)*64 + ph) * 512;
    const __half* ar = xnA + row * (2*Dd);
#pragma unroll
    for (int i = 0; i < 16; i++) {
        int d = i*32 + lane;
        float v = __half2float(ar[d]) + __half2float(ar[Dd + d]);
        atomicAdd(&dst[d], v);
    }
    if (lane == 0) atomicAdd(&cnt[((long)b*64 + pv)*64 + ph], 1.0f);
}

__global__ __launch_bounds__(512) void gconv_kernel(
    const float* __restrict__ in, float* __restrict__ out,
    const float* __restrict__ Av, int stride_fix, int stride_c)
{
    __shared__ float AsT[64][64];
    int fix = blockIdx.x, b = blockIdx.y, tid = threadIdx.x;
    for (int i = tid; i < 4096; i += 512)
        AsT[i & 63][i >> 6] = Av[i];
    __syncthreads();
    const float* ib = in  + (long)b*2097152 + (long)fix*stride_fix + tid;
    float* ob       = out + (long)b*2097152 + (long)fix*stride_fix + tid;
    float acc[64];
#pragma unroll
    for (int v = 0; v < 64; v++) acc[v] = 0.f;
    for (int c = 0; c < 64; c++) {
        float g = ib[(long)c * stride_c];
#pragma unroll
        for (int v4 = 0; v4 < 16; v4++) {
            float4 a4 = *(const float4*)&AsT[c][v4*4];
            acc[v4*4+0] += a4.x*g; acc[v4*4+1] += a4.y*g;
            acc[v4*4+2] += a4.z*g; acc[v4*4+3] += a4.w*g;
        }
    }
#pragma unroll
    for (int v = 0; v < 64; v++) ob[(long)v * stride_c] = acc[v];
}

__global__ __launch_bounds__(1024) void dcnt_kernel(
    const float* __restrict__ cnt, const float* __restrict__ Av,
    float* __restrict__ dcnt)
{
    __shared__ float sc[4096], st[4096];
    int b = blockIdx.x, tid = threadIdx.x;
    for (int i = tid; i < 4096; i += 1024) sc[i] = cnt[(long)b*4096 + i];
    __syncthreads();
    for (int i = tid; i < 4096; i += 1024) {
        int v = i >> 6, hp = i & 63;
        float s = 0.f;
        for (int vp = 0; vp < 64; vp++) s += Av[v*64+vp] * sc[vp*64+hp];
        st[i] = s;
    }
    __syncthreads();
    for (int i = tid; i < 4096; i += 1024) {
        int v = i >> 6, h = i & 63;
        float s = 0.f;
        for (int hp = 0; hp < 64; hp++) s += Av[h*64+hp] * st[v*64+hp];
        dcnt[(long)b*4096 + i] = 1.0f / s;
    }
}

// ---------------- combine + LN2 ----------------
__global__ __launch_bounds__(256) void combine_ln2_kernel(
    const float* __restrict__ x, const float* __restrict__ stdo,
    const float* __restrict__ O, const float* __restrict__ dcntInv,
    const int* __restrict__ posv, const int* __restrict__ posh,
    const float* __restrict__ gate,
    const float* __restrict__ w, const float* __restrict__ bb,
    float* __restrict__ x1, __half* __restrict__ xn2A)
{
    int warp = threadIdx.x >> 5, lane = threadIdx.x & 31;
    long row = (long)blockIdx.x * 8 + warp;
    int b = (int)(row >> 10), t = (int)(row & 1023);
    int pv = posv[b*Tt + t], ph = posh[b*Tt + t];
    float g = 1.0f / (1.0f + __expf(-gate[0]));
    float gi = 1.0f - g;
    float inv_ks = dcntInv[((long)b*64 + pv)*64 + ph];
    const float* korow = O + (((long)b*64 + pv)*64 + ph) * 512;
    long base = row * Dd;
    float4 v[4];
    float s = 0.f, sq = 0.f;
#pragma unroll
    for (int i = 0; i < 4; i++) {
        int d = lane*4 + i*128;
        float4 xv = *(const float4*)&x[base + d];
        float4 sv = *(const float4*)&stdo[base + d];
        float4 kv = *(const float4*)&korow[d];
        float4 o4;
        o4.x = xv.x + g*sv.x + gi*kv.x*inv_ks;
        o4.y = xv.y + g*sv.y + gi*kv.y*inv_ks;
        o4.z = xv.z + g*sv.z + gi*kv.z*inv_ks;
        o4.w = xv.w + g*sv.w + gi*kv.w*inv_ks;
        *(float4*)&x1[base + d] = o4;
        v[i] = o4;
        s  += o4.x + o4.y + o4.z + o4.w;
        sq += o4.x*o4.x + o4.y*o4.y + o4.z*o4.z + o4.w*o4.w;
    }
#pragma unroll
    for (int o = 16; o; o >>= 1) {
        s  += __shfl_xor_sync(0xffffffffu, s,  o);
        sq += __shfl_xor_sync(0xffffffffu, sq, o);
    }
    float mean = s * (1.0f/512.0f);
    float var  = sq * (1.0f/512.0f) - mean*mean;
    float rr   = rsqrtf(var + 1e-5f);
    __half* arow = xn2A + row * (2*Dd);
#pragma unroll
    for (int i = 0; i < 4; i++) {
        int d = lane*4 + i*128;
        float4 wv = *(const float4*)&w[d];
        float4 bv = *(const float4*)&bb[d];
        float4 o4;
        o4.x = (v[i].x - mean)*rr*wv.x + bv.x;
        o4.y = (v[i].y - mean)*rr*wv.y + bv.y;
        o4.z = (v[i].z - mean)*rr*wv.z + bv.z;
        o4.w = (v[i].w - mean)*rr*wv.w + bv.w;
        uint2 H, L; split4_h(o4, H, L);
        *(uint2*)&arow[d]      = H;
        *(uint2*)&arow[Dd + d] = L;
    }
}

// ---------------- launch ----------------
extern "C" void kernel_launch(void* const* d_in, const int* in_sizes, int n_in,
                              void* d_out, int out_size)
{
    const float* x      = (const float*)d_in[0];
    const int*   posv   = (const int*)  d_in[1];
    const int*   posh   = (const int*)  d_in[2];
    const float* n1w    = (const float*)d_in[3];
    const float* n1b    = (const float*)d_in[4];
    const float* in_w   = (const float*)d_in[5];
    const float* in_b   = (const float*)d_in[6];
    const float* out_w  = (const float*)d_in[7];
    const float* out_b  = (const float*)d_in[8];
    const float* n2w    = (const float*)d_in[9];
    const float* n2b    = (const float*)d_in[10];
    const float* w1     = (const float*)d_in[11];
    const float* b1     = (const float*)d_in[12];
    const float* w2     = (const float*)d_in[13];
    const float* b2     = (const float*)d_in[14];
    const float* gate   = (const float*)d_in[15];
    float* out = (float*)d_out;

    __half *xnA, *ctxA, *xn2A, *hA, *wIN, *wOUT, *w1p, *w2p;
    __nv_bfloat16 *Qbp, *Kbp, *Vbp;
    float *stdo, *G, *T1, *cnt, *dcnt, *Av, *x1;
    cudaGetSymbolAddress((void**)&xnA,  g_xnA);
    cudaGetSymbolAddress((void**)&Qbp,  g_Qb);
    cudaGetSymbolAddress((void**)&Kbp,  g_Kb);
    cudaGetSymbolAddress((void**)&Vbp,  g_Vb);
    cudaGetSymbolAddress((void**)&ctxA, g_ctxA);
    cudaGetSymbolAddress((void**)&stdo, g_stdo);
    cudaGetSymbolAddress((void**)&G,    g_G);
    cudaGetSymbolAddress((void**)&T1,   g_T1);
    cudaGetSymbolAddress((void**)&cnt,  g_cnt);
    cudaGetSymbolAddress((void**)&dcnt, g_dcnt);
    cudaGetSymbolAddress((void**)&Av,   g_Av);
    cudaGetSymbolAddress((void**)&x1,   g_x1);
    cudaGetSymbolAddress((void**)&xn2A, g_xn2A);
    cudaGetSymbolAddress((void**)&hA,   g_hA);
    cudaGetSymbolAddress((void**)&wIN,  g_wIN);
    cudaGetSymbolAddress((void**)&wOUT, g_wOUT);
    cudaGetSymbolAddress((void**)&w1p,  g_w1);
    cudaGetSymbolAddress((void**)&w2p,  g_w2);

    cudaFuncSetAttribute(gemm_fp16<256,3>, cudaFuncAttributeMaxDynamicSharedMemorySize, GSMEM_W256);
    cudaFuncSetAttribute(gemm_fp16<256,1>, cudaFuncAttributeMaxDynamicSharedMemorySize, GSMEM_W256);
    cudaFuncSetAttribute(gemm_fp16<128,0>, cudaFuncAttributeMaxDynamicSharedMemorySize, GSMEM_W128);
    cudaFuncSetAttribute(gemm_fp16<128,2>, cudaFuncAttributeMaxDynamicSharedMemorySize, GSMEM_W128);
    cudaFuncSetAttribute(attn_mma_kernel,  cudaFuncAttributeMaxDynamicSharedMemorySize, ATTN_SMEM);

    // weight conversions
    conv_w_kernel<<<(3*Dd*Dd/4 + 255)/256, 256>>>(in_w,  wIN,  Dd, 3*Dd*Dd/4);
    conv_w_kernel<<<(Dd*Dd/4   + 255)/256, 256>>>(out_w, wOUT, Dd, Dd*Dd/4);
    conv_w_kernel<<<(D4*Dd/4   + 255)/256, 256>>>(w1,    w1p,  Dd, D4*Dd/4);
    conv_w_kernel<<<(Dd*D4/4   + 255)/256, 256>>>(w2,    w2p,  D4, Dd*D4/4);

    // Gaussian prep
    av_init_kernel<<<16, 256>>>(Av);
    zero_kernel<<<(Bb*4096*512/4 + 255)/256, 256>>>(G, Bb*4096*512/4);
    zero_kernel<<<(Bb*4096/4 + 255)/256, 256>>>(cnt, Bb*4096/4);

    // 1) LN1 -> xnA [hi|lo]
    ln1_kernel<<<ROWS/8, 256>>>(x, n1w, n1b, xnA);

    // 2) QKV GEMM, epilogue writes pre-split attention buffers
    gemm_fp16<256, 3><<<dim3(6, 64), 256, GSMEM_W256>>>(
        xnA, wIN, in_b, nullptr, Qbp, Kbp, Vbp, 3*Dd, 2*Dd);

    // 3) flash attention (pipelined) -> ctxA
    attn_mma_kernel<<<dim3(Tt/64, Hh, Bb), 128, ATTN_SMEM>>>(Qbp, Kbp, Vbp, ctxA);

    // 4) std_out = ctx @ out_w^T + out_b
    gemm_fp16<128, 0><<<dim3(4, 64), 256, GSMEM_W128>>>(
        ctxA, wOUT, out_b, nullptr, stdo, nullptr, nullptr, Dd, 2*Dd);

    // 5) separable Gaussian position attention
    scatter_kernel<<<ROWS/8, 256>>>(xnA, posv, posh, G, cnt);
    gconv_kernel<<<dim3(64, Bb), 512>>>(G, T1, Av, 512, 64*512);
    gconv_kernel<<<dim3(64, Bb), 512>>>(T1, G, Av, 64*512, 512);
    dcnt_kernel<<<Bb, 1024>>>(cnt, Av, dcnt);

    // 6) combine + LN2
    combine_ln2_kernel<<<ROWS/8, 256>>>(
        x, stdo, G, dcnt, posv, posh, gate, n2w, n2b, x1, xn2A);

    // 7) h = gelu(xn2 @ w1^T + b1)
    gemm_fp16<256, 1><<<dim3(8, 64), 256, GSMEM_W256>>>(
        xn2A, w1p, b1, nullptr, hA, nullptr, nullptr, D4, 2*Dd);

    // 8) out = x1 + h @ w2^T + b2
    gemm_fp16<128, 2><<<dim3(4, 64), 256, GSMEM_W128>>>(
        hA, w2p, b2, x1, out, nullptr, nullptr, Dd, 2*D4);
}

// round 10
// speedup vs baseline: 2.1439x; 1.1768x over previous
#include <cuda_runtime.h>
#include <cuda_bf16.h>
#include <cuda_fp16.h>
#include <mma.h>
#include <math.h>
#include <stdint.h>

using namespace nvcuda;

#define Bb 8
#define Tt 1024
#define Dd 512
#define Hh 8
#define HD 64
#define D4 2048
#define ROWS (Bb*Tt)

// ---------------- scratch (device globals) ----------------
__device__ __half g_xnA [ROWS*2*Dd];      // LN1 out, A-form [hi|lo] fp16
__device__ __half g_Qb  [Bb*Hh*Tt*128];   // Q split [hi|lo], pre-scaled 1/8
__device__ __half g_Kb  [Bb*Hh*Tt*128];   // K split [hi|hi]
__device__ __half g_Vb  [Bb*Hh*Tt*64];    // V fp16
__device__ __half g_ctxA[ROWS*2*Dd];      // attn out, A-form fp16
__device__ float  g_stdo[ROWS*Dd];
__device__ float  g_G   [Bb*64*64*512];
__device__ float  g_T1  [Bb*64*64*512];
__device__ float  g_cnt [Bb*4096];
__device__ float  g_dcnt[Bb*4096];
__device__ float  g_Av  [4096];
__device__ float  g_x1  [ROWS*Dd];
__device__ __half g_xn2A[ROWS*2*Dd];
__device__ __half g_hA  [ROWS*2*D4];
__device__ __half g_wIN [3*Dd*2*Dd];
__device__ __half g_wOUT[Dd*2*Dd];
__device__ __half g_w1  [D4*2*Dd];
__device__ __half g_w2  [Dd*2*D4];

// ---------------- helpers ----------------
__device__ __forceinline__ uint32_t smem_u32(const void* p) {
    uint32_t a;
    asm("{ .reg .u64 t; cvta.to.shared.u64 t, %1; cvt.u32.u64 %0, t; }" : "=r"(a) : "l"(p));
    return a;
}
__device__ __forceinline__ void cp16(uint32_t sdst, const void* gsrc) {
    asm volatile("cp.async.cg.shared.global [%0], [%1], 16;" :: "r"(sdst), "l"(gsrc));
}
__device__ __forceinline__ void cp_commit() {
    asm volatile("cp.async.commit_group;" ::: "memory");
}
template<int N>
__device__ __forceinline__ void cp_wait() {
    asm volatile("cp.async.wait_group %0;" :: "n"(N) : "memory");
}
__device__ __forceinline__ void split_h(float v, __half& h, __half& l) {
    h = __float2half_rn(v);
    l = __float2half_rn(v - __half2float(h));
}
__device__ __forceinline__ void split4_h(float4 v, uint2& H, uint2& L) {
    __half hx,lx,hy,ly,hz,lz,hw,lw;
    split_h(v.x,hx,lx); split_h(v.y,hy,ly);
    split_h(v.z,hz,lz); split_h(v.w,hw,lw);
    __half2 h01 = __halves2half2(hx,hy), h23 = __halves2half2(hz,hw);
    __half2 l01 = __halves2half2(lx,ly), l23 = __halves2half2(lz,lw);
    H.x = *reinterpret_cast<unsigned*>(&h01); H.y = *reinterpret_cast<unsigned*>(&h23);
    L.x = *reinterpret_cast<unsigned*>(&l01); L.y = *reinterpret_cast<unsigned*>(&l23);
}
__device__ __forceinline__ float gelu_exact(float v) {
    return 0.5f * v * (1.0f + erff(v * 0.7071067811865476f));
}

// ---------------- mma / ldmatrix primitives ----------------
__device__ __forceinline__ void ldsm_x4(uint32_t& r0, uint32_t& r1, uint32_t& r2, uint32_t& r3, uint32_t a) {
    asm volatile("ldmatrix.sync.aligned.m8n8.x4.shared.b16 {%0,%1,%2,%3}, [%4];"
                 : "=r"(r0),"=r"(r1),"=r"(r2),"=r"(r3) : "r"(a));
}
__device__ __forceinline__ void ldsm_x2(uint32_t& r0, uint32_t& r1, uint32_t a) {
    asm volatile("ldmatrix.sync.aligned.m8n8.x2.shared.b16 {%0,%1}, [%2];"
                 : "=r"(r0),"=r"(r1) : "r"(a));
}
__device__ __forceinline__ void ldsm_x2t(uint32_t& r0, uint32_t& r1, uint32_t a) {
    asm volatile("ldmatrix.sync.aligned.m8n8.x2.trans.shared.b16 {%0,%1}, [%2];"
                 : "=r"(r0),"=r"(r1) : "r"(a));
}
__device__ __forceinline__ void mma16816h(float* c, uint32_t a0, uint32_t a1, uint32_t a2, uint32_t a3,
                                          uint32_t b0, uint32_t b1) {
    asm volatile("mma.sync.aligned.m16n8k16.row.col.f32.f16.f16.f32 "
                 "{%0,%1,%2,%3}, {%4,%5,%6,%7}, {%8,%9}, {%0,%1,%2,%3};"
                 : "+f"(c[0]),"+f"(c[1]),"+f"(c[2]),"+f"(c[3])
                 : "r"(a0),"r"(a1),"r"(a2),"r"(a3),"r"(b0),"r"(b1));
}

// ---------------- zero kernel ----------------
__global__ __launch_bounds__(256) void zero_kernel(float* __restrict__ p, int n4) {
    int i = blockIdx.x * 256 + threadIdx.x;
    if (i < n4) *(float4*)&p[i*4] = make_float4(0.f,0.f,0.f,0.f);
}

// ---------------- weight conversion ----------------
__global__ __launch_bounds__(256) void conv_w_kernel(
    const float* __restrict__ W, __half* __restrict__ Wp, int K, int total4)
{
    int idx = blockIdx.x * 256 + threadIdx.x;
    if (idx >= total4) return;
    long e = (long)idx * 4;
    int r = (int)(e / K), c = (int)(e % K);
    float4 v = *(const float4*)&W[(long)r * K + c];
    uint2 H, L; split4_h(v, H, L);
    __half* row = Wp + (long)r * 2 * K;
    *(uint2*)&row[c]     = H;
    *(uint2*)&row[K + c] = H;
}

// ================ fp16 2-term split GEMM ================
// EPI: 0 fp32+bias, 1 bias+gelu->fp16 A-form, 2 fp32+bias+residual,
//      3 QKV writer -> split fp16 attention buffers
#define GSTAGES 3
#define ASTR 40
#define ASZ   (128*ASTR*2)

template<int NT, int EPI>
__global__ __launch_bounds__(256) void gemm_fp16(
    const __half* __restrict__ A, const __half* __restrict__ B,
    const float* __restrict__ bias, const float* __restrict__ res,
    void* __restrict__ Cout, void* __restrict__ aux1, void* __restrict__ aux2,
    int N, int Kp)
{
    constexpr int NFR = NT/64;
    constexpr int BSZ = NT*ASTR*2;

    extern __shared__ __align__(128) char sm[];
    char* Abase = sm;
    char* Bbase = sm + GSTAGES * ASZ;

    const int tid = threadIdx.x;
    int w = tid >> 5, lane = tid & 31, wm = w >> 2, wn = w & 3;
    int m0 = blockIdx.y << 7, n0 = blockIdx.x * NT;

    int ar = tid >> 2, ac = (tid & 3) * 8;
    const __half* Ag = A + (long)(m0 + ar) * Kp + ac;
    const __half* Bg = B + (long)(n0 + ar) * Kp + ac;
    uint32_t Asw = smem_u32(Abase) + (uint32_t)(ar * (ASTR*2) + ac * 2);
    uint32_t Bsw = smem_u32(Bbase) + (uint32_t)(ar * (ASTR*2) + ac * 2);

    int nk = Kp >> 5;

#define GISSUE(kt) do { \
        if ((kt) < nk) { \
            int st_ = (kt) % GSTAGES; \
            long ko_ = (long)(kt) * 32; \
            uint32_t ad = Asw + (uint32_t)st_ * ASZ; \
            cp16(ad,                Ag + ko_); \
            cp16(ad + 64*(ASTR*2),  Ag + ko_ + (long)64*Kp); \
            uint32_t bd = Bsw + (uint32_t)st_ * BSZ; \
            _Pragma("unroll") \
            for (int i_ = 0; i_ < NT/64; i_++) \
                cp16(bd + i_*64*(ASTR*2), Bg + ko_ + (long)(i_*64)*Kp); \
        } \
        cp_commit(); \
    } while (0)

    wmma::fragment<wmma::accumulator, 16, 16, 16, float> acc[4][NFR];
#pragma unroll
    for (int i = 0; i < 4; i++)
#pragma unroll
        for (int j = 0; j < NFR; j++) wmma::fill_fragment(acc[i][j], 0.f);

#pragma unroll
    for (int i = 0; i < GSTAGES - 1; i++) GISSUE(i);

    for (int kt = 0; kt < nk; kt++) {
        cp_wait<GSTAGES - 2>();
        __syncthreads();
        GISSUE(kt + GSTAGES - 1);
        int st = kt % GSTAGES;
        const __half* Asm = (const __half*)(Abase + st * ASZ);
        const __half* Bsm = (const __half*)(Bbase + st * BSZ);
#pragma unroll
        for (int kk = 0; kk < 2; kk++) {
            wmma::fragment<wmma::matrix_a, 16, 16, 16, __half, wmma::row_major> af[4];
#pragma unroll
            for (int i = 0; i < 4; i++)
                wmma::load_matrix_sync(af[i], Asm + (wm*64 + i*16)*ASTR + kk*16, ASTR);
#pragma unroll
            for (int jh = 0; jh < NFR/2; jh++) {
                wmma::fragment<wmma::matrix_b, 16, 16, 16, __half, wmma::col_major> bf[2];
#pragma unroll
                for (int j = 0; j < 2; j++)
                    wmma::load_matrix_sync(bf[j], Bsm + (wn*(NT/4) + jh*32 + j*16)*ASTR + kk*16, ASTR);
#pragma unroll
                for (int i = 0; i < 4; i++)
#pragma unroll
                    for (int j = 0; j < 2; j++)
                        wmma::mma_sync(acc[i][jh*2+j], af[i], bf[j], acc[i][jh*2+j]);
            }
        }
        __syncthreads();
    }
#undef GISSUE

    float* EP = (float*)sm + w * 256;
    int r = lane >> 1, c0 = (lane & 1) * 8;
    long ldc = (EPI == 1) ? (long)2 * N : (long)N;
#pragma unroll
    for (int i = 0; i < 4; i++) {
#pragma unroll
        for (int j = 0; j < NFR; j++) {
            wmma::store_matrix_sync(EP, acc[i][j], 16, wmma::mem_row_major);
            __syncwarp();
            long grow = m0 + wm*64 + i*16 + r;
            int  gcol = n0 + wn*(NT/4) + j*16 + c0;
            float4 v0 = *(float4*)&EP[r*16 + c0];
            float4 v1 = *(float4*)&EP[r*16 + c0 + 4];
            if (bias) {
                float4 b0 = *(const float4*)&bias[gcol];
                float4 b1 = *(const float4*)&bias[gcol + 4];
                v0.x += b0.x; v0.y += b0.y; v0.z += b0.z; v0.w += b0.w;
                v1.x += b1.x; v1.y += b1.y; v1.z += b1.z; v1.w += b1.w;
            }
            if (EPI == 1) {
                v0.x = gelu_exact(v0.x); v0.y = gelu_exact(v0.y);
                v0.z = gelu_exact(v0.z); v0.w = gelu_exact(v0.w);
                v1.x = gelu_exact(v1.x); v1.y = gelu_exact(v1.y);
                v1.z = gelu_exact(v1.z); v1.w = gelu_exact(v1.w);
                uint2 H0,L0,H1,L1;
                split4_h(v0,H0,L0); split4_h(v1,H1,L1);
                __half* Crow = (__half*)Cout + grow * ldc;
                uint4 Hq = make_uint4(H0.x,H0.y,H1.x,H1.y);
                uint4 Lq = make_uint4(L0.x,L0.y,L1.x,L1.y);
                *(uint4*)&Crow[gcol]     = Hq;
                *(uint4*)&Crow[N + gcol] = Lq;
            } else if (EPI == 3) {
                int bidx = (int)(grow >> 10), t = (int)(grow & 1023);
                int sec = gcol >> 9, cc = gcol & 511, h = cc >> 6, d = cc & 63;
                long hrow = ((long)bidx*Hh + h)*Tt + t;
                if (sec == 0) {
                    v0.x *= 0.125f; v0.y *= 0.125f; v0.z *= 0.125f; v0.w *= 0.125f;
                    v1.x *= 0.125f; v1.y *= 0.125f; v1.z *= 0.125f; v1.w *= 0.125f;
                    uint2 H0,L0,H1,L1; split4_h(v0,H0,L0); split4_h(v1,H1,L1);
                    __half* row = (__half*)Cout + hrow*128;
                    *(uint2*)&row[d]      = H0; *(uint2*)&row[d+4]    = H1;
                    *(uint2*)&row[64+d]   = L0; *(uint2*)&row[68+d]   = L1;
                } else if (sec == 1) {
                    uint2 H0,L0,H1,L1; split4_h(v0,H0,L0); split4_h(v1,H1,L1);
                    __half* row = (__half*)aux1 + hrow*128;
                    *(uint2*)&row[d]      = H0; *(uint2*)&row[d+4]    = H1;
                    *(uint2*)&row[64+d]   = H0; *(uint2*)&row[68+d]   = H1;
                } else {
                    __half2 p0 = __floats2half2_rn(v0.x, v0.y);
                    __half2 p1 = __floats2half2_rn(v0.z, v0.w);
                    __half2 p2 = __floats2half2_rn(v1.x, v1.y);
                    __half2 p3 = __floats2half2_rn(v1.z, v1.w);
                    uint4 P = make_uint4(*(unsigned*)&p0, *(unsigned*)&p1,
                                         *(unsigned*)&p2, *(unsigned*)&p3);
                    *(uint4*)((__half*)aux2 + hrow*64 + d) = P;
                }
            } else {
                float* C = (float*)Cout;
                if (EPI == 2) {
                    float4 r0 = *(const float4*)&res[grow*N + gcol];
                    float4 r1 = *(const float4*)&res[grow*N + gcol + 4];
                    v0.x += r0.x; v0.y += r0.y; v0.z += r0.z; v0.w += r0.w;
                    v1.x += r1.x; v1.y += r1.y; v1.z += r1.z; v1.w += r1.w;
                }
                *(float4*)&C[grow*ldc + gcol]     = v0;
                *(float4*)&C[grow*ldc + gcol + 4] = v1;
            }
            __syncwarp();
        }
    }
}

#define GSMEM_W256 (GSTAGES*(ASZ + 256*ASTR*2))
#define GSMEM_W128 (GSTAGES*(ASZ + 128*ASTR*2))

// ---------------- LN1 ----------------
__global__ __launch_bounds__(256) void ln1_kernel(
    const float* __restrict__ x, const float* __restrict__ w,
    const float* __restrict__ b, __half* __restrict__ xnA)
{
    int warp = threadIdx.x >> 5, lane = threadIdx.x & 31;
    long row = (long)blockIdx.x * 8 + warp;
    const float* xr = x + row * Dd;
    float4 v[4];
    float s = 0.f, sq = 0.f;
#pragma unroll
    for (int i = 0; i < 4; i++) {
        v[i] = *(const float4*)&xr[lane*4 + i*128];
        s  += v[i].x + v[i].y + v[i].z + v[i].w;
        sq += v[i].x*v[i].x + v[i].y*v[i].y + v[i].z*v[i].z + v[i].w*v[i].w;
    }
#pragma unroll
    for (int o = 16; o; o >>= 1) {
        s  += __shfl_xor_sync(0xffffffffu, s,  o);
        sq += __shfl_xor_sync(0xffffffffu, sq, o);
    }
    float mean = s * (1.0f/512.0f);
    float var  = sq * (1.0f/512.0f) - mean*mean;
    float rr   = rsqrtf(var + 1e-5f);
    __half* arow = xnA + row * (2*Dd);
#pragma unroll
    for (int i = 0; i < 4; i++) {
        int d = lane*4 + i*128;
        float4 wv = *(const float4*)&w[d];
        float4 bv = *(const float4*)&b[d];
        float4 o4;
        o4.x = (v[i].x - mean)*rr*wv.x + bv.x;
        o4.y = (v[i].y - mean)*rr*wv.y + bv.y;
        o4.z = (v[i].z - mean)*rr*wv.z + bv.z;
        o4.w = (v[i].w - mean)*rr*wv.w + bv.w;
        uint2 H, L; split4_h(o4, H, L);
        *(uint2*)&arow[d]      = H;
        *(uint2*)&arow[Dd + d] = L;
    }
}

// ---------------- flash attention: fp16 2-term, cp.async pipelined ----------------
#define QSTR 136
#define VSTR 72
#define KBUF (64*QSTR)
#define VBUF (64*VSTR)
#define ATTN_SMEM ((3*KBUF + 2*VBUF)*2)   // 70656 B

__global__ __launch_bounds__(128) void attn_mma_kernel(
    const __half* __restrict__ Qb, const __half* __restrict__ Kb,
    const __half* __restrict__ Vb, __half* __restrict__ ctxA)
{
    extern __shared__ __half smh[];
    __half* Qs  = smh;
    __half* Ks0 = smh + KBUF;
    __half* Vs0 = smh + 3*KBUF;

    int b = blockIdx.z, h = blockIdx.y, qt = blockIdx.x;
    int tid = threadIdx.x, wq = tid >> 5, lane = tid & 31;
    long hbase = ((long)b*Hh + h)*Tt;

    const __half* Qg = Qb + (hbase + qt*64)*128;
    const __half* Kg = Kb + hbase*128;
    const __half* Vg = Vb + hbase*64;

    int lr = tid >> 1, lc = tid & 1;
    uint32_t QsA = smem_u32(Qs)  + lr*(QSTR*2) + lc*128;
    uint32_t KsA = smem_u32(Ks0) + lr*(QSTR*2) + lc*128;
    uint32_t VsA = smem_u32(Vs0) + lr*(VSTR*2) + lc*64;

#pragma unroll
    for (int i = 0; i < 8; i++)
        cp16(QsA + i*16, Qg + lr*128 + lc*64 + i*8);
#define ISSUE_KV(kt, buf) do { \
        const __half* kg_ = Kg + (long)((kt)*64 + lr)*128 + lc*64; \
        uint32_t kd_ = KsA + (buf)*(KBUF*2); \
        _Pragma("unroll") \
        for (int i_ = 0; i_ < 8; i_++) cp16(kd_ + i_*16, kg_ + i_*8); \
        const __half* vg_ = Vg + (long)((kt)*64 + lr)*64 + lc*32; \
        uint32_t vd_ = VsA + (buf)*(VBUF*2); \
        _Pragma("unroll") \
        for (int i_ = 0; i_ < 4; i_++) cp16(vd_ + i_*16, vg_ + i_*8); \
    } while (0)
    ISSUE_KV(0, 0);
    cp_commit();

    float cf[8][4];
#pragma unroll
    for (int j = 0; j < 8; j++) { cf[j][0]=0.f; cf[j][1]=0.f; cf[j][2]=0.f; cf[j][3]=0.f; }
    float m0 = -1e30f, m1 = -1e30f, l0 = 0.f, l1 = 0.f;

    uint32_t qaddr = smem_u32(&Qs[(16*wq + (lane & 15))*QSTR + 8*(lane >> 4)]);

    for (int kt = 0; kt < 16; kt++) {
        if (kt + 1 < 16) ISSUE_KV(kt + 1, (kt + 1) & 1);
        cp_commit();
        cp_wait<1>();
        __syncthreads();
        const __half* Kbuf = Ks0 + (kt & 1)*KBUF;
        const __half* Vbuf = Vs0 + (kt & 1)*VBUF;

        float sf[8][4] = {};
#pragma unroll
        for (int kc = 0; kc < 8; kc++) {
            uint32_t a0, a1, a2, a3;
            ldsm_x4(a0, a1, a2, a3, qaddr + kc*32);
#pragma unroll
            for (int n8 = 0; n8 < 8; n8++) {
                uint32_t b0, b1;
                uint32_t ka = smem_u32(&Kbuf[(8*n8 + (lane & 7))*QSTR + 16*kc + 8*((lane >> 3) & 1)]);
                ldsm_x2(b0, b1, ka);
                mma16816h(sf[n8], a0, a1, a2, a3, b0, b1);
            }
        }

        float mt0 = -1e30f, mt1 = -1e30f;
#pragma unroll
        for (int j = 0; j < 8; j++) {
            mt0 = fmaxf(mt0, fmaxf(sf[j][0], sf[j][1]));
            mt1 = fmaxf(mt1, fmaxf(sf[j][2], sf[j][3]));
        }
        mt0 = fmaxf(mt0, __shfl_xor_sync(0xffffffffu, mt0, 1));
        mt0 = fmaxf(mt0, __shfl_xor_sync(0xffffffffu, mt0, 2));
        mt1 = fmaxf(mt1, __shfl_xor_sync(0xffffffffu, mt1, 1));
        mt1 = fmaxf(mt1, __shfl_xor_sync(0xffffffffu, mt1, 2));
        float mn0 = fmaxf(m0, mt0), mn1 = fmaxf(m1, mt1);
        float cr0 = __expf(m0 - mn0), cr1 = __expf(m1 - mn1);
        m0 = mn0; m1 = mn1; l0 *= cr0; l1 *= cr1;
#pragma unroll
        for (int j = 0; j < 8; j++) {
            cf[j][0] *= cr0; cf[j][1] *= cr0; cf[j][2] *= cr1; cf[j][3] *= cr1;
        }

        uint32_t pa[4][4];
#pragma unroll
        for (int jk = 0; jk < 4; jk++) {
            float e00 = __expf(sf[2*jk][0]   - mn0), e01 = __expf(sf[2*jk][1]   - mn0);
            float e10 = __expf(sf[2*jk][2]   - mn1), e11 = __expf(sf[2*jk][3]   - mn1);
            float e20 = __expf(sf[2*jk+1][0] - mn0), e21 = __expf(sf[2*jk+1][1] - mn0);
            float e30 = __expf(sf[2*jk+1][2] - mn1), e31 = __expf(sf[2*jk+1][3] - mn1);
            l0 += e00 + e01 + e20 + e21;
            l1 += e10 + e11 + e30 + e31;
            __half2 t;
            t = __floats2half2_rn(e00, e01); pa[jk][0] = *(unsigned*)&t;
            t = __floats2half2_rn(e10, e11); pa[jk][1] = *(unsigned*)&t;
            t = __floats2half2_rn(e20, e21); pa[jk][2] = *(unsigned*)&t;
            t = __floats2half2_rn(e30, e31); pa[jk][3] = *(unsigned*)&t;
        }

#pragma unroll
        for (int jk = 0; jk < 4; jk++) {
#pragma unroll
            for (int jd = 0; jd < 8; jd++) {
                uint32_t b0, b1;
                uint32_t va = smem_u32(&Vbuf[(16*jk + (lane & 15))*VSTR + 8*jd]);
                ldsm_x2t(b0, b1, va);
                mma16816h(cf[jd], pa[jk][0], pa[jk][1], pa[jk][2], pa[jk][3], b0, b1);
            }
        }
        __syncthreads();
    }
#undef ISSUE_KV

    l0 += __shfl_xor_sync(0xffffffffu, l0, 1);
    l0 += __shfl_xor_sync(0xffffffffu, l0, 2);
    l1 += __shfl_xor_sync(0xffffffffu, l1, 1);
    l1 += __shfl_xor_sync(0xffffffffu, l1, 2);
    float inv0 = 1.0f / l0, inv1 = 1.0f / l1;

    long grow0 = (long)b*Tt + qt*64 + 16*wq + (lane >> 2);
    long grow1 = grow0 + 8;
    int colb = h*HD + 2*(lane & 3);
    __half* cr0p = ctxA + grow0 * (2*Dd);
    __half* cr1p = ctxA + grow1 * (2*Dd);
#pragma unroll
    for (int jd = 0; jd < 8; jd++) {
        int col = colb + 8*jd;
        {
            float v0 = cf[jd][0]*inv0, v1 = cf[jd][1]*inv0;
            __half h0,lo0,h1,lo1; split_h(v0,h0,lo0); split_h(v1,h1,lo1);
            __half2 Hp = __halves2half2(h0,h1), Lp = __halves2half2(lo0,lo1);
            *(unsigned*)&cr0p[col]      = *(unsigned*)&Hp;
            *(unsigned*)&cr0p[Dd + col] = *(unsigned*)&Lp;
        }
        {
            float v0 = cf[jd][2]*inv1, v1 = cf[jd][3]*inv1;
            __half h0,lo0,h1,lo1; split_h(v0,h0,lo0); split_h(v1,h1,lo1);
            __half2 Hp = __halves2half2(h0,h1), Lp = __halves2half2(lo0,lo1);
            *(unsigned*)&cr1p[col]      = *(unsigned*)&Hp;
            *(unsigned*)&cr1p[Dd + col] = *(unsigned*)&Lp;
        }
    }
}

// ---------------- separable Gaussian position attention ----------------
__global__ __launch_bounds__(256) void av_init_kernel(float* __restrict__ Av) {
    int i = blockIdx.x * 256 + threadIdx.x;
    float d = (float)((i >> 6) - (i & 63));
    Av[i] = __expf(-d * d * (1.0f/512.0f));
}

__global__ __launch_bounds__(256) void scatter_kernel(
    const __half* __restrict__ xnA, const int* __restrict__ posv,
    const int* __restrict__ posh, float* __restrict__ G, float* __restrict__ cnt)
{
    int warp = threadIdx.x >> 5, lane = threadIdx.x & 31;
    long row = (long)blockIdx.x * 8 + warp;
    int b = (int)(row >> 10), t = (int)(row & 1023);
    int pv = posv[b*Tt + t], ph = posh[b*Tt + t];
    float* dst = G + (((long)b*64 + pv)*64 + ph) * 512;
    const __half* ar = xnA + row * (2*Dd);
#pragma unroll
    for (int i = 0; i < 16; i++) {
        int d = i*32 + lane;
        float v = __half2float(ar[d]) + __half2float(ar[Dd + d]);
        atomicAdd(&dst[d], v);
    }
    if (lane == 0) atomicAdd(&cnt[((long)b*64 + pv)*64 + ph], 1.0f);
}

__global__ __launch_bounds__(512) void gconv_kernel(
    const float* __restrict__ in, float* __restrict__ out,
    const float* __restrict__ Av, int stride_fix, int stride_c)
{
    __shared__ float AsT[64][64];
    int fix = blockIdx.x, b = blockIdx.y, tid = threadIdx.x;
    for (int i = tid; i < 4096; i += 512)
        AsT[i & 63][i >> 6] = Av[i];
    __syncthreads();
    const float* ib = in  + (long)b*2097152 + (long)fix*stride_fix + tid;
    float* ob       = out + (long)b*2097152 + (long)fix*stride_fix + tid;
    float acc[64];
#pragma unroll
    for (int v = 0; v < 64; v++) acc[v] = 0.f;
    for (int c = 0; c < 64; c++) {
        float g = ib[(long)c * stride_c];
#pragma unroll
        for (int v4 = 0; v4 < 16; v4++) {
            float4 a4 = *(const float4*)&AsT[c][v4*4];
            acc[v4*4+0] += a4.x*g; acc[v4*4+1] += a4.y*g;
            acc[v4*4+2] += a4.z*g; acc[v4*4+3] += a4.w*g;
        }
    }
#pragma unroll
    for (int v = 0; v < 64; v++) ob[(long)v * stride_c] = acc[v];
}

__global__ __launch_bounds__(1024) void dcnt_kernel(
    const float* __restrict__ cnt, const float* __restrict__ Av,
    float* __restrict__ dcnt)
{
    __shared__ float sc[4096], st[4096];
    int b = blockIdx.x, tid = threadIdx.x;
    for (int i = tid; i < 4096; i += 1024) sc[i] = cnt[(long)b*4096 + i];
    __syncthreads();
    for (int i = tid; i < 4096; i += 1024) {
        int v = i >> 6, hp = i & 63;
        float s = 0.f;
        for (int vp = 0; vp < 64; vp++) s += Av[v*64+vp] * sc[vp*64+hp];
        st[i] = s;
    }
    __syncthreads();
    for (int i = tid; i < 4096; i += 1024) {
        int v = i >> 6, h = i & 63;
        float s = 0.f;
        for (int hp = 0; hp < 64; hp++) s += Av[h*64+hp] * st[v*64+hp];
        dcnt[(long)b*4096 + i] = 1.0f / s;
    }
}

// ---------------- combine + LN2 ----------------
__global__ __launch_bounds__(256) void combine_ln2_kernel(
    const float* __restrict__ x, const float* __restrict__ stdo,
    const float* __restrict__ O, const float* __restrict__ dcntInv,
    const int* __restrict__ posv, const int* __restrict__ posh,
    const float* __restrict__ gate,
    const float* __restrict__ w, const float* __restrict__ bb,
    float* __restrict__ x1, __half* __restrict__ xn2A)
{
    int warp = threadIdx.x >> 5, lane = threadIdx.x & 31;
    long row = (long)blockIdx.x * 8 + warp;
    int b = (int)(row >> 10), t = (int)(row & 1023);
    int pv = posv[b*Tt + t], ph = posh[b*Tt + t];
    float g = 1.0f / (1.0f + __expf(-gate[0]));
    float gi = 1.0f - g;
    float inv_ks = dcntInv[((long)b*64 + pv)*64 + ph];
    const float* korow = O + (((long)b*64 + pv)*64 + ph) * 512;
    long base = row * Dd;
    float4 v[4];
    float s = 0.f, sq = 0.f;
#pragma unroll
    for (int i = 0; i < 4; i++) {
        int d = lane*4 + i*128;
        float4 xv = *(const float4*)&x[base + d];
        float4 sv = *(const float4*)&stdo[base + d];
        float4 kv = *(const float4*)&korow[d];
        float4 o4;
        o4.x = xv.x + g*sv.x + gi*kv.x*inv_ks;
        o4.y = xv.y + g*sv.y + gi*kv.y*inv_ks;
        o4.z = xv.z + g*sv.z + gi*kv.z*inv_ks;
        o4.w = xv.w + g*sv.w + gi*kv.w*inv_ks;
        *(float4*)&x1[base + d] = o4;
        v[i] = o4;
        s  += o4.x + o4.y + o4.z + o4.w;
        sq += o4.x*o4.x + o4.y*o4.y + o4.z*o4.z + o4.w*o4.w;
    }
#pragma unroll
    for (int o = 16; o; o >>= 1) {
        s  += __shfl_xor_sync(0xffffffffu, s,  o);
        sq += __shfl_xor_sync(0xffffffffu, sq, o);
    }
    float mean = s * (1.0f/512.0f);
    float var  = sq * (1.0f/512.0f) - mean*mean;
    float rr   = rsqrtf(var + 1e-5f);
    __half* arow = xn2A + row * (2*Dd);
#pragma unroll
    for (int i = 0; i < 4; i++) {
        int d = lane*4 + i*128;
        float4 wv = *(const float4*)&w[d];
        float4 bv = *(const float4*)&bb[d];
        float4 o4;
        o4.x = (v[i].x - mean)*rr*wv.x + bv.x;
        o4.y = (v[i].y - mean)*rr*wv.y + bv.y;
        o4.z = (v[i].z - mean)*rr*wv.z + bv.z;
        o4.w = (v[i].w - mean)*rr*wv.w + bv.w;
        uint2 H, L; split4_h(o4, H, L);
        *(uint2*)&arow[d]      = H;
        *(uint2*)&arow[Dd + d] = L;
    }
}

// ---------------- launch ----------------
extern "C" void kernel_launch(void* const* d_in, const int* in_sizes, int n_in,
                              void* d_out, int out_size)
{
    const float* x      = (const float*)d_in[0];
    const int*   posv   = (const int*)  d_in[1];
    const int*   posh   = (const int*)  d_in[2];
    const float* n1w    = (const float*)d_in[3];
    const float* n1b    = (const float*)d_in[4];
    const float* in_w   = (const float*)d_in[5];
    const float* in_b   = (const float*)d_in[6];
    const float* out_w  = (const float*)d_in[7];
    const float* out_b  = (const float*)d_in[8];
    const float* n2w    = (const float*)d_in[9];
    const float* n2b    = (const float*)d_in[10];
    const float* w1     = (const float*)d_in[11];
    const float* b1     = (const float*)d_in[12];
    const float* w2     = (const float*)d_in[13];
    const float* b2     = (const float*)d_in[14];
    const float* gate   = (const float*)d_in[15];
    float* out = (float*)d_out;

    __half *xnA, *ctxA, *xn2A, *hA, *wIN, *wOUT, *w1p, *w2p, *Qbp, *Kbp, *Vbp;
    float *stdo, *G, *T1, *cnt, *dcnt, *Av, *x1;
    cudaGetSymbolAddress((void**)&xnA,  g_xnA);
    cudaGetSymbolAddress((void**)&Qbp,  g_Qb);
    cudaGetSymbolAddress((void**)&Kbp,  g_Kb);
    cudaGetSymbolAddress((void**)&Vbp,  g_Vb);
    cudaGetSymbolAddress((void**)&ctxA, g_ctxA);
    cudaGetSymbolAddress((void**)&stdo, g_stdo);
    cudaGetSymbolAddress((void**)&G,    g_G);
    cudaGetSymbolAddress((void**)&T1,   g_T1);
    cudaGetSymbolAddress((void**)&cnt,  g_cnt);
    cudaGetSymbolAddress((void**)&dcnt, g_dcnt);
    cudaGetSymbolAddress((void**)&Av,   g_Av);
    cudaGetSymbolAddress((void**)&x1,   g_x1);
    cudaGetSymbolAddress((void**)&xn2A, g_xn2A);
    cudaGetSymbolAddress((void**)&hA,   g_hA);
    cudaGetSymbolAddress((void**)&wIN,  g_wIN);
    cudaGetSymbolAddress((void**)&wOUT, g_wOUT);
    cudaGetSymbolAddress((void**)&w1p,  g_w1);
    cudaGetSymbolAddress((void**)&w2p,  g_w2);

    cudaFuncSetAttribute(gemm_fp16<256,3>, cudaFuncAttributeMaxDynamicSharedMemorySize, GSMEM_W256);
    cudaFuncSetAttribute(gemm_fp16<256,1>, cudaFuncAttributeMaxDynamicSharedMemorySize, GSMEM_W256);
    cudaFuncSetAttribute(gemm_fp16<128,0>, cudaFuncAttributeMaxDynamicSharedMemorySize, GSMEM_W128);
    cudaFuncSetAttribute(gemm_fp16<128,2>, cudaFuncAttributeMaxDynamicSharedMemorySize, GSMEM_W128);
    cudaFuncSetAttribute(attn_mma_kernel,  cudaFuncAttributeMaxDynamicSharedMemorySize, ATTN_SMEM);

    // side stream fork (graph-capture-legal event fork/join)
    cudaStream_t sA;
    cudaStreamCreateWithFlags(&sA, cudaStreamNonBlocking);
    cudaEvent_t evRoot, evW, evLN, evG;
    cudaEventCreateWithFlags(&evRoot, cudaEventDisableTiming);
    cudaEventCreateWithFlags(&evW,   cudaEventDisableTiming);
    cudaEventCreateWithFlags(&evLN,  cudaEventDisableTiming);
    cudaEventCreateWithFlags(&evG,   cudaEventDisableTiming);

    cudaEventRecord(evRoot, 0);
    cudaStreamWaitEvent(sA, evRoot, 0);

    // ---- side stream: weight conversions (out/w1/w2), Av, zeros ----
    conv_w_kernel<<<(Dd*Dd/4 + 255)/256, 256, 0, sA>>>(out_w, wOUT, Dd, Dd*Dd/4);
    conv_w_kernel<<<(D4*Dd/4 + 255)/256, 256, 0, sA>>>(w1,    w1p,  Dd, D4*Dd/4);
    conv_w_kernel<<<(Dd*D4/4 + 255)/256, 256, 0, sA>>>(w2,    w2p,  D4, Dd*D4/4);
    cudaEventRecord(evW, sA);
    av_init_kernel<<<16, 256, 0, sA>>>(Av);
    zero_kernel<<<(Bb*4096*512/4 + 255)/256, 256, 0, sA>>>(G, Bb*4096*512/4);
    zero_kernel<<<(Bb*4096/4 + 255)/256, 256, 0, sA>>>(cnt, Bb*4096/4);

    // ---- main: conv wIN, LN1 ----
    conv_w_kernel<<<(3*Dd*Dd/4 + 255)/256, 256>>>(in_w, wIN, Dd, 3*Dd*Dd/4);
    ln1_kernel<<<ROWS/8, 256>>>(x, n1w, n1b, xnA);
    cudaEventRecord(evLN, 0);

    // ---- side: Gaussian path (needs LN1 + zeros) ----
    cudaStreamWaitEvent(sA, evLN, 0);
    scatter_kernel<<<ROWS/8, 256, 0, sA>>>(xnA, posv, posh, G, cnt);
    gconv_kernel<<<dim3(64, Bb), 512, 0, sA>>>(G, T1, Av, 512, 64*512);
    gconv_kernel<<<dim3(64, Bb), 512, 0, sA>>>(T1, G, Av, 64*512, 512);
    dcnt_kernel<<<Bb, 1024, 0, sA>>>(cnt, Av, dcnt);
    cudaEventRecord(evG, sA);

    // ---- main: QKV GEMM (writes split fp16 attention buffers) ----
    gemm_fp16<256, 3><<<dim3(6, 64), 256, GSMEM_W256>>>(
        xnA, wIN, in_b, nullptr, Qbp, Kbp, Vbp, 3*Dd, 2*Dd);

    // ---- main: attention ----
    attn_mma_kernel<<<dim3(Tt/64, Hh, Bb), 128, ATTN_SMEM>>>(Qbp, Kbp, Vbp, ctxA);

    // ---- main: out-proj (needs wOUT from side) ----
    cudaStreamWaitEvent(0, evW, 0);
    gemm_fp16<128, 0><<<dim3(4, 64), 256, GSMEM_W128>>>(
        ctxA, wOUT, out_b, nullptr, stdo, nullptr, nullptr, Dd, 2*Dd);

    // ---- main: combine + LN2 (needs Gaussian path) ----
    cudaStreamWaitEvent(0, evG, 0);
    combine_ln2_kernel<<<ROWS/8, 256>>>(
        x, stdo, G, dcnt, posv, posh, gate, n2w, n2b, x1, xn2A);

    // ---- main: MLP ----
    gemm_fp16<256, 1><<<dim3(8, 64), 256, GSMEM_W256>>>(
        xn2A, w1p, b1, nullptr, hA, nullptr, nullptr, D4, 2*Dd);
    gemm_fp16<128, 2><<<dim3(4, 64), 256, GSMEM_W128>>>(
        hA, w2p, b2, x1, out, nullptr, nullptr, Dd, 2*D4);
}

// round 11
// speedup vs baseline: 2.8639x; 1.3359x over previous
#include <cuda_runtime.h>
#include <cuda_fp16.h>
#include <mma.h>
#include <math.h>
#include <stdint.h>

using namespace nvcuda;

#define Bb 8
#define Tt 1024
#define Dd 512
#define Hh 8
#define HD 64
#define D4 2048
#define ROWS (Bb*Tt)

// ---------------- scratch (device globals) ----------------
__device__ __half g_xn  [ROWS*Dd];        // LN1 out, fp16
__device__ __half g_Qb  [Bb*Hh*Tt*64];    // Q fp16, pre-scaled 1/8
__device__ __half g_Kb  [Bb*Hh*Tt*64];    // K fp16
__device__ __half g_Vb  [Bb*Hh*Tt*64];    // V fp16
__device__ __half g_ctx [ROWS*Dd];        // attn out fp16
__device__ float  g_stdo[ROWS*Dd];
__device__ float  g_G   [Bb*64*64*512];
__device__ float  g_T1  [Bb*64*64*512];
__device__ float  g_cnt [Bb*4096];
__device__ float  g_dcnt[Bb*4096];
__device__ float  g_Av  [4096];
__device__ float  g_x1  [ROWS*Dd];
__device__ __half g_xn2 [ROWS*Dd];
__device__ __half g_hB  [ROWS*D4];
__device__ __half g_wIN [3*Dd*Dd];
__device__ __half g_wOUT[Dd*Dd];
__device__ __half g_w1  [D4*Dd];
__device__ __half g_w2  [Dd*D4];

// ---------------- helpers ----------------
__device__ __forceinline__ uint32_t smem_u32(const void* p) {
    uint32_t a;
    asm("{ .reg .u64 t; cvta.to.shared.u64 t, %1; cvt.u32.u64 %0, t; }" : "=r"(a) : "l"(p));
    return a;
}
__device__ __forceinline__ void cp16(uint32_t sdst, const void* gsrc) {
    asm volatile("cp.async.cg.shared.global [%0], [%1], 16;" :: "r"(sdst), "l"(gsrc));
}
__device__ __forceinline__ void cp_commit() {
    asm volatile("cp.async.commit_group;" ::: "memory");
}
template<int N>
__device__ __forceinline__ void cp_wait() {
    asm volatile("cp.async.wait_group %0;" :: "n"(N) : "memory");
}
__device__ __forceinline__ uint2 cvt4_h(float4 v) {
    __half2 a = __floats2half2_rn(v.x, v.y);
    __half2 b = __floats2half2_rn(v.z, v.w);
    uint2 r; r.x = *(unsigned*)&a; r.y = *(unsigned*)&b; return r;
}
__device__ __forceinline__ float gelu_exact(float v) {
    return 0.5f * v * (1.0f + erff(v * 0.7071067811865476f));
}

// ---------------- mma / ldmatrix primitives ----------------
__device__ __forceinline__ void ldsm_x4(uint32_t& r0, uint32_t& r1, uint32_t& r2, uint32_t& r3, uint32_t a) {
    asm volatile("ldmatrix.sync.aligned.m8n8.x4.shared.b16 {%0,%1,%2,%3}, [%4];"
                 : "=r"(r0),"=r"(r1),"=r"(r2),"=r"(r3) : "r"(a));
}
__device__ __forceinline__ void ldsm_x2(uint32_t& r0, uint32_t& r1, uint32_t a) {
    asm volatile("ldmatrix.sync.aligned.m8n8.x2.shared.b16 {%0,%1}, [%2];"
                 : "=r"(r0),"=r"(r1) : "r"(a));
}
__device__ __forceinline__ void ldsm_x2t(uint32_t& r0, uint32_t& r1, uint32_t a) {
    asm volatile("ldmatrix.sync.aligned.m8n8.x2.trans.shared.b16 {%0,%1}, [%2];"
                 : "=r"(r0),"=r"(r1) : "r"(a));
}
__device__ __forceinline__ void mma16816h(float* c, uint32_t a0, uint32_t a1, uint32_t a2, uint32_t a3,
                                          uint32_t b0, uint32_t b1) {
    asm volatile("mma.sync.aligned.m16n8k16.row.col.f32.f16.f16.f32 "
                 "{%0,%1,%2,%3}, {%4,%5,%6,%7}, {%8,%9}, {%0,%1,%2,%3};"
                 : "+f"(c[0]),"+f"(c[1]),"+f"(c[2]),"+f"(c[3])
                 : "r"(a0),"r"(a1),"r"(a2),"r"(a3),"r"(b0),"r"(b1));
}

// ---------------- zero kernel ----------------
__global__ __launch_bounds__(256) void zero_kernel(float* __restrict__ p, int n4) {
    int i = blockIdx.x * 256 + threadIdx.x;
    if (i < n4) *(float4*)&p[i*4] = make_float4(0.f,0.f,0.f,0.f);
}

// ---------------- weight conversion: plain fp16 cast ----------------
__global__ __launch_bounds__(256) void conv_w_kernel(
    const float* __restrict__ W, __half* __restrict__ Wp, int total4)
{
    int idx = blockIdx.x * 256 + threadIdx.x;
    if (idx >= total4) return;
    float4 v = *(const float4*)&W[(long)idx * 4];
    *(uint2*)&Wp[(long)idx * 4] = cvt4_h(v);
}

// ================ plain fp16 GEMM ================
// EPI: 0 fp32+bias, 1 bias+gelu->fp16, 2 fp32+bias+residual, 3 QKV writer
#define GSTAGES 3
#define ASTR 40
#define ASZ   (128*ASTR*2)

template<int NT, int EPI>
__global__ __launch_bounds__(256) void gemm_fp16(
    const __half* __restrict__ A, const __half* __restrict__ B,
    const float* __restrict__ bias, const float* __restrict__ res,
    void* __restrict__ Cout, void* __restrict__ aux1, void* __restrict__ aux2,
    int N, int Kp)
{
    constexpr int NFR = NT/64;
    constexpr int BSZ = NT*ASTR*2;

    extern __shared__ __align__(128) char sm[];
    char* Abase = sm;
    char* Bbase = sm + GSTAGES * ASZ;

    const int tid = threadIdx.x;
    int w = tid >> 5, lane = tid & 31, wm = w >> 2, wn = w & 3;
    int m0 = blockIdx.y << 7, n0 = blockIdx.x * NT;

    int ar = tid >> 2, ac = (tid & 3) * 8;
    const __half* Ag = A + (long)(m0 + ar) * Kp + ac;
    const __half* Bg = B + (long)(n0 + ar) * Kp + ac;
    uint32_t Asw = smem_u32(Abase) + (uint32_t)(ar * (ASTR*2) + ac * 2);
    uint32_t Bsw = smem_u32(Bbase) + (uint32_t)(ar * (ASTR*2) + ac * 2);

    int nk = Kp >> 5;

#define GISSUE(kt) do { \
        if ((kt) < nk) { \
            int st_ = (kt) % GSTAGES; \
            long ko_ = (long)(kt) * 32; \
            uint32_t ad = Asw + (uint32_t)st_ * ASZ; \
            cp16(ad,                Ag + ko_); \
            cp16(ad + 64*(ASTR*2),  Ag + ko_ + (long)64*Kp); \
            uint32_t bd = Bsw + (uint32_t)st_ * BSZ; \
            _Pragma("unroll") \
            for (int i_ = 0; i_ < NT/64; i_++) \
                cp16(bd + i_*64*(ASTR*2), Bg + ko_ + (long)(i_*64)*Kp); \
        } \
        cp_commit(); \
    } while (0)

    wmma::fragment<wmma::accumulator, 16, 16, 16, float> acc[4][NFR];
#pragma unroll
    for (int i = 0; i < 4; i++)
#pragma unroll
        for (int j = 0; j < NFR; j++) wmma::fill_fragment(acc[i][j], 0.f);

#pragma unroll
    for (int i = 0; i < GSTAGES - 1; i++) GISSUE(i);

    for (int kt = 0; kt < nk; kt++) {
        cp_wait<GSTAGES - 2>();
        __syncthreads();
        GISSUE(kt + GSTAGES - 1);
        int st = kt % GSTAGES;
        const __half* Asm = (const __half*)(Abase + st * ASZ);
        const __half* Bsm = (const __half*)(Bbase + st * BSZ);
#pragma unroll
        for (int kk = 0; kk < 2; kk++) {
            wmma::fragment<wmma::matrix_a, 16, 16, 16, __half, wmma::row_major> af[4];
#pragma unroll
            for (int i = 0; i < 4; i++)
                wmma::load_matrix_sync(af[i], Asm + (wm*64 + i*16)*ASTR + kk*16, ASTR);
#pragma unroll
            for (int jh = 0; jh < NFR/2; jh++) {
                wmma::fragment<wmma::matrix_b, 16, 16, 16, __half, wmma::col_major> bf[2];
#pragma unroll
                for (int j = 0; j < 2; j++)
                    wmma::load_matrix_sync(bf[j], Bsm + (wn*(NT/4) + jh*32 + j*16)*ASTR + kk*16, ASTR);
#pragma unroll
                for (int i = 0; i < 4; i++)
#pragma unroll
                    for (int j = 0; j < 2; j++)
                        wmma::mma_sync(acc[i][jh*2+j], af[i], bf[j], acc[i][jh*2+j]);
            }
        }
        __syncthreads();
    }
#undef GISSUE

    float* EP = (float*)sm + w * 256;
    int r = lane >> 1, c0 = (lane & 1) * 8;
#pragma unroll
    for (int i = 0; i < 4; i++) {
#pragma unroll
        for (int j = 0; j < NFR; j++) {
            wmma::store_matrix_sync(EP, acc[i][j], 16, wmma::mem_row_major);
            __syncwarp();
            long grow = m0 + wm*64 + i*16 + r;
            int  gcol = n0 + wn*(NT/4) + j*16 + c0;
            float4 v0 = *(float4*)&EP[r*16 + c0];
            float4 v1 = *(float4*)&EP[r*16 + c0 + 4];
            if (bias) {
                float4 b0 = *(const float4*)&bias[gcol];
                float4 b1 = *(const float4*)&bias[gcol + 4];
                v0.x += b0.x; v0.y += b0.y; v0.z += b0.z; v0.w += b0.w;
                v1.x += b1.x; v1.y += b1.y; v1.z += b1.z; v1.w += b1.w;
            }
            if (EPI == 1) {
                v0.x = gelu_exact(v0.x); v0.y = gelu_exact(v0.y);
                v0.z = gelu_exact(v0.z); v0.w = gelu_exact(v0.w);
                v1.x = gelu_exact(v1.x); v1.y = gelu_exact(v1.y);
                v1.z = gelu_exact(v1.z); v1.w = gelu_exact(v1.w);
                uint2 H0 = cvt4_h(v0), H1 = cvt4_h(v1);
                *(uint4*)((__half*)Cout + grow * N + gcol) = make_uint4(H0.x,H0.y,H1.x,H1.y);
            } else if (EPI == 3) {
                int bidx = (int)(grow >> 10), t = (int)(grow & 1023);
                int sec = gcol >> 9, cc = gcol & 511, h = cc >> 6, d = cc & 63;
                long hrow = ((long)bidx*Hh + h)*Tt + t;
                if (sec == 0) {
                    v0.x *= 0.125f; v0.y *= 0.125f; v0.z *= 0.125f; v0.w *= 0.125f;
                    v1.x *= 0.125f; v1.y *= 0.125f; v1.z *= 0.125f; v1.w *= 0.125f;
                    uint2 H0 = cvt4_h(v0), H1 = cvt4_h(v1);
                    *(uint4*)((__half*)Cout + hrow*64 + d) = make_uint4(H0.x,H0.y,H1.x,H1.y);
                } else if (sec == 1) {
                    uint2 H0 = cvt4_h(v0), H1 = cvt4_h(v1);
                    *(uint4*)((__half*)aux1 + hrow*64 + d) = make_uint4(H0.x,H0.y,H1.x,H1.y);
                } else {
                    uint2 H0 = cvt4_h(v0), H1 = cvt4_h(v1);
                    *(uint4*)((__half*)aux2 + hrow*64 + d) = make_uint4(H0.x,H0.y,H1.x,H1.y);
                }
            } else {
                float* C = (float*)Cout;
                if (EPI == 2) {
                    float4 r0 = *(const float4*)&res[grow*N + gcol];
                    float4 r1 = *(const float4*)&res[grow*N + gcol + 4];
                    v0.x += r0.x; v0.y += r0.y; v0.z += r0.z; v0.w += r0.w;
                    v1.x += r1.x; v1.y += r1.y; v1.z += r1.z; v1.w += r1.w;
                }
                *(float4*)&C[grow*(long)N + gcol]     = v0;
                *(float4*)&C[grow*(long)N + gcol + 4] = v1;
            }
            __syncwarp();
        }
    }
}

#define GSMEM_W256 (GSTAGES*(ASZ + 256*ASTR*2))
#define GSMEM_W128 (GSTAGES*(ASZ + 128*ASTR*2))

// ---------------- LN1: fp32 in -> fp16 out ----------------
__global__ __launch_bounds__(256) void ln1_kernel(
    const float* __restrict__ x, const float* __restrict__ w,
    const float* __restrict__ b, __half* __restrict__ xn)
{
    int warp = threadIdx.x >> 5, lane = threadIdx.x & 31;
    long row = (long)blockIdx.x * 8 + warp;
    const float* xr = x + row * Dd;
    float4 v[4];
    float s = 0.f, sq = 0.f;
#pragma unroll
    for (int i = 0; i < 4; i++) {
        v[i] = *(const float4*)&xr[lane*4 + i*128];
        s  += v[i].x + v[i].y + v[i].z + v[i].w;
        sq += v[i].x*v[i].x + v[i].y*v[i].y + v[i].z*v[i].z + v[i].w*v[i].w;
    }
#pragma unroll
    for (int o = 16; o; o >>= 1) {
        s  += __shfl_xor_sync(0xffffffffu, s,  o);
        sq += __shfl_xor_sync(0xffffffffu, sq, o);
    }
    float mean = s * (1.0f/512.0f);
    float var  = sq * (1.0f/512.0f) - mean*mean;
    float rr   = rsqrtf(var + 1e-5f);
    __half* yr = xn + row * Dd;
#pragma unroll
    for (int i = 0; i < 4; i++) {
        int d = lane*4 + i*128;
        float4 wv = *(const float4*)&w[d];
        float4 bv = *(const float4*)&b[d];
        float4 o4;
        o4.x = (v[i].x - mean)*rr*wv.x + bv.x;
        o4.y = (v[i].y - mean)*rr*wv.y + bv.y;
        o4.z = (v[i].z - mean)*rr*wv.z + bv.z;
        o4.w = (v[i].w - mean)*rr*wv.w + bv.w;
        *(uint2*)&yr[d] = cvt4_h(o4);
    }
}

// ---------------- flash attention: plain fp16, cp.async pipelined ----------------
#define QSTR 72
#define KBUF (64*QSTR)
#define ATTN_SMEM (5*KBUF*2)   // 46080 B

__global__ __launch_bounds__(128) void attn_mma_kernel(
    const __half* __restrict__ Qb, const __half* __restrict__ Kb,
    const __half* __restrict__ Vb, __half* __restrict__ ctx)
{
    extern __shared__ __half smh[];
    __half* Qs  = smh;
    __half* Ks0 = smh + KBUF;
    __half* Vs0 = smh + 3*KBUF;

    int b = blockIdx.z, h = blockIdx.y, qt = blockIdx.x;
    int tid = threadIdx.x, wq = tid >> 5, lane = tid & 31;
    long hbase = ((long)b*Hh + h)*Tt;

    const __half* Qg = Qb + (hbase + qt*64)*64;
    const __half* Kg = Kb + hbase*64;
    const __half* Vg = Vb + hbase*64;

    int lr = tid >> 1, lc = tid & 1;
    uint32_t QsA = smem_u32(Qs)  + lr*(QSTR*2) + lc*64;
    uint32_t KsA = smem_u32(Ks0) + lr*(QSTR*2) + lc*64;
    uint32_t VsA = smem_u32(Vs0) + lr*(QSTR*2) + lc*64;

#pragma unroll
    for (int i = 0; i < 4; i++)
        cp16(QsA + i*16, Qg + lr*64 + lc*32 + i*8);
#define ISSUE_KV(kt, buf) do { \
        const __half* kg_ = Kg + (long)((kt)*64 + lr)*64 + lc*32; \
        uint32_t kd_ = KsA + (buf)*(KBUF*2); \
        _Pragma("unroll") \
        for (int i_ = 0; i_ < 4; i_++) cp16(kd_ + i_*16, kg_ + i_*8); \
        const __half* vg_ = Vg + (long)((kt)*64 + lr)*64 + lc*32; \
        uint32_t vd_ = VsA + (buf)*(KBUF*2); \
        _Pragma("unroll") \
        for (int i_ = 0; i_ < 4; i_++) cp16(vd_ + i_*16, vg_ + i_*8); \
    } while (0)
    ISSUE_KV(0, 0);
    cp_commit();

    float cf[8][4];
#pragma unroll
    for (int j = 0; j < 8; j++) { cf[j][0]=0.f; cf[j][1]=0.f; cf[j][2]=0.f; cf[j][3]=0.f; }
    float m0 = -1e30f, m1 = -1e30f, l0 = 0.f, l1 = 0.f;

    uint32_t qaddr = smem_u32(&Qs[(16*wq + (lane & 15))*QSTR + 8*(lane >> 4)]);

    for (int kt = 0; kt < 16; kt++) {
        if (kt + 1 < 16) ISSUE_KV(kt + 1, (kt + 1) & 1);
        cp_commit();
        cp_wait<1>();
        __syncthreads();
        const __half* Kbuf = Ks0 + (kt & 1)*KBUF;
        const __half* Vbuf = Vs0 + (kt & 1)*KBUF;

        float sf[8][4] = {};
#pragma unroll
        for (int kc = 0; kc < 4; kc++) {
            uint32_t a0, a1, a2, a3;
            ldsm_x4(a0, a1, a2, a3, qaddr + kc*32);
#pragma unroll
            for (int n8 = 0; n8 < 8; n8++) {
                uint32_t b0, b1;
                uint32_t ka = smem_u32(&Kbuf[(8*n8 + (lane & 7))*QSTR + 16*kc + 8*((lane >> 3) & 1)]);
                ldsm_x2(b0, b1, ka);
                mma16816h(sf[n8], a0, a1, a2, a3, b0, b1);
            }
        }

        float mt0 = -1e30f, mt1 = -1e30f;
#pragma unroll
        for (int j = 0; j < 8; j++) {
            mt0 = fmaxf(mt0, fmaxf(sf[j][0], sf[j][1]));
            mt1 = fmaxf(mt1, fmaxf(sf[j][2], sf[j][3]));
        }
        mt0 = fmaxf(mt0, __shfl_xor_sync(0xffffffffu, mt0, 1));
        mt0 = fmaxf(mt0, __shfl_xor_sync(0xffffffffu, mt0, 2));
        mt1 = fmaxf(mt1, __shfl_xor_sync(0xffffffffu, mt1, 1));
        mt1 = fmaxf(mt1, __shfl_xor_sync(0xffffffffu, mt1, 2));
        float mn0 = fmaxf(m0, mt0), mn1 = fmaxf(m1, mt1);
        float cr0 = __expf(m0 - mn0), cr1 = __expf(m1 - mn1);
        m0 = mn0; m1 = mn1; l0 *= cr0; l1 *= cr1;
#pragma unroll
        for (int j = 0; j < 8; j++) {
            cf[j][0] *= cr0; cf[j][1] *= cr0; cf[j][2] *= cr1; cf[j][3] *= cr1;
        }

        uint32_t pa[4][4];
#pragma unroll
        for (int jk = 0; jk < 4; jk++) {
            float e00 = __expf(sf[2*jk][0]   - mn0), e01 = __expf(sf[2*jk][1]   - mn0);
            float e10 = __expf(sf[2*jk][2]   - mn1), e11 = __expf(sf[2*jk][3]   - mn1);
            float e20 = __expf(sf[2*jk+1][0] - mn0), e21 = __expf(sf[2*jk+1][1] - mn0);
            float e30 = __expf(sf[2*jk+1][2] - mn1), e31 = __expf(sf[2*jk+1][3] - mn1);
            l0 += e00 + e01 + e20 + e21;
            l1 += e10 + e11 + e30 + e31;
            __half2 t;
            t = __floats2half2_rn(e00, e01); pa[jk][0] = *(unsigned*)&t;
            t = __floats2half2_rn(e10, e11); pa[jk][1] = *(unsigned*)&t;
            t = __floats2half2_rn(e20, e21); pa[jk][2] = *(unsigned*)&t;
            t = __floats2half2_rn(e30, e31); pa[jk][3] = *(unsigned*)&t;
        }

#pragma unroll
        for (int jk = 0; jk < 4; jk++) {
#pragma unroll
            for (int jd = 0; jd < 8; jd++) {
                uint32_t b0, b1;
                uint32_t va = smem_u32(&Vbuf[(16*jk + (lane & 15))*QSTR + 8*jd]);
                ldsm_x2t(b0, b1, va);
                mma16816h(cf[jd], pa[jk][0], pa[jk][1], pa[jk][2], pa[jk][3], b0, b1);
            }
        }
        __syncthreads();
    }
#undef ISSUE_KV

    l0 += __shfl_xor_sync(0xffffffffu, l0, 1);
    l0 += __shfl_xor_sync(0xffffffffu, l0, 2);
    l1 += __shfl_xor_sync(0xffffffffu, l1, 1);
    l1 += __shfl_xor_sync(0xffffffffu, l1, 2);
    float inv0 = 1.0f / l0, inv1 = 1.0f / l1;

    long grow0 = (long)b*Tt + qt*64 + 16*wq + (lane >> 2);
    long grow1 = grow0 + 8;
    int colb = h*HD + 2*(lane & 3);
    __half* cr0p = ctx + grow0 * Dd;
    __half* cr1p = ctx + grow1 * Dd;
#pragma unroll
    for (int jd = 0; jd < 8; jd++) {
        int col = colb + 8*jd;
        {
            __half2 Hp = __floats2half2_rn(cf[jd][0]*inv0, cf[jd][1]*inv0);
            *(unsigned*)&cr0p[col] = *(unsigned*)&Hp;
        }
        {
            __half2 Hp = __floats2half2_rn(cf[jd][2]*inv1, cf[jd][3]*inv1);
            *(unsigned*)&cr1p[col] = *(unsigned*)&Hp;
        }
    }
}

// ---------------- separable Gaussian position attention ----------------
__global__ __launch_bounds__(256) void av_init_kernel(float* __restrict__ Av) {
    int i = blockIdx.x * 256 + threadIdx.x;
    float d = (float)((i >> 6) - (i & 63));
    Av[i] = __expf(-d * d * (1.0f/512.0f));
}

__global__ __launch_bounds__(256) void scatter_kernel(
    const __half* __restrict__ xn, const int* __restrict__ posv,
    const int* __restrict__ posh, float* __restrict__ G, float* __restrict__ cnt)
{
    int warp = threadIdx.x >> 5, lane = threadIdx.x & 31;
    long row = (long)blockIdx.x * 8 + warp;
    int b = (int)(row >> 10), t = (int)(row & 1023);
    int pv = posv[b*Tt + t], ph = posh[b*Tt + t];
    float* dst = G + (((long)b*64 + pv)*64 + ph) * 512;
    const __half* ar = xn + row * Dd;
#pragma unroll
    for (int i = 0; i < 16; i++) {
        int d = i*32 + lane;
        atomicAdd(&dst[d], __half2float(ar[d]));
    }
    if (lane == 0) atomicAdd(&cnt[((long)b*64 + pv)*64 + ph], 1.0f);
}

__global__ __launch_bounds__(512) void gconv_kernel(
    const float* __restrict__ in, float* __restrict__ out,
    const float* __restrict__ Av, int stride_fix, int stride_c)
{
    __shared__ float AsT[64][64];
    int fix = blockIdx.x, b = blockIdx.y, tid = threadIdx.x;
    for (int i = tid; i < 4096; i += 512)
        AsT[i & 63][i >> 6] = Av[i];
    __syncthreads();
    const float* ib = in  + (long)b*2097152 + (long)fix*stride_fix + tid;
    float* ob       = out + (long)b*2097152 + (long)fix*stride_fix + tid;
    float acc[64];
#pragma unroll
    for (int v = 0; v < 64; v++) acc[v] = 0.f;
    for (int c = 0; c < 64; c++) {
        float g = ib[(long)c * stride_c];
#pragma unroll
        for (int v4 = 0; v4 < 16; v4++) {
            float4 a4 = *(const float4*)&AsT[c][v4*4];
            acc[v4*4+0] += a4.x*g; acc[v4*4+1] += a4.y*g;
            acc[v4*4+2] += a4.z*g; acc[v4*4+3] += a4.w*g;
        }
    }
#pragma unroll
    for (int v = 0; v < 64; v++) ob[(long)v * stride_c] = acc[v];
}

__global__ __launch_bounds__(1024) void dcnt_kernel(
    const float* __restrict__ cnt, const float* __restrict__ Av,
    float* __restrict__ dcnt)
{
    __shared__ float sc[4096], st[4096];
    int b = blockIdx.x, tid = threadIdx.x;
    for (int i = tid; i < 4096; i += 1024) sc[i] = cnt[(long)b*4096 + i];
    __syncthreads();
    for (int i = tid; i < 4096; i += 1024) {
        int v = i >> 6, hp = i & 63;
        float s = 0.f;
        for (int vp = 0; vp < 64; vp++) s += Av[v*64+vp] * sc[vp*64+hp];
        st[i] = s;
    }
    __syncthreads();
    for (int i = tid; i < 4096; i += 1024) {
        int v = i >> 6, h = i & 63;
        float s = 0.f;
        for (int hp = 0; hp < 64; hp++) s += Av[h*64+hp] * st[v*64+hp];
        dcnt[(long)b*4096 + i] = 1.0f / s;
    }
}

// ---------------- combine + LN2 ----------------
__global__ __launch_bounds__(256) void combine_ln2_kernel(
    const float* __restrict__ x, const float* __restrict__ stdo,
    const float* __restrict__ O, const float* __restrict__ dcntInv,
    const int* __restrict__ posv, const int* __restrict__ posh,
    const float* __restrict__ gate,
    const float* __restrict__ w, const float* __restrict__ bb,
    float* __restrict__ x1, __half* __restrict__ xn2)
{
    int warp = threadIdx.x >> 5, lane = threadIdx.x & 31;
    long row = (long)blockIdx.x * 8 + warp;
    int b = (int)(row >> 10), t = (int)(row & 1023);
    int pv = posv[b*Tt + t], ph = posh[b*Tt + t];
    float g = 1.0f / (1.0f + __expf(-gate[0]));
    float gi = 1.0f - g;
    float inv_ks = dcntInv[((long)b*64 + pv)*64 + ph];
    const float* korow = O + (((long)b*64 + pv)*64 + ph) * 512;
    long base = row * Dd;
    float4 v[4];
    float s = 0.f, sq = 0.f;
#pragma unroll
    for (int i = 0; i < 4; i++) {
        int d = lane*4 + i*128;
        float4 xv = *(const float4*)&x[base + d];
        float4 sv = *(const float4*)&stdo[base + d];
        float4 kv = *(const float4*)&korow[d];
        float4 o4;
        o4.x = xv.x + g*sv.x + gi*kv.x*inv_ks;
        o4.y = xv.y + g*sv.y + gi*kv.y*inv_ks;
        o4.z = xv.z + g*sv.z + gi*kv.z*inv_ks;
        o4.w = xv.w + g*sv.w + gi*kv.w*inv_ks;
        *(float4*)&x1[base + d] = o4;
        v[i] = o4;
        s  += o4.x + o4.y + o4.z + o4.w;
        sq += o4.x*o4.x + o4.y*o4.y + o4.z*o4.z + o4.w*o4.w;
    }
#pragma unroll
    for (int o = 16; o; o >>= 1) {
        s  += __shfl_xor_sync(0xffffffffu, s,  o);
        sq += __shfl_xor_sync(0xffffffffu, sq, o);
    }
    float mean = s * (1.0f/512.0f);
    float var  = sq * (1.0f/512.0f) - mean*mean;
    float rr   = rsqrtf(var + 1e-5f);
    __half* arow = xn2 + row * Dd;
#pragma unroll
    for (int i = 0; i < 4; i++) {
        int d = lane*4 + i*128;
        float4 wv = *(const float4*)&w[d];
        float4 bv = *(const float4*)&bb[d];
        float4 o4;
        o4.x = (v[i].x - mean)*rr*wv.x + bv.x;
        o4.y = (v[i].y - mean)*rr*wv.y + bv.y;
        o4.z = (v[i].z - mean)*rr*wv.z + bv.z;
        o4.w = (v[i].w - mean)*rr*wv.w + bv.w;
        *(uint2*)&arow[d] = cvt4_h(o4);
    }
}

// ---------------- launch ----------------
extern "C" void kernel_launch(void* const* d_in, const int* in_sizes, int n_in,
                              void* d_out, int out_size)
{
    const float* x      = (const float*)d_in[0];
    const int*   posv   = (const int*)  d_in[1];
    const int*   posh   = (const int*)  d_in[2];
    const float* n1w    = (const float*)d_in[3];
    const float* n1b    = (const float*)d_in[4];
    const float* in_w   = (const float*)d_in[5];
    const float* in_b   = (const float*)d_in[6];
    const float* out_w  = (const float*)d_in[7];
    const float* out_b  = (const float*)d_in[8];
    const float* n2w    = (const float*)d_in[9];
    const float* n2b    = (const float*)d_in[10];
    const float* w1     = (const float*)d_in[11];
    const float* b1     = (const float*)d_in[12];
    const float* w2     = (const float*)d_in[13];
    const float* b2     = (const float*)d_in[14];
    const float* gate   = (const float*)d_in[15];
    float* out = (float*)d_out;

    __half *xn, *ctx, *xn2, *hB, *wIN, *wOUT, *w1p, *w2p, *Qbp, *Kbp, *Vbp;
    float *stdo, *G, *T1, *cnt, *dcnt, *Av, *x1;
    cudaGetSymbolAddress((void**)&xn,   g_xn);
    cudaGetSymbolAddress((void**)&Qbp,  g_Qb);
    cudaGetSymbolAddress((void**)&Kbp,  g_Kb);
    cudaGetSymbolAddress((void**)&Vbp,  g_Vb);
    cudaGetSymbolAddress((void**)&ctx,  g_ctx);
    cudaGetSymbolAddress((void**)&stdo, g_stdo);
    cudaGetSymbolAddress((void**)&G,    g_G);
    cudaGetSymbolAddress((void**)&T1,   g_T1);
    cudaGetSymbolAddress((void**)&cnt,  g_cnt);
    cudaGetSymbolAddress((void**)&dcnt, g_dcnt);
    cudaGetSymbolAddress((void**)&Av,   g_Av);
    cudaGetSymbolAddress((void**)&x1,   g_x1);
    cudaGetSymbolAddress((void**)&xn2,  g_xn2);
    cudaGetSymbolAddress((void**)&hB,   g_hB);
    cudaGetSymbolAddress((void**)&wIN,  g_wIN);
    cudaGetSymbolAddress((void**)&wOUT, g_wOUT);
    cudaGetSymbolAddress((void**)&w1p,  g_w1);
    cudaGetSymbolAddress((void**)&w2p,  g_w2);

    cudaFuncSetAttribute(gemm_fp16<256,3>, cudaFuncAttributeMaxDynamicSharedMemorySize, GSMEM_W256);
    cudaFuncSetAttribute(gemm_fp16<256,1>, cudaFuncAttributeMaxDynamicSharedMemorySize, GSMEM_W256);
    cudaFuncSetAttribute(gemm_fp16<128,0>, cudaFuncAttributeMaxDynamicSharedMemorySize, GSMEM_W128);
    cudaFuncSetAttribute(gemm_fp16<128,2>, cudaFuncAttributeMaxDynamicSharedMemorySize, GSMEM_W128);
    cudaFuncSetAttribute(attn_mma_kernel,  cudaFuncAttributeMaxDynamicSharedMemorySize, ATTN_SMEM);

    // side stream fork
    cudaStream_t sA;
    cudaStreamCreateWithFlags(&sA, cudaStreamNonBlocking);
    cudaEvent_t evRoot, evW, evLN, evG;
    cudaEventCreateWithFlags(&evRoot, cudaEventDisableTiming);
    cudaEventCreateWithFlags(&evW,   cudaEventDisableTiming);
    cudaEventCreateWithFlags(&evLN,  cudaEventDisableTiming);
    cudaEventCreateWithFlags(&evG,   cudaEventDisableTiming);

    cudaEventRecord(evRoot, 0);
    cudaStreamWaitEvent(sA, evRoot, 0);

    // side: weight conversions (out/w1/w2), Av, zeros
    conv_w_kernel<<<(Dd*Dd/4 + 255)/256, 256, 0, sA>>>(out_w, wOUT, Dd*Dd/4);
    conv_w_kernel<<<(D4*Dd/4 + 255)/256, 256, 0, sA>>>(w1,    w1p,  D4*Dd/4);
    conv_w_kernel<<<(Dd*D4/4 + 255)/256, 256, 0, sA>>>(w2,    w2p,  Dd*D4/4);
    cudaEventRecord(evW, sA);
    av_init_kernel<<<16, 256, 0, sA>>>(Av);
    zero_kernel<<<(Bb*4096*512/4 + 255)/256, 256, 0, sA>>>(G, Bb*4096*512/4);
    zero_kernel<<<(Bb*4096/4 + 255)/256, 256, 0, sA>>>(cnt, Bb*4096/4);

    // main: conv wIN, LN1
    conv_w_kernel<<<(3*Dd*Dd/4 + 255)/256, 256>>>(in_w, wIN, 3*Dd*Dd/4);
    ln1_kernel<<<ROWS/8, 256>>>(x, n1w, n1b, xn);
    cudaEventRecord(evLN, 0);

    // side: Gaussian path
    cudaStreamWaitEvent(sA, evLN, 0);
    scatter_kernel<<<ROWS/8, 256, 0, sA>>>(xn, posv, posh, G, cnt);
    gconv_kernel<<<dim3(64, Bb), 512, 0, sA>>>(G, T1, Av, 512, 64*512);
    gconv_kernel<<<dim3(64, Bb), 512, 0, sA>>>(T1, G, Av, 64*512, 512);
    dcnt_kernel<<<Bb, 1024, 0, sA>>>(cnt, Av, dcnt);
    cudaEventRecord(evG, sA);

    // main: QKV GEMM (Kp=512), writes fp16 attention buffers
    gemm_fp16<256, 3><<<dim3(6, 64), 256, GSMEM_W256>>>(
        xn, wIN, in_b, nullptr, Qbp, Kbp, Vbp, 3*Dd, Dd);

    // main: attention
    attn_mma_kernel<<<dim3(Tt/64, Hh, Bb), 128, ATTN_SMEM>>>(Qbp, Kbp, Vbp, ctx);

    // main: out-proj
    cudaStreamWaitEvent(0, evW, 0);
    gemm_fp16<128, 0><<<dim3(4, 64), 256, GSMEM_W128>>>(
        ctx, wOUT, out_b, nullptr, stdo, nullptr, nullptr, Dd, Dd);

    // main: combine + LN2
    cudaStreamWaitEvent(0, evG, 0);
    combine_ln2_kernel<<<ROWS/8, 256>>>(
        x, stdo, G, dcnt, posv, posh, gate, n2w, n2b, x1, xn2);

    // main: MLP
    gemm_fp16<256, 1><<<dim3(8, 64), 256, GSMEM_W256>>>(
        xn2, w1p, b1, nullptr, hB, nullptr, nullptr, D4, Dd);
    gemm_fp16<128, 2><<<dim3(4, 64), 256, GSMEM_W128>>>(
        hB, w2p, b2, x1, out, nullptr, nullptr, Dd, D4);
}